// round 10
// baseline (speedup 1.0000x reference)
#include <cuda_runtime.h>
#include <math.h>
#include <stdint.h>

#define NVW 4
#define B_ 4
#define N_ 256
#define C_ 768
#define H_ 12
#define HD_ 64
#define HID_ 3072
#define MROWS (B_*N_)   // 1024 rows per view

// ---------------- scratch (device globals; no allocation) ----------------
__device__ float g_Xn [NVW*MROWS*C_];
__device__ float g_qkv[NVW*MROWS*3*C_];
__device__ float g_ctx[NVW*MROWS*C_];
__device__ float g_x  [NVW*MROWS*C_];
__device__ float g_hn [NVW*MROWS*C_];
__device__ float g_h1 [NVW*MROWS*HID_];
__device__ float g_x2 [NVW*MROWS*C_];
__device__ float g_kv [NVW*MROWS*2*C_];
__device__ float g_qh [NVW*C_];
__device__ float g_c2 [NVW*B_*C_];
// hi/lo tf32 planes (reused across GEMMs; sized for largest operands)
__device__ float g_Ahi[NVW*MROWS*HID_];
__device__ float g_Alo[NVW*MROWS*HID_];
__device__ float g_Whi[NVW*HID_*C_];
__device__ float g_Wlo[NVW*HID_*C_];

__device__ __forceinline__ float gelu_exact(float x) {
    return 0.5f * x * (1.0f + erff(x * 0.70710678118654752f));
}

__device__ __forceinline__ float to_tf32(float x) {
    float r;
    asm("cvt.rna.tf32.f32 %0, %1;" : "=f"(r) : "f"(x));
    return r;
}

__device__ __forceinline__ uint32_t smem_u32(const void* p) {
    uint32_t a;
    asm("{ .reg .u64 t; cvta.to.shared.u64 t, %1; cvt.u32.u64 %0, t; }"
        : "=r"(a) : "l"(p));
    return a;
}

#define CP_ASYNC16(dst, src) \
    asm volatile("cp.async.ca.shared.global [%0], [%1], 16;" \
                 :: "r"(dst), "l"(src) : "memory")
#define CP_COMMIT() \
    asm volatile("cp.async.commit_group;" ::: "memory")
#define CP_WAIT1() \
    asm volatile("cp.async.wait_group 1;" ::: "memory")

#define MMA_TF32(d, a, b) \
    asm volatile( \
        "mma.sync.aligned.m16n8k8.row.col.f32.tf32.tf32.f32 " \
        "{%0,%1,%2,%3}, {%4,%5,%6,%7}, {%8,%9}, {%0,%1,%2,%3};" \
        : "+f"((d)[0]), "+f"((d)[1]), "+f"((d)[2]), "+f"((d)[3]) \
        : "r"((a)[0]), "r"((a)[1]), "r"((a)[2]), "r"((a)[3]), \
          "r"((b)[0]), "r"((b)[1]))

// ---------------- hi/lo split kernel (elementwise, float4) ----------------
__global__ __launch_bounds__(256) void cvt_kernel(
    const float* __restrict__ src, float* __restrict__ hi,
    float* __restrict__ lo, int n4)
{
    int i = blockIdx.x * 256 + threadIdx.x;
    if (i >= n4) return;
    float4 s = ((const float4*)src)[i];
    float4 h, l;
    h.x = to_tf32(s.x); l.x = to_tf32(s.x - h.x);
    h.y = to_tf32(s.y); l.y = to_tf32(s.y - h.y);
    h.z = to_tf32(s.z); l.z = to_tf32(s.z - h.z);
    h.w = to_tf32(s.w); l.w = to_tf32(s.w - h.w);
    ((float4*)hi)[i] = h;
    ((float4*)lo)[i] = l;
}

// ---------------- LayerNorm ----------------
__global__ __launch_bounds__(256) void ln_kernel(
    const float* __restrict__ X, const float* __restrict__ g,
    const float* __restrict__ be, float* __restrict__ Y,
    int remap, int pervw)
{
    int r = blockIdx.x;
    int v = r / (B_ * N_);
    long inrow;
    if (remap) {
        int rem = r % (B_ * N_);
        int bb = rem / N_;
        int n  = rem % N_;
        inrow = ((long)(bb * NVW + v) * N_ + n);
    } else {
        inrow = r;
    }
    const float* x = X + inrow * C_;
    float* y = Y + (long)r * C_;
    const float* gg = g  + (pervw ? v * C_ : 0);
    const float* bb2 = be + (pervw ? v * C_ : 0);

    int t = threadIdx.x;
    float v0 = x[t], v1 = x[t + 256], v2 = x[t + 512];
    float s  = v0 + v1 + v2;
    float sq = v0 * v0 + v1 * v1 + v2 * v2;

    __shared__ float rs[256], rq[256];
    rs[t] = s; rq[t] = sq;
    __syncthreads();
    for (int off = 128; off > 0; off >>= 1) {
        if (t < off) { rs[t] += rs[t + off]; rq[t] += rq[t + off]; }
        __syncthreads();
    }
    float mean = rs[0] * (1.0f / C_);
    float var  = rq[0] * (1.0f / C_) - mean * mean;
    float rstd = rsqrtf(var + 1e-6f);

    y[t]       = (v0 - mean) * rstd * gg[t]       + bb2[t];
    y[t + 256] = (v1 - mean) * rstd * gg[t + 256] + bb2[t + 256];
    y[t + 512] = (v2 - mean) * rstd * gg[t + 512] + bb2[t + 512];
}

// ---------------- 3xTF32 mma.sync batched NT GEMM (v5) ----------------
// Inputs are PRE-SPLIT hi/lo tf32 planes. Inner loop is pure
// cp.async -> LDS(u32) -> MMA: zero cvt instructions.
// CTA tile 128x128, 256 threads, 8 warps (2x4), warp tile 64x32.
// 3-stage cp.async pipeline, 4 tiles per chunk (Ahi/Alo/Whi/Wlo),
// [row][k] stride 36 (bank = 4*fr+fk: conflict-free), 1 sync per chunk.
#define KC 32
#define RSTRIDE 36
#define TILE_F (128 * RSTRIDE)                  // 4608 floats
#define NSTAGE 3
#define GEMM_SMEM (NSTAGE * 4 * TILE_F * 4)     // 221184 bytes

__global__ void __launch_bounds__(256, 1)
gemm_mma(const float* __restrict__ Ahi, const float* __restrict__ Alo,
         const float* __restrict__ Whi, const float* __restrict__ Wlo,
         const float* __restrict__ bias, const float* __restrict__ res,
         float* __restrict__ Cout, int Kdim, int D,
         long sA, long sW, long sB, long sR, long sC, float alpha, int act)
{
    extern __shared__ float sm[];
    const int v = blockIdx.z;
    float* Cv = Cout + (long)v * sC;
    const int bm = blockIdx.y * 128, bn = blockIdx.x * 128;

    const int t = threadIdx.x, lane = t & 31, wid = t >> 5;
    const int wm = (wid >> 2) * 64;    // 2 row groups
    const int wn = (wid & 3) * 32;     // 4 col groups
    const int fr = lane >> 2;          // 0..7
    const int fk = lane & 3;           // 0..3

    // cp.async tasks: thread t handles (tile t>>7, row t&127) and
    // (tile 2+(t>>7), same row). tiles: 0=Ahi 1=Alo 2=Whi 3=Wlo.
    const int crow = t & 127;
    const int hi1  = t >> 7;           // 0/1
    const float* gp0 = (hi1 ? (Alo + (long)v * sA) : (Ahi + (long)v * sA))
                       + (long)(bm + crow) * Kdim;
    const float* gp1 = (hi1 ? (Wlo + (long)v * sW) : (Whi + (long)v * sW))
                       + (long)(bn + crow) * Kdim;
    const uint32_t sbase = smem_u32(sm);
    const uint32_t so0 = (uint32_t)(((hi1)     * TILE_F + crow * RSTRIDE) * 4);
    const uint32_t so1 = (uint32_t)(((2 + hi1) * TILE_F + crow * RSTRIDE) * 4);

    float acc[4][4][4];
    #pragma unroll
    for (int a = 0; a < 4; a++)
        #pragma unroll
        for (int b = 0; b < 4; b++)
            #pragma unroll
            for (int c = 0; c < 4; c++) acc[a][b][c] = 0.0f;

    const int steps = Kdim / KC;

    // prologue: chunks 0,1
    #pragma unroll
    for (int p = 0; p < 2; p++) {
        uint32_t st = sbase + (uint32_t)((p % NSTAGE) * 4 * TILE_F * 4);
        const float* g0 = gp0 + p * KC;
        const float* g1 = gp1 + p * KC;
        #pragma unroll
        for (int i = 0; i < 8; i++) {
            CP_ASYNC16(st + so0 + i * 16, g0 + i * 4);
            CP_ASYNC16(st + so1 + i * 16, g1 + i * 4);
        }
        CP_COMMIT();
    }

    for (int c = 0; c < steps; c++) {
        CP_WAIT1();
        __syncthreads();

        int p = c + 2;
        if (p < steps) {
            uint32_t st = sbase + (uint32_t)((p % NSTAGE) * 4 * TILE_F * 4);
            const float* g0 = gp0 + p * KC;
            const float* g1 = gp1 + p * KC;
            #pragma unroll
            for (int i = 0; i < 8; i++) {
                CP_ASYNC16(st + so0 + i * 16, g0 + i * 4);
                CP_ASYNC16(st + so1 + i * 16, g1 + i * 4);
            }
        }
        CP_COMMIT();

        const uint32_t* AhS = (const uint32_t*)(sm + (c % NSTAGE) * 4 * TILE_F);
        const uint32_t* AlS = AhS + TILE_F;
        const uint32_t* WhS = AlS + TILE_F;
        const uint32_t* WlS = WhS + TILE_F;

        #pragma unroll
        for (int kk = 0; kk < 4; kk++) {
            int k0 = kk * 8 + fk;
            uint32_t ah[4][4], al[4][4], bh[4][2], bl[4][2];
            #pragma unroll
            for (int mt = 0; mt < 4; mt++) {
                int r0 = wm + mt * 16 + fr;
                ah[mt][0] = AhS[(r0    ) * RSTRIDE + k0];
                ah[mt][1] = AhS[(r0 + 8) * RSTRIDE + k0];
                ah[mt][2] = AhS[(r0    ) * RSTRIDE + k0 + 4];
                ah[mt][3] = AhS[(r0 + 8) * RSTRIDE + k0 + 4];
                al[mt][0] = AlS[(r0    ) * RSTRIDE + k0];
                al[mt][1] = AlS[(r0 + 8) * RSTRIDE + k0];
                al[mt][2] = AlS[(r0    ) * RSTRIDE + k0 + 4];
                al[mt][3] = AlS[(r0 + 8) * RSTRIDE + k0 + 4];
            }
            #pragma unroll
            for (int nt = 0; nt < 4; nt++) {
                int n0 = wn + nt * 8 + fr;
                bh[nt][0] = WhS[n0 * RSTRIDE + k0];
                bh[nt][1] = WhS[n0 * RSTRIDE + k0 + 4];
                bl[nt][0] = WlS[n0 * RSTRIDE + k0];
                bl[nt][1] = WlS[n0 * RSTRIDE + k0 + 4];
            }
            #pragma unroll
            for (int mt = 0; mt < 4; mt++)
                #pragma unroll
                for (int nt = 0; nt < 4; nt++) {
                    MMA_TF32(acc[mt][nt], ah[mt], bh[nt]);
                    MMA_TF32(acc[mt][nt], ah[mt], bl[nt]);
                    MMA_TF32(acc[mt][nt], al[mt], bh[nt]);
                }
        }
    }

    __syncthreads();

    // epilogue
    #pragma unroll
    for (int mt = 0; mt < 4; mt++) {
        #pragma unroll
        for (int nt = 0; nt < 4; nt++) {
            int row = bm + wm + mt * 16 + fr;
            int col = bn + wn + nt * 8 + 2 * fk;
            float b0 = 0.f, b1 = 0.f;
            if (bias) {
                b0 = bias[(long)v * sB + col];
                b1 = bias[(long)v * sB + col + 1];
            }
            #pragma unroll
            for (int half = 0; half < 2; half++) {
                int r = row + half * 8;
                float v0 = alpha * (acc[mt][nt][half * 2 + 0] + b0);
                float v1 = alpha * (acc[mt][nt][half * 2 + 1] + b1);
                if (act == 1) { v0 = gelu_exact(v0); v1 = gelu_exact(v1); }
                if (res) {
                    v0 += res[(long)v * sR + (long)r * D + col];
                    v1 += res[(long)v * sR + (long)r * D + col + 1];
                }
                float2 o2 = {v0, v1};
                *(float2*)&Cv[(long)r * D + col] = o2;
            }
        }
    }
}

// ---------------- Pairwise cross-view attention with mean over j ----------------
__global__ __launch_bounds__(256) void attn_kernel(
    const float* __restrict__ qkv, float* __restrict__ ctx_out)
{
    int h = blockIdx.x, b = blockIdx.y, i = blockIdx.z;
    int n = threadIdx.x;
    const float scale = 0.125f;

    __shared__ __align__(16) float sKV[64 * 64];

    float q[64];
    const float* qptr = qkv + ((long)((i * B_ + b) * N_ + n)) * (3 * C_) + h * HD_;
    #pragma unroll
    for (int e4 = 0; e4 < 16; e4++) {
        float4 t4 = *(const float4*)(qptr + e4 * 4);
        q[e4 * 4 + 0] = t4.x; q[e4 * 4 + 1] = t4.y;
        q[e4 * 4 + 2] = t4.z; q[e4 * 4 + 3] = t4.w;
    }

    float ctx[64];
    #pragma unroll
    for (int e = 0; e < 64; e++) ctx[e] = 0.0f;

    float sloc[256];

    for (int j = 0; j < NVW; j++) {
        const float* kbase = qkv + ((long)((j * B_ + b) * N_)) * (3 * C_) + C_ + h * HD_;
        const float* vbase = kbase + C_;

        float smax = -1e30f;
        for (int c = 0; c < 4; c++) {
            __syncthreads();
            #pragma unroll
            for (int r = 0; r < 4; r++) {
                int F = threadIdx.x + 256 * r;
                int row  = F >> 4;
                int col4 = (F & 15) << 2;
                float4 t4 = *(const float4*)(kbase + (long)(c * 64 + row) * (3 * C_) + col4);
                *(float4*)&sKV[row * 64 + col4] = t4;
            }
            __syncthreads();
            for (int m = 0; m < 64; m++) {
                float d0 = 0.f, d1 = 0.f, d2 = 0.f, d3 = 0.f;
                const float* kr = &sKV[m * 64];
                #pragma unroll
                for (int e = 0; e < 64; e += 4) {
                    d0 += q[e + 0] * kr[e + 0];
                    d1 += q[e + 1] * kr[e + 1];
                    d2 += q[e + 2] * kr[e + 2];
                    d3 += q[e + 3] * kr[e + 3];
                }
                float s = ((d0 + d1) + (d2 + d3)) * scale;
                sloc[c * 64 + m] = s;
                smax = fmaxf(smax, s);
            }
        }
        float ssum = 0.0f;
        for (int m = 0; m < 256; m++) {
            float e_ = __expf(sloc[m] - smax);
            sloc[m] = e_;
            ssum += e_;
        }
        float inv = 1.0f / ssum;

        for (int c = 0; c < 4; c++) {
            __syncthreads();
            #pragma unroll
            for (int r = 0; r < 4; r++) {
                int F = threadIdx.x + 256 * r;
                int row  = F >> 4;
                int col4 = (F & 15) << 2;
                float4 t4 = *(const float4*)(vbase + (long)(c * 64 + row) * (3 * C_) + col4);
                *(float4*)&sKV[row * 64 + col4] = t4;
            }
            __syncthreads();
            for (int m = 0; m < 64; m++) {
                float pm = sloc[c * 64 + m] * inv;
                const float* vr = &sKV[m * 64];
                #pragma unroll
                for (int e = 0; e < 64; e++) ctx[e] += pm * vr[e];
            }
        }
    }

    float* outp = ctx_out + ((long)((i * B_ + b) * N_ + n)) * C_ + h * HD_;
    #pragma unroll
    for (int e4 = 0; e4 < 16; e4++) {
        float4 o4;
        o4.x = ctx[e4 * 4 + 0] * 0.25f;
        o4.y = ctx[e4 * 4 + 1] * 0.25f;
        o4.z = ctx[e4 * 4 + 2] * 0.25f;
        o4.w = ctx[e4 * 4 + 3] * 0.25f;
        *(float4*)(outp + e4 * 4) = o4;
    }
}

// ---------------- learnable-query projection ----------------
__global__ __launch_bounds__(256) void qh_kernel(
    const float* __restrict__ query, const float* __restrict__ w,
    const float* __restrict__ bq, float* __restrict__ qh)
{
    int v = blockIdx.x;
    int t = threadIdx.x;
    for (int d = t; d < C_; d += 256) {
        const float* wr = w + (long)v * (3 * C_) * C_ + (long)d * C_;
        float acc = 0.0f;
        #pragma unroll 4
        for (int c = 0; c < C_; c++) acc += query[c] * wr[c];
        qh[v * C_ + d] = acc + bq[(long)v * (3 * C_) + d];
    }
}

// ---------------- cross attention (single query) ----------------
__global__ __launch_bounds__(256) void cross_attn_kernel(
    const float* __restrict__ kv, const float* __restrict__ qh,
    float* __restrict__ c2)
{
    int h = blockIdx.x, b = blockIdx.y, v = blockIdx.z;
    int t = threadIdx.x;

    __shared__ float p[256];
    __shared__ float red[256];
    __shared__ float part[4][64];

    const float* kvb = kv + ((long)(v * B_ + b) * N_) * (2 * C_);
    const float* qhp = qh + v * C_ + h * HD_;
    const float* krow = kvb + (long)t * (2 * C_) + h * HD_;

    float s = 0.0f;
    #pragma unroll
    for (int e = 0; e < 64; e++) s += qhp[e] * krow[e];
    s *= 0.125f;

    red[t] = s; __syncthreads();
    for (int off = 128; off > 0; off >>= 1) {
        if (t < off) red[t] = fmaxf(red[t], red[t + off]);
        __syncthreads();
    }
    float mx = red[0];
    __syncthreads();

    float e_ = __expf(s - mx);
    p[t] = e_; red[t] = e_;
    __syncthreads();
    for (int off = 128; off > 0; off >>= 1) {
        if (t < off) red[t] += red[t + off];
        __syncthreads();
    }
    float inv = 1.0f / red[0];
    __syncthreads();

    int e = t & 63, pid = t >> 6;
    float acc = 0.0f;
    for (int n = pid * 64; n < pid * 64 + 64; n++)
        acc += p[n] * kvb[(long)n * (2 * C_) + C_ + h * HD_ + e];
    part[pid][e] = acc;
    __syncthreads();
    if (t < 64) {
        float r = (part[0][t] + part[1][t]) + (part[2][t] + part[3][t]);
        c2[(long)(v * B_ + b) * C_ + h * HD_ + t] = r * inv;
    }
}

// ---------------- output projection + broadcast over N ----------------
__global__ __launch_bounds__(256) void out_kernel(
    const float* __restrict__ c2, const float* __restrict__ w,
    const float* __restrict__ bias, float* __restrict__ out)
{
    int v = blockIdx.x, b = blockIdx.y;
    int t = threadIdx.x;

    __shared__ float sc[C_];
    for (int c = t; c < C_; c += 256) sc[c] = c2[(long)(v * B_ + b) * C_ + c];
    __syncthreads();

    float o[3];
    #pragma unroll
    for (int r = 0; r < 3; r++) {
        int co = t + r * 256;
        const float* wr = w + (long)v * C_ * C_ + (long)co * C_;
        float d0 = 0.f, d1 = 0.f, d2 = 0.f, d3 = 0.f;
        #pragma unroll 4
        for (int c = 0; c < C_; c += 4) {
            d0 += sc[c + 0] * wr[c + 0];
            d1 += sc[c + 1] * wr[c + 1];
            d2 += sc[c + 2] * wr[c + 2];
            d3 += sc[c + 3] * wr[c + 3];
        }
        o[r] = ((d0 + d1) + (d2 + d3)) + bias[v * C_ + co];
    }
    for (int n = 0; n < N_; n++) {
        long base = ((long)b * N_ + n) * (NVW * C_) + (long)v * C_;
        #pragma unroll
        for (int r = 0; r < 3; r++) out[base + t + r * 256] = o[r];
    }
}

// ---------------- launch ----------------
extern "C" void kernel_launch(void* const* d_in, const int* in_sizes, int n_in,
                              void* d_out, int out_size)
{
    const float* X        = (const float*)d_in[0];
    const float* norm1_g  = (const float*)d_in[1];
    const float* norm1_b  = (const float*)d_in[2];
    const float* qkv_w    = (const float*)d_in[3];
    const float* proj_w   = (const float*)d_in[4];
    const float* proj_b   = (const float*)d_in[5];
    const float* norm2_g  = (const float*)d_in[6];
    const float* norm2_b  = (const float*)d_in[7];
    const float* fc1_w    = (const float*)d_in[8];
    const float* fc1_b    = (const float*)d_in[9];
    const float* fc2_w    = (const float*)d_in[10];
    const float* fc2_b    = (const float*)d_in[11];
    const float* query    = (const float*)d_in[12];
    const float* mha_in_w = (const float*)d_in[13];
    const float* mha_in_b = (const float*)d_in[14];
    const float* mha_out_w= (const float*)d_in[15];
    const float* mha_out_b= (const float*)d_in[16];
    float* out = (float*)d_out;

    float *Xn, *qkvb, *ctx, *x, *hn, *h1, *x2, *kv, *qh, *c2;
    float *Ahi, *Alo, *Whi, *Wlo;
    cudaGetSymbolAddress((void**)&Xn,   g_Xn);
    cudaGetSymbolAddress((void**)&qkvb, g_qkv);
    cudaGetSymbolAddress((void**)&ctx,  g_ctx);
    cudaGetSymbolAddress((void**)&x,    g_x);
    cudaGetSymbolAddress((void**)&hn,   g_hn);
    cudaGetSymbolAddress((void**)&h1,   g_h1);
    cudaGetSymbolAddress((void**)&x2,   g_x2);
    cudaGetSymbolAddress((void**)&kv,   g_kv);
    cudaGetSymbolAddress((void**)&qh,   g_qh);
    cudaGetSymbolAddress((void**)&c2,   g_c2);
    cudaGetSymbolAddress((void**)&Ahi,  g_Ahi);
    cudaGetSymbolAddress((void**)&Alo,  g_Alo);
    cudaGetSymbolAddress((void**)&Whi,  g_Whi);
    cudaGetSymbolAddress((void**)&Wlo,  g_Wlo);

    cudaFuncSetAttribute(gemm_mma, cudaFuncAttributeMaxDynamicSharedMemorySize,
                         GEMM_SMEM);

    const long MC  = (long)MROWS * C_;
    const long MH  = (long)MROWS * HID_;

    auto cvt = [&](const float* src, float* hi, float* lo, long n) {
        int n4 = (int)(n / 4);
        cvt_kernel<<<(n4 + 255) / 256, 256>>>(src, hi, lo, n4);
    };

    // 1. LN1 (remap [b*NV+v] -> [v][b]), shared params
    ln_kernel<<<NVW * B_ * N_, 256>>>(X, norm1_g, norm1_b, Xn, 1, 0);

    // 2. QKV GEMM: [1024,768] x [2304,768]^T -> [1024,2304]
    cvt(Xn, Ahi, Alo, NVW * MC);
    cvt(qkv_w, Whi, Wlo, (long)NVW * 3 * C_ * C_);
    gemm_mma<<<dim3(3 * C_ / 128, MROWS / 128, NVW), 256, GEMM_SMEM>>>(
        Ahi, Alo, Whi, Wlo, nullptr, nullptr, qkvb,
        C_, 3 * C_, MC, (long)3 * C_ * C_, 0, 0, (long)MROWS * 3 * C_, 1.0f, 0);

    // 3. pairwise attention, mean over j
    attn_kernel<<<dim3(H_, B_, NVW), 256>>>(qkvb, ctx);

    // 4. proj GEMM, alpha=2 folds the residual doubling
    cvt(ctx, Ahi, Alo, NVW * MC);
    cvt(proj_w, Whi, Wlo, (long)NVW * C_ * C_);
    gemm_mma<<<dim3(C_ / 128, MROWS / 128, NVW), 256, GEMM_SMEM>>>(
        Ahi, Alo, Whi, Wlo, proj_b, nullptr, x,
        C_, C_, MC, (long)C_ * C_, C_, 0, MC, 2.0f, 0);

    // 5. LN2 (per-view params)
    ln_kernel<<<NVW * B_ * N_, 256>>>(x, norm2_g, norm2_b, hn, 0, 1);

    // 6. fc1 GEMM + bias + GELU
    cvt(hn, Ahi, Alo, NVW * MC);
    cvt(fc1_w, Whi, Wlo, (long)NVW * HID_ * C_);
    gemm_mma<<<dim3(HID_ / 128, MROWS / 128, NVW), 256, GEMM_SMEM>>>(
        Ahi, Alo, Whi, Wlo, fc1_b, nullptr, h1,
        C_, HID_, MC, (long)HID_ * C_, HID_, 0, MH, 1.0f, 1);

    // 7. fc2 GEMM + bias + residual add (x)
    cvt(h1, Ahi, Alo, NVW * MH);
    cvt(fc2_w, Whi, Wlo, (long)NVW * C_ * HID_);
    gemm_mma<<<dim3(C_ / 128, MROWS / 128, NVW), 256, GEMM_SMEM>>>(
        Ahi, Alo, Whi, Wlo, fc2_b, x, x2,
        HID_, C_, MH, (long)C_ * HID_, C_, MC, MC, 1.0f, 0);

    // 8. learnable query projection
    qh_kernel<<<NVW, 256>>>(query, mha_in_w, mha_in_b, qh);

    // 9. K/V projection of x2 (convert whole mha_in_w; use same offset math)
    cvt(x2, Ahi, Alo, NVW * MC);
    cvt(mha_in_w, Whi, Wlo, (long)NVW * 3 * C_ * C_);
    gemm_mma<<<dim3(2 * C_ / 128, MROWS / 128, NVW), 256, GEMM_SMEM>>>(
        Ahi, Alo, Whi + (long)C_ * C_, Wlo + (long)C_ * C_,
        mha_in_b + C_, nullptr, kv,
        C_, 2 * C_, MC, (long)3 * C_ * C_, (long)3 * C_, 0,
        (long)MROWS * 2 * C_, 1.0f, 0);

    // 10. single-query cross attention -> c2[v][b][C]
    cross_attn_kernel<<<dim3(H_, B_, NVW), 256>>>(kv, qh, c2);

    // 11. output projection + broadcast over N
    out_kernel<<<dim3(NVW, B_), 256>>>(c2, mha_out_w, mha_out_b, out);
}

// round 11
// speedup vs baseline: 1.8495x; 1.8495x over previous
#include <cuda_runtime.h>
#include <cuda_bf16.h>
#include <math.h>
#include <stdint.h>

#define NVW 4
#define B_ 4
#define N_ 256
#define C_ 768
#define H_ 12
#define HD_ 64
#define HID_ 3072
#define MROWS (B_*N_)   // 1024 rows per view

// ---------------- scratch (device globals; no allocation) ----------------
__device__ float g_qkv[NVW*MROWS*3*C_];
__device__ float g_x  [NVW*MROWS*C_];
__device__ float g_kv [NVW*MROWS*2*C_];
__device__ float g_qh [NVW*C_];
__device__ float g_c2 [NVW*B_*C_];
// bf16 hi/lo activation planes
__device__ __nv_bfloat16 g_XnH [NVW*MROWS*C_],  g_XnL [NVW*MROWS*C_];
__device__ __nv_bfloat16 g_ctxH[NVW*MROWS*C_],  g_ctxL[NVW*MROWS*C_];
__device__ __nv_bfloat16 g_hnH [NVW*MROWS*C_],  g_hnL [NVW*MROWS*C_];
__device__ __nv_bfloat16 g_h1H [NVW*MROWS*HID_],g_h1L [NVW*MROWS*HID_];
__device__ __nv_bfloat16 g_x2H [NVW*MROWS*C_],  g_x2L [NVW*MROWS*C_];
// bf16 hi/lo weight planes
__device__ __nv_bfloat16 g_WqkvH[NVW*3*C_*C_], g_WqkvL[NVW*3*C_*C_];
__device__ __nv_bfloat16 g_WprjH[NVW*C_*C_],   g_WprjL[NVW*C_*C_];
__device__ __nv_bfloat16 g_Wf1H [NVW*HID_*C_], g_Wf1L [NVW*HID_*C_];
__device__ __nv_bfloat16 g_Wf2H [NVW*C_*HID_], g_Wf2L [NVW*C_*HID_];
__device__ __nv_bfloat16 g_WmhaH[NVW*3*C_*C_], g_WmhaL[NVW*3*C_*C_];

__device__ __forceinline__ float gelu_exact(float x) {
    return 0.5f * x * (1.0f + erff(x * 0.70710678118654752f));
}

__device__ __forceinline__ void bfsplit(float x, __nv_bfloat16& h, __nv_bfloat16& l) {
    h = __float2bfloat16(x);
    l = __float2bfloat16(x - __bfloat162float(h));
}

__device__ __forceinline__ uint32_t smem_u32(const void* p) {
    uint32_t a;
    asm("{ .reg .u64 t; cvta.to.shared.u64 t, %1; cvt.u32.u64 %0, t; }"
        : "=r"(a) : "l"(p));
    return a;
}

#define CP_ASYNC16(dst, src) \
    asm volatile("cp.async.ca.shared.global [%0], [%1], 16;" \
                 :: "r"(dst), "l"(src) : "memory")
#define CP_COMMIT() \
    asm volatile("cp.async.commit_group;" ::: "memory")
#define CP_WAIT2() \
    asm volatile("cp.async.wait_group 2;" ::: "memory")

#define MMA_BF16(d, a, b) \
    asm volatile( \
        "mma.sync.aligned.m16n8k16.row.col.f32.bf16.bf16.f32 " \
        "{%0,%1,%2,%3}, {%4,%5,%6,%7}, {%8,%9}, {%0,%1,%2,%3};" \
        : "+f"((d)[0]), "+f"((d)[1]), "+f"((d)[2]), "+f"((d)[3]) \
        : "r"((a)[0]), "r"((a)[1]), "r"((a)[2]), "r"((a)[3]), \
          "r"((b)[0]), "r"((b)[1]))

// ---------------- weight split kernel (f32 -> bf16 hi/lo) ----------------
__global__ __launch_bounds__(256) void wsplit_kernel(
    const float* __restrict__ src, __nv_bfloat16* __restrict__ hi,
    __nv_bfloat16* __restrict__ lo, int n4)
{
    int i = blockIdx.x * 256 + threadIdx.x;
    if (i >= n4) return;
    float4 s = ((const float4*)src)[i];
    __nv_bfloat16 h0, h1, h2, h3, l0, l1, l2, l3;
    bfsplit(s.x, h0, l0); bfsplit(s.y, h1, l1);
    bfsplit(s.z, h2, l2); bfsplit(s.w, h3, l3);
    __nv_bfloat162* H = (__nv_bfloat162*)hi;
    __nv_bfloat162* L = (__nv_bfloat162*)lo;
    H[2*i]   = __nv_bfloat162{h0, h1};
    H[2*i+1] = __nv_bfloat162{h2, h3};
    L[2*i]   = __nv_bfloat162{l0, l1};
    L[2*i+1] = __nv_bfloat162{l2, l3};
}

// ---------------- LayerNorm -> bf16 hi/lo planes ----------------
__global__ __launch_bounds__(256) void ln_kernel(
    const float* __restrict__ X, const float* __restrict__ g,
    const float* __restrict__ be, __nv_bfloat16* __restrict__ YH,
    __nv_bfloat16* __restrict__ YL, int remap, int pervw)
{
    int r = blockIdx.x;
    int v = r / (B_ * N_);
    long inrow;
    if (remap) {
        int rem = r % (B_ * N_);
        int bb = rem / N_;
        int n  = rem % N_;
        inrow = ((long)(bb * NVW + v) * N_ + n);
    } else {
        inrow = r;
    }
    const float* x = X + inrow * C_;
    long obase = (long)r * C_;
    const float* gg = g  + (pervw ? v * C_ : 0);
    const float* bb2 = be + (pervw ? v * C_ : 0);

    int t = threadIdx.x;
    float v0 = x[t], v1 = x[t + 256], v2 = x[t + 512];
    float s  = v0 + v1 + v2;
    float sq = v0 * v0 + v1 * v1 + v2 * v2;

    __shared__ float rs[256], rq[256];
    rs[t] = s; rq[t] = sq;
    __syncthreads();
    for (int off = 128; off > 0; off >>= 1) {
        if (t < off) { rs[t] += rs[t + off]; rq[t] += rq[t + off]; }
        __syncthreads();
    }
    float mean = rs[0] * (1.0f / C_);
    float var  = rq[0] * (1.0f / C_) - mean * mean;
    float rstd = rsqrtf(var + 1e-6f);

    #pragma unroll
    for (int rr = 0; rr < 3; rr++) {
        int c = t + rr * 256;
        float val = (rr == 0 ? v0 : (rr == 1 ? v1 : v2));
        float y = (val - mean) * rstd * gg[c] + bb2[c];
        __nv_bfloat16 h, l;
        bfsplit(y, h, l);
        YH[obase + c] = h;
        YL[obase + c] = l;
    }
}

// ---------------- 3xBF16 mma.sync batched NT GEMM ----------------
// CTA tile 128x128, 256 threads, 8 warps (2x4), warp tile 64x32.
// m16n8k16 bf16; hi/lo planes pre-split. K-chunk 32 (2 k-steps).
// smem [row][k2] u32 stride 20 (banks 20*fr+fk all distinct).
// 4-stage cp.async, wait_group 2, 1 syncthreads/chunk.
#define KC 32
#define RSU 20
#define TILE_U (128 * RSU)                   // 2560 u32
#define NSTAGE 4
#define GEMM_SMEM (NSTAGE * 4 * TILE_U * 4)  // 163840 bytes

__global__ void __launch_bounds__(256, 1)
gemm_mma(const __nv_bfloat16* __restrict__ Ah, const __nv_bfloat16* __restrict__ Al,
         const __nv_bfloat16* __restrict__ Wh, const __nv_bfloat16* __restrict__ Wl,
         const float* __restrict__ bias, const float* __restrict__ res,
         float* __restrict__ Cf,
         __nv_bfloat16* __restrict__ CH, __nv_bfloat16* __restrict__ CL,
         int Kdim, int D,
         long sA, long sW, long sB, long sR, long sC, float alpha, int act)
{
    extern __shared__ uint32_t smu[];
    const int v = blockIdx.z;
    const int bm = blockIdx.y * 128, bn = blockIdx.x * 128;

    const int t = threadIdx.x, lane = t & 31, wid = t >> 5;
    const int wm = (wid >> 2) * 64;    // 2 row groups
    const int wn = (wid & 3) * 32;     // 4 col groups
    const int fr = lane >> 2;          // 0..7
    const int fk = lane & 3;           // 0..3

    // cp.async: thread t -> (A plane sel, row crow) + (W plane sel, row crow)
    const int crow = t & 127;
    const int sel  = t >> 7;           // 0=hi, 1=lo
    const __nv_bfloat16* gA = (sel ? Al : Ah) + (long)v * sA + (long)(bm + crow) * Kdim;
    const __nv_bfloat16* gW = (sel ? Wl : Wh) + (long)v * sW + (long)(bn + crow) * Kdim;
    const uint32_t sbase = smem_u32(smu);
    const uint32_t so0 = (uint32_t)(((sel)     * TILE_U + crow * RSU) * 4);
    const uint32_t so1 = (uint32_t)(((2 + sel) * TILE_U + crow * RSU) * 4);

    float acc[4][4][4];
    #pragma unroll
    for (int a = 0; a < 4; a++)
        #pragma unroll
        for (int b = 0; b < 4; b++)
            #pragma unroll
            for (int c = 0; c < 4; c++) acc[a][b][c] = 0.0f;

    const int steps = Kdim / KC;

    // prologue: chunks 0..2
    #pragma unroll
    for (int p = 0; p < 3; p++) {
        if (p < steps) {
            uint32_t st = sbase + (uint32_t)((p & 3) * 4 * TILE_U * 4);
            const char* a8 = (const char*)gA + p * 64;   // 32 bf16 = 64B
            const char* w8 = (const char*)gW + p * 64;
            #pragma unroll
            for (int i = 0; i < 4; i++) {
                CP_ASYNC16(st + so0 + i * 16, a8 + i * 16);
                CP_ASYNC16(st + so1 + i * 16, w8 + i * 16);
            }
        }
        CP_COMMIT();
    }

    for (int c = 0; c < steps; c++) {
        CP_WAIT2();
        __syncthreads();

        int p = c + 3;
        if (p < steps) {
            uint32_t st = sbase + (uint32_t)((p & 3) * 4 * TILE_U * 4);
            const char* a8 = (const char*)gA + p * 64;
            const char* w8 = (const char*)gW + p * 64;
            #pragma unroll
            for (int i = 0; i < 4; i++) {
                CP_ASYNC16(st + so0 + i * 16, a8 + i * 16);
                CP_ASYNC16(st + so1 + i * 16, w8 + i * 16);
            }
        }
        CP_COMMIT();

        const uint32_t* S   = smu + (c & 3) * 4 * TILE_U;
        const uint32_t* AhS = S;
        const uint32_t* AlS = S + TILE_U;
        const uint32_t* WhS = S + 2 * TILE_U;
        const uint32_t* WlS = S + 3 * TILE_U;

        #pragma unroll
        for (int s = 0; s < 2; s++) {
            int ko = s * 8 + fk;
            uint32_t ah[4][4], al[4][4], bh[4][2], bl[4][2];
            #pragma unroll
            for (int mt = 0; mt < 4; mt++) {
                int r0 = wm + mt * 16 + fr;
                // m16n8k16 A-frag: a0=rows fr k2=ko, a1=fr+8 ko, a2=fr ko+4, a3=fr+8 ko+4
                ah[mt][0] = AhS[(r0    ) * RSU + ko];
                ah[mt][1] = AhS[(r0 + 8) * RSU + ko];
                ah[mt][2] = AhS[(r0    ) * RSU + ko + 4];
                ah[mt][3] = AhS[(r0 + 8) * RSU + ko + 4];
                al[mt][0] = AlS[(r0    ) * RSU + ko];
                al[mt][1] = AlS[(r0 + 8) * RSU + ko];
                al[mt][2] = AlS[(r0    ) * RSU + ko + 4];
                al[mt][3] = AlS[(r0 + 8) * RSU + ko + 4];
            }
            #pragma unroll
            for (int nt = 0; nt < 4; nt++) {
                int n0 = wn + nt * 8 + fr;
                bh[nt][0] = WhS[n0 * RSU + ko];
                bh[nt][1] = WhS[n0 * RSU + ko + 4];
                bl[nt][0] = WlS[n0 * RSU + ko];
                bl[nt][1] = WlS[n0 * RSU + ko + 4];
            }
            #pragma unroll
            for (int mt = 0; mt < 4; mt++)
                #pragma unroll
                for (int nt = 0; nt < 4; nt++)
                    MMA_BF16(acc[mt][nt], ah[mt], bh[nt]);
            #pragma unroll
            for (int mt = 0; mt < 4; mt++)
                #pragma unroll
                for (int nt = 0; nt < 4; nt++)
                    MMA_BF16(acc[mt][nt], ah[mt], bl[nt]);
            #pragma unroll
            for (int mt = 0; mt < 4; mt++)
                #pragma unroll
                for (int nt = 0; nt < 4; nt++)
                    MMA_BF16(acc[mt][nt], al[mt], bh[nt]);
        }
    }

    __syncthreads();

    // epilogue: c0,c1 -> (row, 2fk..2fk+1); c2,c3 -> row+8
    #pragma unroll
    for (int mt = 0; mt < 4; mt++) {
        #pragma unroll
        for (int nt = 0; nt < 4; nt++) {
            int row = bm + wm + mt * 16 + fr;
            int col = bn + wn + nt * 8 + 2 * fk;
            float b0 = 0.f, b1 = 0.f;
            if (bias) {
                b0 = bias[(long)v * sB + col];
                b1 = bias[(long)v * sB + col + 1];
            }
            #pragma unroll
            for (int half = 0; half < 2; half++) {
                int r = row + half * 8;
                float v0 = alpha * (acc[mt][nt][half * 2 + 0] + b0);
                float v1 = alpha * (acc[mt][nt][half * 2 + 1] + b1);
                if (act == 1) { v0 = gelu_exact(v0); v1 = gelu_exact(v1); }
                if (res) {
                    v0 += res[(long)v * sR + (long)r * D + col];
                    v1 += res[(long)v * sR + (long)r * D + col + 1];
                }
                long off = (long)v * sC + (long)r * D + col;
                if (Cf) {
                    float2 o2 = {v0, v1};
                    *(float2*)&Cf[off] = o2;
                } else {
                    __nv_bfloat16 h0, h1, l0, l1;
                    bfsplit(v0, h0, l0);
                    bfsplit(v1, h1, l1);
                    *(__nv_bfloat162*)&CH[off] = __nv_bfloat162{h0, h1};
                    *(__nv_bfloat162*)&CL[off] = __nv_bfloat162{l0, l1};
                }
            }
        }
    }
}

// ---------------- Pairwise cross-view attention with mean over j ----------------
// output: bf16 hi/lo planes (consumed only by proj GEMM)
__global__ __launch_bounds__(256) void attn_kernel(
    const float* __restrict__ qkv,
    __nv_bfloat16* __restrict__ ctxH, __nv_bfloat16* __restrict__ ctxL)
{
    int h = blockIdx.x, b = blockIdx.y, i = blockIdx.z;
    int n = threadIdx.x;
    const float scale = 0.125f;

    __shared__ __align__(16) float sKV[64 * 64];

    float q[64];
    const float* qptr = qkv + ((long)((i * B_ + b) * N_ + n)) * (3 * C_) + h * HD_;
    #pragma unroll
    for (int e4 = 0; e4 < 16; e4++) {
        float4 t4 = *(const float4*)(qptr + e4 * 4);
        q[e4 * 4 + 0] = t4.x; q[e4 * 4 + 1] = t4.y;
        q[e4 * 4 + 2] = t4.z; q[e4 * 4 + 3] = t4.w;
    }

    float ctx[64];
    #pragma unroll
    for (int e = 0; e < 64; e++) ctx[e] = 0.0f;

    float sloc[256];

    for (int j = 0; j < NVW; j++) {
        const float* kbase = qkv + ((long)((j * B_ + b) * N_)) * (3 * C_) + C_ + h * HD_;
        const float* vbase = kbase + C_;

        float smax = -1e30f;
        for (int c = 0; c < 4; c++) {
            __syncthreads();
            #pragma unroll
            for (int r = 0; r < 4; r++) {
                int F = threadIdx.x + 256 * r;
                int row  = F >> 4;
                int col4 = (F & 15) << 2;
                float4 t4 = *(const float4*)(kbase + (long)(c * 64 + row) * (3 * C_) + col4);
                *(float4*)&sKV[row * 64 + col4] = t4;
            }
            __syncthreads();
            for (int m = 0; m < 64; m++) {
                float d0 = 0.f, d1 = 0.f, d2 = 0.f, d3 = 0.f;
                const float* kr = &sKV[m * 64];
                #pragma unroll
                for (int e = 0; e < 64; e += 4) {
                    d0 += q[e + 0] * kr[e + 0];
                    d1 += q[e + 1] * kr[e + 1];
                    d2 += q[e + 2] * kr[e + 2];
                    d3 += q[e + 3] * kr[e + 3];
                }
                float s = ((d0 + d1) + (d2 + d3)) * scale;
                sloc[c * 64 + m] = s;
                smax = fmaxf(smax, s);
            }
        }
        float ssum = 0.0f;
        for (int m = 0; m < 256; m++) {
            float e_ = __expf(sloc[m] - smax);
            sloc[m] = e_;
            ssum += e_;
        }
        float inv = 1.0f / ssum;

        for (int c = 0; c < 4; c++) {
            __syncthreads();
            #pragma unroll
            for (int r = 0; r < 4; r++) {
                int F = threadIdx.x + 256 * r;
                int row  = F >> 4;
                int col4 = (F & 15) << 2;
                float4 t4 = *(const float4*)(vbase + (long)(c * 64 + row) * (3 * C_) + col4);
                *(float4*)&sKV[row * 64 + col4] = t4;
            }
            __syncthreads();
            for (int m = 0; m < 64; m++) {
                float pm = sloc[c * 64 + m] * inv;
                const float* vr = &sKV[m * 64];
                #pragma unroll
                for (int e = 0; e < 64; e++) ctx[e] += pm * vr[e];
            }
        }
    }

    long obase = ((long)((i * B_ + b) * N_ + n)) * C_ + h * HD_;
    #pragma unroll
    for (int e2 = 0; e2 < 32; e2++) {
        float c0 = ctx[e2 * 2 + 0] * 0.25f;
        float c1 = ctx[e2 * 2 + 1] * 0.25f;
        __nv_bfloat16 h0, h1, l0, l1;
        bfsplit(c0, h0, l0);
        bfsplit(c1, h1, l1);
        *(__nv_bfloat162*)&ctxH[obase + e2 * 2] = __nv_bfloat162{h0, h1};
        *(__nv_bfloat162*)&ctxL[obase + e2 * 2] = __nv_bfloat162{l0, l1};
    }
}

// ---------------- learnable-query projection ----------------
__global__ __launch_bounds__(256) void qh_kernel(
    const float* __restrict__ query, const float* __restrict__ w,
    const float* __restrict__ bq, float* __restrict__ qh)
{
    int v = blockIdx.x;
    int t = threadIdx.x;
    for (int d = t; d < C_; d += 256) {
        const float* wr = w + (long)v * (3 * C_) * C_ + (long)d * C_;
        float acc = 0.0f;
        #pragma unroll 4
        for (int c = 0; c < C_; c++) acc += query[c] * wr[c];
        qh[v * C_ + d] = acc + bq[(long)v * (3 * C_) + d];
    }
}

// ---------------- cross attention (single query) ----------------
__global__ __launch_bounds__(256) void cross_attn_kernel(
    const float* __restrict__ kv, const float* __restrict__ qh,
    float* __restrict__ c2)
{
    int h = blockIdx.x, b = blockIdx.y, v = blockIdx.z;
    int t = threadIdx.x;

    __shared__ float p[256];
    __shared__ float red[256];
    __shared__ float part[4][64];

    const float* kvb = kv + ((long)(v * B_ + b) * N_) * (2 * C_);
    const float* qhp = qh + v * C_ + h * HD_;
    const float* krow = kvb + (long)t * (2 * C_) + h * HD_;

    float s = 0.0f;
    #pragma unroll
    for (int e = 0; e < 64; e++) s += qhp[e] * krow[e];
    s *= 0.125f;

    red[t] = s; __syncthreads();
    for (int off = 128; off > 0; off >>= 1) {
        if (t < off) red[t] = fmaxf(red[t], red[t + off]);
        __syncthreads();
    }
    float mx = red[0];
    __syncthreads();

    float e_ = __expf(s - mx);
    p[t] = e_; red[t] = e_;
    __syncthreads();
    for (int off = 128; off > 0; off >>= 1) {
        if (t < off) red[t] += red[t + off];
        __syncthreads();
    }
    float inv = 1.0f / red[0];
    __syncthreads();

    int e = t & 63, pid = t >> 6;
    float acc = 0.0f;
    for (int n = pid * 64; n < pid * 64 + 64; n++)
        acc += p[n] * kvb[(long)n * (2 * C_) + C_ + h * HD_ + e];
    part[pid][e] = acc;
    __syncthreads();
    if (t < 64) {
        float r = (part[0][t] + part[1][t]) + (part[2][t] + part[3][t]);
        c2[(long)(v * B_ + b) * C_ + h * HD_ + t] = r * inv;
    }
}

// ---------------- output projection + broadcast over N ----------------
__global__ __launch_bounds__(256) void out_kernel(
    const float* __restrict__ c2, const float* __restrict__ w,
    const float* __restrict__ bias, float* __restrict__ out)
{
    int v = blockIdx.x, b = blockIdx.y;
    int t = threadIdx.x;

    __shared__ float sc[C_];
    for (int c = t; c < C_; c += 256) sc[c] = c2[(long)(v * B_ + b) * C_ + c];
    __syncthreads();

    float o[3];
    #pragma unroll
    for (int r = 0; r < 3; r++) {
        int co = t + r * 256;
        const float* wr = w + (long)v * C_ * C_ + (long)co * C_;
        float d0 = 0.f, d1 = 0.f, d2 = 0.f, d3 = 0.f;
        #pragma unroll 4
        for (int c = 0; c < C_; c += 4) {
            d0 += sc[c + 0] * wr[c + 0];
            d1 += sc[c + 1] * wr[c + 1];
            d2 += sc[c + 2] * wr[c + 2];
            d3 += sc[c + 3] * wr[c + 3];
        }
        o[r] = ((d0 + d1) + (d2 + d3)) + bias[v * C_ + co];
    }
    for (int n = 0; n < N_; n++) {
        long base = ((long)b * N_ + n) * (NVW * C_) + (long)v * C_;
        #pragma unroll
        for (int r = 0; r < 3; r++) out[base + t + r * 256] = o[r];
    }
}

// ---------------- launch ----------------
extern "C" void kernel_launch(void* const* d_in, const int* in_sizes, int n_in,
                              void* d_out, int out_size)
{
    const float* X        = (const float*)d_in[0];
    const float* norm1_g  = (const float*)d_in[1];
    const float* norm1_b  = (const float*)d_in[2];
    const float* qkv_w    = (const float*)d_in[3];
    const float* proj_w   = (const float*)d_in[4];
    const float* proj_b   = (const float*)d_in[5];
    const float* norm2_g  = (const float*)d_in[6];
    const float* norm2_b  = (const float*)d_in[7];
    const float* fc1_w    = (const float*)d_in[8];
    const float* fc1_b    = (const float*)d_in[9];
    const float* fc2_w    = (const float*)d_in[10];
    const float* fc2_b    = (const float*)d_in[11];
    const float* query    = (const float*)d_in[12];
    const float* mha_in_w = (const float*)d_in[13];
    const float* mha_in_b = (const float*)d_in[14];
    const float* mha_out_w= (const float*)d_in[15];
    const float* mha_out_b= (const float*)d_in[16];
    float* out = (float*)d_out;

    float *qkvb, *x, *kv, *qh, *c2;
    __nv_bfloat16 *XnH, *XnL, *ctxH, *ctxL, *hnH, *hnL, *h1H, *h1L, *x2H, *x2L;
    __nv_bfloat16 *WqkvH, *WqkvL, *WprjH, *WprjL, *Wf1H, *Wf1L, *Wf2H, *Wf2L, *WmhaH, *WmhaL;
    cudaGetSymbolAddress((void**)&qkvb, g_qkv);
    cudaGetSymbolAddress((void**)&x,    g_x);
    cudaGetSymbolAddress((void**)&kv,   g_kv);
    cudaGetSymbolAddress((void**)&qh,   g_qh);
    cudaGetSymbolAddress((void**)&c2,   g_c2);
    cudaGetSymbolAddress((void**)&XnH,  g_XnH);  cudaGetSymbolAddress((void**)&XnL,  g_XnL);
    cudaGetSymbolAddress((void**)&ctxH, g_ctxH); cudaGetSymbolAddress((void**)&ctxL, g_ctxL);
    cudaGetSymbolAddress((void**)&hnH,  g_hnH);  cudaGetSymbolAddress((void**)&hnL,  g_hnL);
    cudaGetSymbolAddress((void**)&h1H,  g_h1H);  cudaGetSymbolAddress((void**)&h1L,  g_h1L);
    cudaGetSymbolAddress((void**)&x2H,  g_x2H);  cudaGetSymbolAddress((void**)&x2L,  g_x2L);
    cudaGetSymbolAddress((void**)&WqkvH, g_WqkvH); cudaGetSymbolAddress((void**)&WqkvL, g_WqkvL);
    cudaGetSymbolAddress((void**)&WprjH, g_WprjH); cudaGetSymbolAddress((void**)&WprjL, g_WprjL);
    cudaGetSymbolAddress((void**)&Wf1H,  g_Wf1H);  cudaGetSymbolAddress((void**)&Wf1L,  g_Wf1L);
    cudaGetSymbolAddress((void**)&Wf2H,  g_Wf2H);  cudaGetSymbolAddress((void**)&Wf2L,  g_Wf2L);
    cudaGetSymbolAddress((void**)&WmhaH, g_WmhaH); cudaGetSymbolAddress((void**)&WmhaL, g_WmhaL);

    cudaFuncSetAttribute(gemm_mma, cudaFuncAttributeMaxDynamicSharedMemorySize,
                         GEMM_SMEM);

    const long MC  = (long)MROWS * C_;
    const long MH  = (long)MROWS * HID_;

    auto wsplit = [&](const float* src, __nv_bfloat16* hi, __nv_bfloat16* lo, long n) {
        int n4 = (int)(n / 4);
        wsplit_kernel<<<(n4 + 255) / 256, 256>>>(src, hi, lo, n4);
    };

    // 0. split all weights (independent; front of stream)
    wsplit(qkv_w,    WqkvH, WqkvL, (long)NVW * 3 * C_ * C_);
    wsplit(proj_w,   WprjH, WprjL, (long)NVW * C_ * C_);
    wsplit(fc1_w,    Wf1H,  Wf1L,  (long)NVW * HID_ * C_);
    wsplit(fc2_w,    Wf2H,  Wf2L,  (long)NVW * C_ * HID_);
    wsplit(mha_in_w, WmhaH, WmhaL, (long)NVW * 3 * C_ * C_);

    // 1. LN1 -> Xn hi/lo (remap [b*NV+v] -> [v][b])
    ln_kernel<<<NVW * B_ * N_, 256>>>(X, norm1_g, norm1_b, XnH, XnL, 1, 0);

    // 2. QKV GEMM -> f32 qkv
    gemm_mma<<<dim3(3 * C_ / 128, MROWS / 128, NVW), 256, GEMM_SMEM>>>(
        XnH, XnL, WqkvH, WqkvL, nullptr, nullptr, qkvb, nullptr, nullptr,
        C_, 3 * C_, MC, (long)3 * C_ * C_, 0, 0, (long)MROWS * 3 * C_, 1.0f, 0);

    // 3. pairwise attention, mean over j -> ctx hi/lo
    attn_kernel<<<dim3(H_, B_, NVW), 256>>>(qkvb, ctxH, ctxL);

    // 4. proj GEMM (alpha=2 folds residual doubling) -> f32 x
    gemm_mma<<<dim3(C_ / 128, MROWS / 128, NVW), 256, GEMM_SMEM>>>(
        ctxH, ctxL, WprjH, WprjL, proj_b, nullptr, x, nullptr, nullptr,
        C_, C_, MC, (long)C_ * C_, C_, 0, MC, 2.0f, 0);

    // 5. LN2 -> hn hi/lo
    ln_kernel<<<NVW * B_ * N_, 256>>>(x, norm2_g, norm2_b, hnH, hnL, 0, 1);

    // 6. fc1 GEMM + bias + GELU -> h1 hi/lo (bf16 out)
    gemm_mma<<<dim3(HID_ / 128, MROWS / 128, NVW), 256, GEMM_SMEM>>>(
        hnH, hnL, Wf1H, Wf1L, fc1_b, nullptr, nullptr, h1H, h1L,
        C_, HID_, MC, (long)HID_ * C_, HID_, 0, MH, 1.0f, 1);

    // 7. fc2 GEMM + bias + residual(x) -> x2 hi/lo (bf16 out)
    gemm_mma<<<dim3(C_ / 128, MROWS / 128, NVW), 256, GEMM_SMEM>>>(
        h1H, h1L, Wf2H, Wf2L, fc2_b, x, nullptr, x2H, x2L,
        HID_, C_, MH, (long)C_ * HID_, C_, MC, MC, 1.0f, 0);

    // 8. learnable query projection (f32 weights)
    qh_kernel<<<NVW, 256>>>(query, mha_in_w, mha_in_b, qh);

    // 9. K/V projection of x2 -> f32 kv (W rows [C,3C) of mha_in_w)
    gemm_mma<<<dim3(2 * C_ / 128, MROWS / 128, NVW), 256, GEMM_SMEM>>>(
        x2H, x2L, WmhaH + (long)C_ * C_, WmhaL + (long)C_ * C_,
        mha_in_b + C_, nullptr, kv, nullptr, nullptr,
        C_, 2 * C_, MC, (long)3 * C_ * C_, (long)3 * C_, 0,
        (long)MROWS * 2 * C_, 1.0f, 0);

    // 10. single-query cross attention -> c2[v][b][C]
    cross_attn_kernel<<<dim3(H_, B_, NVW), 256>>>(kv, qh, c2);

    // 11. output projection + broadcast over N
    out_kernel<<<dim3(NVW, B_), 256>>>(c2, mha_out_w, mha_out_b, out);
}

// round 12
// speedup vs baseline: 2.4272x; 1.3124x over previous
#include <cuda_runtime.h>
#include <cuda_bf16.h>
#include <math.h>
#include <stdint.h>

#define NVW 4
#define B_ 4
#define N_ 256
#define C_ 768
#define H_ 12
#define HD_ 64
#define HID_ 3072
#define MROWS (B_*N_)   // 1024 rows per view

// ---------------- scratch (device globals; no allocation) ----------------
__device__ float g_x  [NVW*MROWS*C_];
__device__ float g_kv [NVW*MROWS*2*C_];
__device__ float g_qh [NVW*C_];
__device__ float g_c2 [NVW*B_*C_];
// bf16 hi/lo activation planes
__device__ __nv_bfloat16 g_qkvH[NVW*MROWS*3*C_], g_qkvL[NVW*MROWS*3*C_];
__device__ __nv_bfloat16 g_XnH [NVW*MROWS*C_],  g_XnL [NVW*MROWS*C_];
__device__ __nv_bfloat16 g_ctxH[NVW*MROWS*C_],  g_ctxL[NVW*MROWS*C_];
__device__ __nv_bfloat16 g_hnH [NVW*MROWS*C_],  g_hnL [NVW*MROWS*C_];
__device__ __nv_bfloat16 g_h1H [NVW*MROWS*HID_],g_h1L [NVW*MROWS*HID_];
__device__ __nv_bfloat16 g_x2H [NVW*MROWS*C_],  g_x2L [NVW*MROWS*C_];
// bf16 hi/lo weight planes
__device__ __nv_bfloat16 g_WqkvH[NVW*3*C_*C_], g_WqkvL[NVW*3*C_*C_];
__device__ __nv_bfloat16 g_WprjH[NVW*C_*C_],   g_WprjL[NVW*C_*C_];
__device__ __nv_bfloat16 g_Wf1H [NVW*HID_*C_], g_Wf1L [NVW*HID_*C_];
__device__ __nv_bfloat16 g_Wf2H [NVW*C_*HID_], g_Wf2L [NVW*C_*HID_];
__device__ __nv_bfloat16 g_WmhaH[NVW*3*C_*C_], g_WmhaL[NVW*3*C_*C_];

__device__ __forceinline__ float gelu_exact(float x) {
    return 0.5f * x * (1.0f + erff(x * 0.70710678118654752f));
}

__device__ __forceinline__ void bfsplit(float x, __nv_bfloat16& h, __nv_bfloat16& l) {
    h = __float2bfloat16(x);
    l = __float2bfloat16(x - __bfloat162float(h));
}

__device__ __forceinline__ uint32_t bfpack(float a, float b) {
    __nv_bfloat16 ha = __float2bfloat16(a);
    __nv_bfloat16 hb = __float2bfloat16(b);
    uint16_t ua = *(uint16_t*)&ha, ub = *(uint16_t*)&hb;
    return ((uint32_t)ub << 16) | ua;
}

__device__ __forceinline__ uint32_t smem_u32(const void* p) {
    uint32_t a;
    asm("{ .reg .u64 t; cvta.to.shared.u64 t, %1; cvt.u32.u64 %0, t; }"
        : "=r"(a) : "l"(p));
    return a;
}

#define CP_ASYNC16(dst, src) \
    asm volatile("cp.async.ca.shared.global [%0], [%1], 16;" \
                 :: "r"(dst), "l"(src) : "memory")
#define CP_COMMIT() \
    asm volatile("cp.async.commit_group;" ::: "memory")
#define CP_WAIT2() \
    asm volatile("cp.async.wait_group 2;" ::: "memory")
#define CP_WAIT0() \
    asm volatile("cp.async.wait_group 0;" ::: "memory")

#define MMA_BF16(d, a, b) \
    asm volatile( \
        "mma.sync.aligned.m16n8k16.row.col.f32.bf16.bf16.f32 " \
        "{%0,%1,%2,%3}, {%4,%5,%6,%7}, {%8,%9}, {%0,%1,%2,%3};" \
        : "+f"((d)[0]), "+f"((d)[1]), "+f"((d)[2]), "+f"((d)[3]) \
        : "r"((a)[0]), "r"((a)[1]), "r"((a)[2]), "r"((a)[3]), \
          "r"((b)[0]), "r"((b)[1]))

// ---------------- weight split kernel (f32 -> bf16 hi/lo) ----------------
__global__ __launch_bounds__(256) void wsplit_kernel(
    const float* __restrict__ src, __nv_bfloat16* __restrict__ hi,
    __nv_bfloat16* __restrict__ lo, int n4)
{
    int i = blockIdx.x * 256 + threadIdx.x;
    if (i >= n4) return;
    float4 s = ((const float4*)src)[i];
    __nv_bfloat16 h0, h1, h2, h3, l0, l1, l2, l3;
    bfsplit(s.x, h0, l0); bfsplit(s.y, h1, l1);
    bfsplit(s.z, h2, l2); bfsplit(s.w, h3, l3);
    __nv_bfloat162* H = (__nv_bfloat162*)hi;
    __nv_bfloat162* L = (__nv_bfloat162*)lo;
    H[2*i]   = __nv_bfloat162{h0, h1};
    H[2*i+1] = __nv_bfloat162{h2, h3};
    L[2*i]   = __nv_bfloat162{l0, l1};
    L[2*i+1] = __nv_bfloat162{l2, l3};
}

// ---------------- LayerNorm -> bf16 hi/lo planes ----------------
__global__ __launch_bounds__(256) void ln_kernel(
    const float* __restrict__ X, const float* __restrict__ g,
    const float* __restrict__ be, __nv_bfloat16* __restrict__ YH,
    __nv_bfloat16* __restrict__ YL, int remap, int pervw)
{
    int r = blockIdx.x;
    int v = r / (B_ * N_);
    long inrow;
    if (remap) {
        int rem = r % (B_ * N_);
        int bb = rem / N_;
        int n  = rem % N_;
        inrow = ((long)(bb * NVW + v) * N_ + n);
    } else {
        inrow = r;
    }
    const float* x = X + inrow * C_;
    long obase = (long)r * C_;
    const float* gg = g  + (pervw ? v * C_ : 0);
    const float* bb2 = be + (pervw ? v * C_ : 0);

    int t = threadIdx.x;
    float v0 = x[t], v1 = x[t + 256], v2 = x[t + 512];
    float s  = v0 + v1 + v2;
    float sq = v0 * v0 + v1 * v1 + v2 * v2;

    __shared__ float rs[256], rq[256];
    rs[t] = s; rq[t] = sq;
    __syncthreads();
    for (int off = 128; off > 0; off >>= 1) {
        if (t < off) { rs[t] += rs[t + off]; rq[t] += rq[t + off]; }
        __syncthreads();
    }
    float mean = rs[0] * (1.0f / C_);
    float var  = rq[0] * (1.0f / C_) - mean * mean;
    float rstd = rsqrtf(var + 1e-6f);

    #pragma unroll
    for (int rr = 0; rr < 3; rr++) {
        int c = t + rr * 256;
        float val = (rr == 0 ? v0 : (rr == 1 ? v1 : v2));
        float y = (val - mean) * rstd * gg[c] + bb2[c];
        __nv_bfloat16 h, l;
        bfsplit(y, h, l);
        YH[obase + c] = h;
        YL[obase + c] = l;
    }
}

// ---------------- 3xBF16 mma.sync batched NT GEMM ----------------
#define KC 32
#define RSU 20
#define TILE_U (128 * RSU)
#define NSTAGE 4
#define GEMM_SMEM (NSTAGE * 4 * TILE_U * 4)

__global__ void __launch_bounds__(256, 1)
gemm_mma(const __nv_bfloat16* __restrict__ Ah, const __nv_bfloat16* __restrict__ Al,
         const __nv_bfloat16* __restrict__ Wh, const __nv_bfloat16* __restrict__ Wl,
         const float* __restrict__ bias, const float* __restrict__ res,
         float* __restrict__ Cf,
         __nv_bfloat16* __restrict__ CH, __nv_bfloat16* __restrict__ CL,
         int Kdim, int D,
         long sA, long sW, long sB, long sR, long sC, float alpha, int act)
{
    extern __shared__ uint32_t smu[];
    const int v = blockIdx.z;
    const int bm = blockIdx.y * 128, bn = blockIdx.x * 128;

    const int t = threadIdx.x, lane = t & 31, wid = t >> 5;
    const int wm = (wid >> 2) * 64;
    const int wn = (wid & 3) * 32;
    const int fr = lane >> 2;
    const int fk = lane & 3;

    const int crow = t & 127;
    const int sel  = t >> 7;
    const __nv_bfloat16* gA = (sel ? Al : Ah) + (long)v * sA + (long)(bm + crow) * Kdim;
    const __nv_bfloat16* gW = (sel ? Wl : Wh) + (long)v * sW + (long)(bn + crow) * Kdim;
    const uint32_t sbase = smem_u32(smu);
    const uint32_t so0 = (uint32_t)(((sel)     * TILE_U + crow * RSU) * 4);
    const uint32_t so1 = (uint32_t)(((2 + sel) * TILE_U + crow * RSU) * 4);

    float acc[4][4][4];
    #pragma unroll
    for (int a = 0; a < 4; a++)
        #pragma unroll
        for (int b = 0; b < 4; b++)
            #pragma unroll
            for (int c = 0; c < 4; c++) acc[a][b][c] = 0.0f;

    const int steps = Kdim / KC;

    #pragma unroll
    for (int p = 0; p < 3; p++) {
        if (p < steps) {
            uint32_t st = sbase + (uint32_t)((p & 3) * 4 * TILE_U * 4);
            const char* a8 = (const char*)gA + p * 64;
            const char* w8 = (const char*)gW + p * 64;
            #pragma unroll
            for (int i = 0; i < 4; i++) {
                CP_ASYNC16(st + so0 + i * 16, a8 + i * 16);
                CP_ASYNC16(st + so1 + i * 16, w8 + i * 16);
            }
        }
        CP_COMMIT();
    }

    for (int c = 0; c < steps; c++) {
        CP_WAIT2();
        __syncthreads();

        int p = c + 3;
        if (p < steps) {
            uint32_t st = sbase + (uint32_t)((p & 3) * 4 * TILE_U * 4);
            const char* a8 = (const char*)gA + p * 64;
            const char* w8 = (const char*)gW + p * 64;
            #pragma unroll
            for (int i = 0; i < 4; i++) {
                CP_ASYNC16(st + so0 + i * 16, a8 + i * 16);
                CP_ASYNC16(st + so1 + i * 16, w8 + i * 16);
            }
        }
        CP_COMMIT();

        const uint32_t* S   = smu + (c & 3) * 4 * TILE_U;
        const uint32_t* AhS = S;
        const uint32_t* AlS = S + TILE_U;
        const uint32_t* WhS = S + 2 * TILE_U;
        const uint32_t* WlS = S + 3 * TILE_U;

        #pragma unroll
        for (int s = 0; s < 2; s++) {
            int ko = s * 8 + fk;
            uint32_t ah[4][4], al[4][4], bh[4][2], bl[4][2];
            #pragma unroll
            for (int mt = 0; mt < 4; mt++) {
                int r0 = wm + mt * 16 + fr;
                ah[mt][0] = AhS[(r0    ) * RSU + ko];
                ah[mt][1] = AhS[(r0 + 8) * RSU + ko];
                ah[mt][2] = AhS[(r0    ) * RSU + ko + 4];
                ah[mt][3] = AhS[(r0 + 8) * RSU + ko + 4];
                al[mt][0] = AlS[(r0    ) * RSU + ko];
                al[mt][1] = AlS[(r0 + 8) * RSU + ko];
                al[mt][2] = AlS[(r0    ) * RSU + ko + 4];
                al[mt][3] = AlS[(r0 + 8) * RSU + ko + 4];
            }
            #pragma unroll
            for (int nt = 0; nt < 4; nt++) {
                int n0 = wn + nt * 8 + fr;
                bh[nt][0] = WhS[n0 * RSU + ko];
                bh[nt][1] = WhS[n0 * RSU + ko + 4];
                bl[nt][0] = WlS[n0 * RSU + ko];
                bl[nt][1] = WlS[n0 * RSU + ko + 4];
            }
            #pragma unroll
            for (int mt = 0; mt < 4; mt++)
                #pragma unroll
                for (int nt = 0; nt < 4; nt++)
                    MMA_BF16(acc[mt][nt], ah[mt], bh[nt]);
            #pragma unroll
            for (int mt = 0; mt < 4; mt++)
                #pragma unroll
                for (int nt = 0; nt < 4; nt++)
                    MMA_BF16(acc[mt][nt], ah[mt], bl[nt]);
            #pragma unroll
            for (int mt = 0; mt < 4; mt++)
                #pragma unroll
                for (int nt = 0; nt < 4; nt++)
                    MMA_BF16(acc[mt][nt], al[mt], bh[nt]);
        }
    }

    __syncthreads();

    #pragma unroll
    for (int mt = 0; mt < 4; mt++) {
        #pragma unroll
        for (int nt = 0; nt < 4; nt++) {
            int row = bm + wm + mt * 16 + fr;
            int col = bn + wn + nt * 8 + 2 * fk;
            float b0 = 0.f, b1 = 0.f;
            if (bias) {
                b0 = bias[(long)v * sB + col];
                b1 = bias[(long)v * sB + col + 1];
            }
            #pragma unroll
            for (int half = 0; half < 2; half++) {
                int r = row + half * 8;
                float v0 = alpha * (acc[mt][nt][half * 2 + 0] + b0);
                float v1 = alpha * (acc[mt][nt][half * 2 + 1] + b1);
                if (act == 1) { v0 = gelu_exact(v0); v1 = gelu_exact(v1); }
                if (res) {
                    v0 += res[(long)v * sR + (long)r * D + col];
                    v1 += res[(long)v * sR + (long)r * D + col + 1];
                }
                long off = (long)v * sC + (long)r * D + col;
                if (Cf) {
                    float2 o2 = {v0, v1};
                    *(float2*)&Cf[off] = o2;
                } else {
                    __nv_bfloat16 h0, h1, l0, l1;
                    bfsplit(v0, h0, l0);
                    bfsplit(v1, h1, l1);
                    *(__nv_bfloat162*)&CH[off] = __nv_bfloat162{h0, h1};
                    *(__nv_bfloat162*)&CL[off] = __nv_bfloat162{l0, l1};
                }
            }
        }
    }
}

// ---------------- MMA flash attention: pairwise cross-view, mean over j ----
// CTA = (h, b, i). 8 warps x 32 query rows. 3-term bf16 MMA for S and P*V.
// smem (u32): Qh 9216 | Ql 9216 | Kh 2304 | Kl 2304 | VTh 2304 | VTl 2304 |
//             VRh 2304 | VRl 2304  = 32256 u32 = 129024 B
#define ATTN_SMEM (32256 * 4)

__global__ void __launch_bounds__(256, 1)
attn_mma(const __nv_bfloat16* __restrict__ qkvH,
         const __nv_bfloat16* __restrict__ qkvL,
         __nv_bfloat16* __restrict__ ctxH, __nv_bfloat16* __restrict__ ctxL)
{
    const int h = blockIdx.x, b = blockIdx.y, iv = blockIdx.z;
    const int t = threadIdx.x, lane = t & 31, wid = t >> 5;
    const int fr = lane >> 2, fk = lane & 3;
    const int wm = wid * 32;
    const int D3 = 3 * C_;

    extern __shared__ uint32_t sa[];
    uint32_t* Qs[2] = { sa,          sa + 9216 };
    uint32_t* Ks[2] = { sa + 18432,  sa + 20736 };
    uint32_t* VT[2] = { sa + 23040,  sa + 25344 };
    uint32_t* VR[2] = { sa + 27648,  sa + 29952 };
    const uint32_t sb = smem_u32(sa);

    const long rowQ = (long)(iv * B_ + b) * N_;

    // ---- stage Q (256 rows x 64 bf16, hi+lo) ----
    #pragma unroll
    for (int p = 0; p < 2; p++) {
        const __nv_bfloat16* src = (p ? qkvL : qkvH) + rowQ * D3 + h * HD_;
        uint32_t dstb = sb + (uint32_t)(p ? 9216 * 4 : 0);
        #pragma unroll
        for (int i = 0; i < 8; i++) {
            int lin = i * 256 + t;
            int row = lin >> 3, seg = lin & 7;
            CP_ASYNC16(dstb + row * 144 + seg * 16,
                       (const char*)(src + (long)row * D3) + seg * 16);
        }
    }
    CP_COMMIT();

    float outacc[2][8][4];
    #pragma unroll
    for (int a = 0; a < 2; a++)
        #pragma unroll
        for (int n = 0; n < 8; n++)
            #pragma unroll
            for (int q = 0; q < 4; q++) outacc[a][n][q] = 0.f;

    for (int j = 0; j < NVW; j++) {
        const long rowK = (long)(j * B_ + b) * N_;
        float m_[2][2] = {{-1e30f, -1e30f}, {-1e30f, -1e30f}};
        float l_[2][2] = {{0.f, 0.f}, {0.f, 0.f}};
        float cacc[2][8][4];
        #pragma unroll
        for (int a = 0; a < 2; a++)
            #pragma unroll
            for (int n = 0; n < 8; n++)
                #pragma unroll
                for (int q = 0; q < 4; q++) cacc[a][n][q] = 0.f;

        for (int kc = 0; kc < 4; kc++) {
            __syncthreads();
            // stage K + V-raw (hi/lo)
            #pragma unroll
            for (int p = 0; p < 2; p++) {
                const __nv_bfloat16* gk = (p ? qkvL : qkvH)
                    + (rowK + kc * 64) * D3 + C_ + h * HD_;
                const __nv_bfloat16* gv = (p ? qkvL : qkvH)
                    + (rowK + kc * 64) * D3 + 2 * C_ + h * HD_;
                uint32_t kb = sb + (uint32_t)((18432 + p * 2304) * 4);
                uint32_t vb = sb + (uint32_t)((27648 + p * 2304) * 4);
                #pragma unroll
                for (int i = 0; i < 2; i++) {
                    int lin = i * 256 + t;
                    int row = lin >> 3, seg = lin & 7;
                    CP_ASYNC16(kb + row * 144 + seg * 16,
                               (const char*)(gk + (long)row * D3) + seg * 16);
                    CP_ASYNC16(vb + row * 144 + seg * 16,
                               (const char*)(gv + (long)row * D3) + seg * 16);
                }
            }
            CP_COMMIT();
            CP_WAIT0();
            __syncthreads();

            // transpose V-raw [key][colpair] -> VT [col][keypair]
            #pragma unroll
            for (int p = 0; p < 2; p++) {
                const uint32_t* R = VR[p];
                uint32_t* T = VT[p];
                #pragma unroll
                for (int i = 0; i < 4; i++) {
                    int lin = i * 256 + t;       // 0..1023
                    int kp = lin >> 5, cp = lin & 31;
                    uint32_t r0 = R[(2 * kp) * 36 + cp];
                    uint32_t r1 = R[(2 * kp + 1) * 36 + cp];
                    T[(2 * cp) * 36 + kp]     = (r0 & 0xffffu) | (r1 << 16);
                    T[(2 * cp + 1) * 36 + kp] = (r0 >> 16) | (r1 & 0xffff0000u);
                }
            }
            __syncthreads();

            // ---- S = Q K^T (3-term bf16) ----
            float sacc[2][8][4];
            #pragma unroll
            for (int a = 0; a < 2; a++)
                #pragma unroll
                for (int n = 0; n < 8; n++)
                    #pragma unroll
                    for (int q = 0; q < 4; q++) sacc[a][n][q] = 0.f;

            #pragma unroll
            for (int kt = 0; kt < 4; kt++) {
                uint32_t qh_[2][4], ql_[2][4];
                #pragma unroll
                for (int mt = 0; mt < 2; mt++) {
                    int r0 = wm + mt * 16 + fr;
                    int i0 = r0 * 36 + kt * 8 + fk;
                    int i1 = (r0 + 8) * 36 + kt * 8 + fk;
                    qh_[mt][0] = Qs[0][i0];
                    qh_[mt][1] = Qs[0][i1];
                    qh_[mt][2] = Qs[0][i0 + 4];
                    qh_[mt][3] = Qs[0][i1 + 4];
                    ql_[mt][0] = Qs[1][i0];
                    ql_[mt][1] = Qs[1][i1];
                    ql_[mt][2] = Qs[1][i0 + 4];
                    ql_[mt][3] = Qs[1][i1 + 4];
                }
                #pragma unroll
                for (int nt = 0; nt < 8; nt++) {
                    int ib = (nt * 8 + fr) * 36 + kt * 8 + fk;
                    uint32_t kh_[2] = { Ks[0][ib], Ks[0][ib + 4] };
                    uint32_t kl_[2] = { Ks[1][ib], Ks[1][ib + 4] };
                    #pragma unroll
                    for (int mt = 0; mt < 2; mt++) {
                        MMA_BF16(sacc[mt][nt], qh_[mt], kh_);
                        MMA_BF16(sacc[mt][nt], qh_[mt], kl_);
                        MMA_BF16(sacc[mt][nt], ql_[mt], kh_);
                    }
                }
            }
            #pragma unroll
            for (int a = 0; a < 2; a++)
                #pragma unroll
                for (int n = 0; n < 8; n++)
                    #pragma unroll
                    for (int q = 0; q < 4; q++) sacc[a][n][q] *= 0.125f;

            // ---- online softmax (rows spread across fk quad) ----
            #pragma unroll
            for (int mt = 0; mt < 2; mt++) {
                #pragma unroll
                for (int hf = 0; hf < 2; hf++) {
                    float cm = -1e30f;
                    #pragma unroll
                    for (int nt = 0; nt < 8; nt++)
                        cm = fmaxf(cm, fmaxf(sacc[mt][nt][hf*2], sacc[mt][nt][hf*2+1]));
                    cm = fmaxf(cm, __shfl_xor_sync(0xffffffffu, cm, 1));
                    cm = fmaxf(cm, __shfl_xor_sync(0xffffffffu, cm, 2));
                    float mo = m_[mt][hf];
                    float mn = fmaxf(mo, cm);
                    float corr = __expf(mo - mn);
                    m_[mt][hf] = mn;
                    float ps = 0.f;
                    #pragma unroll
                    for (int nt = 0; nt < 8; nt++) {
                        float p0 = __expf(sacc[mt][nt][hf*2]   - mn);
                        float p1 = __expf(sacc[mt][nt][hf*2+1] - mn);
                        sacc[mt][nt][hf*2]   = p0;
                        sacc[mt][nt][hf*2+1] = p1;
                        ps += p0 + p1;
                    }
                    ps += __shfl_xor_sync(0xffffffffu, ps, 1);
                    ps += __shfl_xor_sync(0xffffffffu, ps, 2);
                    l_[mt][hf] = l_[mt][hf] * corr + ps;
                    #pragma unroll
                    for (int nt = 0; nt < 8; nt++) {
                        cacc[mt][nt][hf*2]   *= corr;
                        cacc[mt][nt][hf*2+1] *= corr;
                    }
                }
            }

            // ---- ctx += P V (3-term; P frags from sacc registers) ----
            #pragma unroll
            for (int ktk = 0; ktk < 4; ktk++) {
                uint32_t ph_[2][4], pl_[2][4];
                #pragma unroll
                for (int mt = 0; mt < 2; mt++) {
                    #pragma unroll
                    for (int q = 0; q < 4; q++) {
                        int nt = 2 * ktk + (q >> 1);
                        int base = (q & 1) * 2;
                        float p0 = sacc[mt][nt][base];
                        float p1 = sacc[mt][nt][base + 1];
                        __nv_bfloat16 h0 = __float2bfloat16(p0);
                        __nv_bfloat16 h1 = __float2bfloat16(p1);
                        float r0 = p0 - __bfloat162float(h0);
                        float r1 = p1 - __bfloat162float(h1);
                        uint16_t u0 = *(uint16_t*)&h0, u1 = *(uint16_t*)&h1;
                        ph_[mt][q] = ((uint32_t)u1 << 16) | u0;
                        pl_[mt][q] = bfpack(r0, r1);
                    }
                }
                #pragma unroll
                for (int nc = 0; nc < 8; nc++) {
                    int ib = (nc * 8 + fr) * 36 + ktk * 8 + fk;
                    uint32_t vh_[2] = { VT[0][ib], VT[0][ib + 4] };
                    uint32_t vl_[2] = { VT[1][ib], VT[1][ib + 4] };
                    #pragma unroll
                    for (int mt = 0; mt < 2; mt++) {
                        MMA_BF16(cacc[mt][nc], ph_[mt], vh_);
                        MMA_BF16(cacc[mt][nc], ph_[mt], vl_);
                        MMA_BF16(cacc[mt][nc], pl_[mt], vh_);
                    }
                }
            }
        } // kc

        // fold per-j normalized ctx into output accumulator (mean over j)
        #pragma unroll
        for (int mt = 0; mt < 2; mt++)
            #pragma unroll
            for (int hf = 0; hf < 2; hf++) {
                float inv = 0.25f / l_[mt][hf];
                #pragma unroll
                for (int nt = 0; nt < 8; nt++) {
                    outacc[mt][nt][hf*2]   += cacc[mt][nt][hf*2]   * inv;
                    outacc[mt][nt][hf*2+1] += cacc[mt][nt][hf*2+1] * inv;
                }
            }
    } // j

    // write ctx hi/lo planes
    #pragma unroll
    for (int mt = 0; mt < 2; mt++) {
        #pragma unroll
        for (int hf = 0; hf < 2; hf++) {
            int row = wm + mt * 16 + fr + hf * 8;
            long obase = (rowQ + row) * C_ + h * HD_;
            #pragma unroll
            for (int nt = 0; nt < 8; nt++) {
                float v0 = outacc[mt][nt][hf*2];
                float v1 = outacc[mt][nt][hf*2+1];
                __nv_bfloat16 h0, l0, h1, l1;
                bfsplit(v0, h0, l0);
                bfsplit(v1, h1, l1);
                int col = nt * 8 + 2 * fk;
                *(__nv_bfloat162*)&ctxH[obase + col] = __nv_bfloat162{h0, h1};
                *(__nv_bfloat162*)&ctxL[obase + col] = __nv_bfloat162{l0, l1};
            }
        }
    }
}

// ---------------- learnable-query projection ----------------
__global__ __launch_bounds__(256) void qh_kernel(
    const float* __restrict__ query, const float* __restrict__ w,
    const float* __restrict__ bq, float* __restrict__ qh)
{
    int v = blockIdx.x;
    int t = threadIdx.x;
    for (int d = t; d < C_; d += 256) {
        const float* wr = w + (long)v * (3 * C_) * C_ + (long)d * C_;
        float acc = 0.0f;
        #pragma unroll 4
        for (int c = 0; c < C_; c++) acc += query[c] * wr[c];
        qh[v * C_ + d] = acc + bq[(long)v * (3 * C_) + d];
    }
}

// ---------------- cross attention (single query) ----------------
__global__ __launch_bounds__(256) void cross_attn_kernel(
    const float* __restrict__ kv, const float* __restrict__ qh,
    float* __restrict__ c2)
{
    int h = blockIdx.x, b = blockIdx.y, v = blockIdx.z;
    int t = threadIdx.x;

    __shared__ float p[256];
    __shared__ float red[256];
    __shared__ float part[4][64];

    const float* kvb = kv + ((long)(v * B_ + b) * N_) * (2 * C_);
    const float* qhp = qh + v * C_ + h * HD_;
    const float* krow = kvb + (long)t * (2 * C_) + h * HD_;

    float s = 0.0f;
    #pragma unroll
    for (int e = 0; e < 64; e++) s += qhp[e] * krow[e];
    s *= 0.125f;

    red[t] = s; __syncthreads();
    for (int off = 128; off > 0; off >>= 1) {
        if (t < off) red[t] = fmaxf(red[t], red[t + off]);
        __syncthreads();
    }
    float mx = red[0];
    __syncthreads();

    float e_ = __expf(s - mx);
    p[t] = e_; red[t] = e_;
    __syncthreads();
    for (int off = 128; off > 0; off >>= 1) {
        if (t < off) red[t] += red[t + off];
        __syncthreads();
    }
    float inv = 1.0f / red[0];
    __syncthreads();

    int e = t & 63, pid = t >> 6;
    float acc = 0.0f;
    for (int n = pid * 64; n < pid * 64 + 64; n++)
        acc += p[n] * kvb[(long)n * (2 * C_) + C_ + h * HD_ + e];
    part[pid][e] = acc;
    __syncthreads();
    if (t < 64) {
        float r = (part[0][t] + part[1][t]) + (part[2][t] + part[3][t]);
        c2[(long)(v * B_ + b) * C_ + h * HD_ + t] = r * inv;
    }
}

// ---------------- output projection + broadcast over N ----------------
__global__ __launch_bounds__(256) void out_kernel(
    const float* __restrict__ c2, const float* __restrict__ w,
    const float* __restrict__ bias, float* __restrict__ out)
{
    int v = blockIdx.x, b = blockIdx.y;
    int t = threadIdx.x;

    __shared__ float sc[C_];
    for (int c = t; c < C_; c += 256) sc[c] = c2[(long)(v * B_ + b) * C_ + c];
    __syncthreads();

    float o[3];
    #pragma unroll
    for (int r = 0; r < 3; r++) {
        int co = t + r * 256;
        const float* wr = w + (long)v * C_ * C_ + (long)co * C_;
        float d0 = 0.f, d1 = 0.f, d2 = 0.f, d3 = 0.f;
        #pragma unroll 4
        for (int c = 0; c < C_; c += 4) {
            d0 += sc[c + 0] * wr[c + 0];
            d1 += sc[c + 1] * wr[c + 1];
            d2 += sc[c + 2] * wr[c + 2];
            d3 += sc[c + 3] * wr[c + 3];
        }
        o[r] = ((d0 + d1) + (d2 + d3)) + bias[v * C_ + co];
    }
    for (int n = 0; n < N_; n++) {
        long base = ((long)b * N_ + n) * (NVW * C_) + (long)v * C_;
        #pragma unroll
        for (int r = 0; r < 3; r++) out[base + t + r * 256] = o[r];
    }
}

// ---------------- launch ----------------
extern "C" void kernel_launch(void* const* d_in, const int* in_sizes, int n_in,
                              void* d_out, int out_size)
{
    const float* X        = (const float*)d_in[0];
    const float* norm1_g  = (const float*)d_in[1];
    const float* norm1_b  = (const float*)d_in[2];
    const float* qkv_w    = (const float*)d_in[3];
    const float* proj_w   = (const float*)d_in[4];
    const float* proj_b   = (const float*)d_in[5];
    const float* norm2_g  = (const float*)d_in[6];
    const float* norm2_b  = (const float*)d_in[7];
    const float* fc1_w    = (const float*)d_in[8];
    const float* fc1_b    = (const float*)d_in[9];
    const float* fc2_w    = (const float*)d_in[10];
    const float* fc2_b    = (const float*)d_in[11];
    const float* query    = (const float*)d_in[12];
    const float* mha_in_w = (const float*)d_in[13];
    const float* mha_in_b = (const float*)d_in[14];
    const float* mha_out_w= (const float*)d_in[15];
    const float* mha_out_b= (const float*)d_in[16];
    float* out = (float*)d_out;

    float *x, *kv, *qh, *c2;
    __nv_bfloat16 *qkvH, *qkvL, *XnH, *XnL, *ctxH, *ctxL, *hnH, *hnL, *h1H, *h1L, *x2H, *x2L;
    __nv_bfloat16 *WqkvH, *WqkvL, *WprjH, *WprjL, *Wf1H, *Wf1L, *Wf2H, *Wf2L, *WmhaH, *WmhaL;
    cudaGetSymbolAddress((void**)&x,    g_x);
    cudaGetSymbolAddress((void**)&kv,   g_kv);
    cudaGetSymbolAddress((void**)&qh,   g_qh);
    cudaGetSymbolAddress((void**)&c2,   g_c2);
    cudaGetSymbolAddress((void**)&qkvH, g_qkvH); cudaGetSymbolAddress((void**)&qkvL, g_qkvL);
    cudaGetSymbolAddress((void**)&XnH,  g_XnH);  cudaGetSymbolAddress((void**)&XnL,  g_XnL);
    cudaGetSymbolAddress((void**)&ctxH, g_ctxH); cudaGetSymbolAddress((void**)&ctxL, g_ctxL);
    cudaGetSymbolAddress((void**)&hnH,  g_hnH);  cudaGetSymbolAddress((void**)&hnL,  g_hnL);
    cudaGetSymbolAddress((void**)&h1H,  g_h1H);  cudaGetSymbolAddress((void**)&h1L,  g_h1L);
    cudaGetSymbolAddress((void**)&x2H,  g_x2H);  cudaGetSymbolAddress((void**)&x2L,  g_x2L);
    cudaGetSymbolAddress((void**)&WqkvH, g_WqkvH); cudaGetSymbolAddress((void**)&WqkvL, g_WqkvL);
    cudaGetSymbolAddress((void**)&WprjH, g_WprjH); cudaGetSymbolAddress((void**)&WprjL, g_WprjL);
    cudaGetSymbolAddress((void**)&Wf1H,  g_Wf1H);  cudaGetSymbolAddress((void**)&Wf1L,  g_Wf1L);
    cudaGetSymbolAddress((void**)&Wf2H,  g_Wf2H);  cudaGetSymbolAddress((void**)&Wf2L,  g_Wf2L);
    cudaGetSymbolAddress((void**)&WmhaH, g_WmhaH); cudaGetSymbolAddress((void**)&WmhaL, g_WmhaL);

    cudaFuncSetAttribute(gemm_mma, cudaFuncAttributeMaxDynamicSharedMemorySize,
                         GEMM_SMEM);
    cudaFuncSetAttribute(attn_mma, cudaFuncAttributeMaxDynamicSharedMemorySize,
                         ATTN_SMEM);

    const long MC  = (long)MROWS * C_;
    const long MH  = (long)MROWS * HID_;

    auto wsplit = [&](const float* src, __nv_bfloat16* hi, __nv_bfloat16* lo, long n) {
        int n4 = (int)(n / 4);
        wsplit_kernel<<<(n4 + 255) / 256, 256>>>(src, hi, lo, n4);
    };

    // 0. split all weights
    wsplit(qkv_w,    WqkvH, WqkvL, (long)NVW * 3 * C_ * C_);
    wsplit(proj_w,   WprjH, WprjL, (long)NVW * C_ * C_);
    wsplit(fc1_w,    Wf1H,  Wf1L,  (long)NVW * HID_ * C_);
    wsplit(fc2_w,    Wf2H,  Wf2L,  (long)NVW * C_ * HID_);
    wsplit(mha_in_w, WmhaH, WmhaL, (long)NVW * 3 * C_ * C_);

    // 1. LN1 -> Xn hi/lo (remap [b*NV+v] -> [v][b])
    ln_kernel<<<NVW * B_ * N_, 256>>>(X, norm1_g, norm1_b, XnH, XnL, 1, 0);

    // 2. QKV GEMM -> bf16 hi/lo qkv planes
    gemm_mma<<<dim3(3 * C_ / 128, MROWS / 128, NVW), 256, GEMM_SMEM>>>(
        XnH, XnL, WqkvH, WqkvL, nullptr, nullptr, nullptr, qkvH, qkvL,
        C_, 3 * C_, MC, (long)3 * C_ * C_, 0, 0, (long)MROWS * 3 * C_, 1.0f, 0);

    // 3. MMA flash attention, mean over j -> ctx hi/lo
    attn_mma<<<dim3(H_, B_, NVW), 256, ATTN_SMEM>>>(qkvH, qkvL, ctxH, ctxL);

    // 4. proj GEMM (alpha=2 folds residual doubling) -> f32 x
    gemm_mma<<<dim3(C_ / 128, MROWS / 128, NVW), 256, GEMM_SMEM>>>(
        ctxH, ctxL, WprjH, WprjL, proj_b, nullptr, x, nullptr, nullptr,
        C_, C_, MC, (long)C_ * C_, C_, 0, MC, 2.0f, 0);

    // 5. LN2 -> hn hi/lo
    ln_kernel<<<NVW * B_ * N_, 256>>>(x, norm2_g, norm2_b, hnH, hnL, 0, 1);

    // 6. fc1 GEMM + bias + GELU -> h1 hi/lo
    gemm_mma<<<dim3(HID_ / 128, MROWS / 128, NVW), 256, GEMM_SMEM>>>(
        hnH, hnL, Wf1H, Wf1L, fc1_b, nullptr, nullptr, h1H, h1L,
        C_, HID_, MC, (long)HID_ * C_, HID_, 0, MH, 1.0f, 1);

    // 7. fc2 GEMM + bias + residual(x) -> x2 hi/lo
    gemm_mma<<<dim3(C_ / 128, MROWS / 128, NVW), 256, GEMM_SMEM>>>(
        h1H, h1L, Wf2H, Wf2L, fc2_b, x, nullptr, x2H, x2L,
        HID_, C_, MH, (long)C_ * HID_, C_, MC, MC, 1.0f, 0);

    // 8. learnable query projection (f32 weights)
    qh_kernel<<<NVW, 256>>>(query, mha_in_w, mha_in_b, qh);

    // 9. K/V projection of x2 -> f32 kv (W rows [C,3C) of mha_in_w)
    gemm_mma<<<dim3(2 * C_ / 128, MROWS / 128, NVW), 256, GEMM_SMEM>>>(
        x2H, x2L, WmhaH + (long)C_ * C_, WmhaL + (long)C_ * C_,
        mha_in_b + C_, nullptr, kv, nullptr, nullptr,
        C_, 2 * C_, MC, (long)3 * C_ * C_, (long)3 * C_, 0,
        (long)MROWS * 2 * C_, 1.0f, 0);

    // 10. single-query cross attention -> c2[v][b][C]
    cross_attn_kernel<<<dim3(H_, B_, NVW), 256>>>(kv, qh, c2);

    // 11. output projection + broadcast over N
    out_kernel<<<dim3(NVW, B_), 256>>>(c2, mha_out_w, mha_out_b, out);
}

// round 13
// speedup vs baseline: 3.5132x; 1.4474x over previous
#include <cuda_runtime.h>
#include <cuda_bf16.h>
#include <cuda_fp16.h>
#include <math.h>
#include <stdint.h>

#define NVW 4
#define B_ 4
#define N_ 256
#define C_ 768
#define H_ 12
#define HD_ 64
#define HID_ 3072
#define MROWS (B_*N_)   // 1024 rows per view

// ---------------- scratch (device globals; no allocation) ----------------
__device__ float g_x  [NVW*MROWS*C_];
__device__ float g_kv [NVW*MROWS*2*C_];
__device__ float g_qh [NVW*C_];
__device__ float g_c2 [NVW*B_*C_];
// bf16 hi/lo qkv planes (consumed by 3-term attention)
__device__ __nv_bfloat16 g_qkvH[NVW*MROWS*3*C_], g_qkvL[NVW*MROWS*3*C_];
// fp16 single-plane activations
__device__ __half g_XnF [NVW*MROWS*C_];
__device__ __half g_ctxF[NVW*MROWS*C_];
__device__ __half g_hnF [NVW*MROWS*C_];
__device__ __half g_h1F [NVW*MROWS*HID_];
__device__ __half g_x2F [NVW*MROWS*C_];
// fp16 hi/lo weight planes
__device__ __half g_WqkvH[NVW*3*C_*C_], g_WqkvL[NVW*3*C_*C_];
__device__ __half g_WprjH[NVW*C_*C_],   g_WprjL[NVW*C_*C_];
__device__ __half g_Wf1H [NVW*HID_*C_], g_Wf1L [NVW*HID_*C_];
__device__ __half g_Wf2H [NVW*C_*HID_], g_Wf2L [NVW*C_*HID_];
__device__ __half g_WmhaH[NVW*3*C_*C_], g_WmhaL[NVW*3*C_*C_];

__device__ __forceinline__ float gelu_exact(float x) {
    return 0.5f * x * (1.0f + erff(x * 0.70710678118654752f));
}

__device__ __forceinline__ void bfsplit(float x, __nv_bfloat16& h, __nv_bfloat16& l) {
    h = __float2bfloat16(x);
    l = __float2bfloat16(x - __bfloat162float(h));
}

__device__ __forceinline__ void hsplit(float x, __half& h, __half& l) {
    h = __float2half(x);
    l = __float2half(x - __half2float(h));
}

__device__ __forceinline__ uint32_t bfpack(float a, float b) {
    __nv_bfloat16 ha = __float2bfloat16(a);
    __nv_bfloat16 hb = __float2bfloat16(b);
    uint16_t ua = *(uint16_t*)&ha, ub = *(uint16_t*)&hb;
    return ((uint32_t)ub << 16) | ua;
}

__device__ __forceinline__ uint32_t smem_u32(const void* p) {
    uint32_t a;
    asm("{ .reg .u64 t; cvta.to.shared.u64 t, %1; cvt.u32.u64 %0, t; }"
        : "=r"(a) : "l"(p));
    return a;
}

#define CP_ASYNC16(dst, src) \
    asm volatile("cp.async.ca.shared.global [%0], [%1], 16;" \
                 :: "r"(dst), "l"(src) : "memory")
#define CP_COMMIT() \
    asm volatile("cp.async.commit_group;" ::: "memory")
#define CP_WAIT2() \
    asm volatile("cp.async.wait_group 2;" ::: "memory")
#define CP_WAIT0() \
    asm volatile("cp.async.wait_group 0;" ::: "memory")

#define MMA_BF16(d, a, b) \
    asm volatile( \
        "mma.sync.aligned.m16n8k16.row.col.f32.bf16.bf16.f32 " \
        "{%0,%1,%2,%3}, {%4,%5,%6,%7}, {%8,%9}, {%0,%1,%2,%3};" \
        : "+f"((d)[0]), "+f"((d)[1]), "+f"((d)[2]), "+f"((d)[3]) \
        : "r"((a)[0]), "r"((a)[1]), "r"((a)[2]), "r"((a)[3]), \
          "r"((b)[0]), "r"((b)[1]))

#define MMA_F16(d, a, b) \
    asm volatile( \
        "mma.sync.aligned.m16n8k16.row.col.f32.f16.f16.f32 " \
        "{%0,%1,%2,%3}, {%4,%5,%6,%7}, {%8,%9}, {%0,%1,%2,%3};" \
        : "+f"((d)[0]), "+f"((d)[1]), "+f"((d)[2]), "+f"((d)[3]) \
        : "r"((a)[0]), "r"((a)[1]), "r"((a)[2]), "r"((a)[3]), \
          "r"((b)[0]), "r"((b)[1]))

// ---------------- weight split kernel (f32 -> fp16 hi/lo) ----------------
__global__ __launch_bounds__(256) void wsplit_kernel(
    const float* __restrict__ src, __half* __restrict__ hi,
    __half* __restrict__ lo, int n4)
{
    int i = blockIdx.x * 256 + threadIdx.x;
    if (i >= n4) return;
    float4 s = ((const float4*)src)[i];
    __half h0, h1, h2, h3, l0, l1, l2, l3;
    hsplit(s.x, h0, l0); hsplit(s.y, h1, l1);
    hsplit(s.z, h2, l2); hsplit(s.w, h3, l3);
    __half2* Hp = (__half2*)hi;
    __half2* Lp = (__half2*)lo;
    Hp[2*i]   = __half2{h0, h1};
    Hp[2*i+1] = __half2{h2, h3};
    Lp[2*i]   = __half2{l0, l1};
    Lp[2*i+1] = __half2{l2, l3};
}

// ---------------- LayerNorm -> fp16 single plane ----------------
__global__ __launch_bounds__(256) void ln_kernel(
    const float* __restrict__ X, const float* __restrict__ g,
    const float* __restrict__ be, __half* __restrict__ Y,
    int remap, int pervw)
{
    int r = blockIdx.x;
    int v = r / (B_ * N_);
    long inrow;
    if (remap) {
        int rem = r % (B_ * N_);
        int bb = rem / N_;
        int n  = rem % N_;
        inrow = ((long)(bb * NVW + v) * N_ + n);
    } else {
        inrow = r;
    }
    const float* x = X + inrow * C_;
    long obase = (long)r * C_;
    const float* gg = g  + (pervw ? v * C_ : 0);
    const float* bb2 = be + (pervw ? v * C_ : 0);

    int t = threadIdx.x;
    float v0 = x[t], v1 = x[t + 256], v2 = x[t + 512];
    float s  = v0 + v1 + v2;
    float sq = v0 * v0 + v1 * v1 + v2 * v2;

    __shared__ float rs[256], rq[256];
    rs[t] = s; rq[t] = sq;
    __syncthreads();
    for (int off = 128; off > 0; off >>= 1) {
        if (t < off) { rs[t] += rs[t + off]; rq[t] += rq[t + off]; }
        __syncthreads();
    }
    float mean = rs[0] * (1.0f / C_);
    float var  = rq[0] * (1.0f / C_) - mean * mean;
    float rstd = rsqrtf(var + 1e-6f);

    #pragma unroll
    for (int rr = 0; rr < 3; rr++) {
        int c = t + rr * 256;
        float val = (rr == 0 ? v0 : (rr == 1 ? v1 : v2));
        float y = (val - mean) * rstd * gg[c] + bb2[c];
        Y[obase + c] = __float2half(y);
    }
}

// ---------------- 2-term FP16 mma.sync batched NT GEMM ----------------
// D = A*Wh + A*Wl. A single fp16 plane, W dual fp16 planes.
// CTA 128x128, 256 threads, 8 warps (2x4), warp tile 64x32, K-chunk 32.
// smem: 3 tiles/stage (A, Wh, Wl), [row][k2] u32 stride 20, 4 stages.
#define KC 32
#define RSU 20
#define TILE_U (128 * RSU)                   // 2560 u32
#define NSTAGE 4
#define GEMM_SMEM (NSTAGE * 3 * TILE_U * 4)  // 122880 bytes

__global__ void __launch_bounds__(256, 1)
gemm_mma(const __half* __restrict__ A,
         const __half* __restrict__ Wh, const __half* __restrict__ Wl,
         const float* __restrict__ bias, const float* __restrict__ res,
         float* __restrict__ Cf,
         __nv_bfloat16* __restrict__ CH, __nv_bfloat16* __restrict__ CL,
         __half* __restrict__ Ch,
         int Kdim, int D,
         long sA, long sW, long sB, long sR, long sC, float alpha, int act)
{
    extern __shared__ uint32_t smu[];
    const int v = blockIdx.z;
    const int bm = blockIdx.y * 128, bn = blockIdx.x * 128;

    const int t = threadIdx.x, lane = t & 31, wid = t >> 5;
    const int wm = (wid >> 2) * 64;
    const int wn = (wid & 3) * 32;
    const int fr = lane >> 2;
    const int fk = lane & 3;

    // cp.async: 6 tasks/thread. lin = s*256+t; tile = lin>>9 (0=A,1=Wh,2=Wl);
    // row = (lin>>2)&127; seg = lin&3 (16B segments of a 64B row chunk)
    const char* gptr[6];
    uint32_t soff[6];
    #pragma unroll
    for (int s = 0; s < 6; s++) {
        int lin = s * 256 + t;
        int tile = lin >> 9;
        int row = (lin >> 2) & 127;
        int seg = lin & 3;
        const __half* base;
        if (tile == 0)      base = A  + (long)v * sA + (long)(bm + row) * Kdim;
        else if (tile == 1) base = Wh + (long)v * sW + (long)(bn + row) * Kdim;
        else                base = Wl + (long)v * sW + (long)(bn + row) * Kdim;
        gptr[s] = (const char*)base + seg * 16;
        soff[s] = (uint32_t)((tile * TILE_U + row * RSU) * 4 + seg * 16);
    }
    const uint32_t sbase = smem_u32(smu);

    float acc[4][4][4];
    #pragma unroll
    for (int a = 0; a < 4; a++)
        #pragma unroll
        for (int b = 0; b < 4; b++)
            #pragma unroll
            for (int c = 0; c < 4; c++) acc[a][b][c] = 0.0f;

    const int steps = Kdim / KC;

    #pragma unroll
    for (int p = 0; p < 3; p++) {
        if (p < steps) {
            uint32_t st = sbase + (uint32_t)((p & 3) * 3 * TILE_U * 4);
            #pragma unroll
            for (int s = 0; s < 6; s++)
                CP_ASYNC16(st + soff[s], gptr[s] + p * 64);
        }
        CP_COMMIT();
    }

    for (int c = 0; c < steps; c++) {
        CP_WAIT2();
        __syncthreads();

        int p = c + 3;
        if (p < steps) {
            uint32_t st = sbase + (uint32_t)((p & 3) * 3 * TILE_U * 4);
            #pragma unroll
            for (int s = 0; s < 6; s++)
                CP_ASYNC16(st + soff[s], gptr[s] + p * 64);
        }
        CP_COMMIT();

        const uint32_t* S   = smu + (c & 3) * 3 * TILE_U;
        const uint32_t* AS  = S;
        const uint32_t* WhS = S + TILE_U;
        const uint32_t* WlS = S + 2 * TILE_U;

        #pragma unroll
        for (int s = 0; s < 2; s++) {
            int ko = s * 8 + fk;
            uint32_t ah[4][4], bh[4][2], bl[4][2];
            #pragma unroll
            for (int mt = 0; mt < 4; mt++) {
                int r0 = wm + mt * 16 + fr;
                ah[mt][0] = AS[(r0    ) * RSU + ko];
                ah[mt][1] = AS[(r0 + 8) * RSU + ko];
                ah[mt][2] = AS[(r0    ) * RSU + ko + 4];
                ah[mt][3] = AS[(r0 + 8) * RSU + ko + 4];
            }
            #pragma unroll
            for (int nt = 0; nt < 4; nt++) {
                int n0 = wn + nt * 8 + fr;
                bh[nt][0] = WhS[n0 * RSU + ko];
                bh[nt][1] = WhS[n0 * RSU + ko + 4];
                bl[nt][0] = WlS[n0 * RSU + ko];
                bl[nt][1] = WlS[n0 * RSU + ko + 4];
            }
            #pragma unroll
            for (int mt = 0; mt < 4; mt++)
                #pragma unroll
                for (int nt = 0; nt < 4; nt++)
                    MMA_F16(acc[mt][nt], ah[mt], bh[nt]);
            #pragma unroll
            for (int mt = 0; mt < 4; mt++)
                #pragma unroll
                for (int nt = 0; nt < 4; nt++)
                    MMA_F16(acc[mt][nt], ah[mt], bl[nt]);
        }
    }

    __syncthreads();

    #pragma unroll
    for (int mt = 0; mt < 4; mt++) {
        #pragma unroll
        for (int nt = 0; nt < 4; nt++) {
            int row = bm + wm + mt * 16 + fr;
            int col = bn + wn + nt * 8 + 2 * fk;
            float b0 = 0.f, b1 = 0.f;
            if (bias) {
                b0 = bias[(long)v * sB + col];
                b1 = bias[(long)v * sB + col + 1];
            }
            #pragma unroll
            for (int half = 0; half < 2; half++) {
                int r = row + half * 8;
                float v0 = alpha * (acc[mt][nt][half * 2 + 0] + b0);
                float v1 = alpha * (acc[mt][nt][half * 2 + 1] + b1);
                if (act == 1) { v0 = gelu_exact(v0); v1 = gelu_exact(v1); }
                if (res) {
                    v0 += res[(long)v * sR + (long)r * D + col];
                    v1 += res[(long)v * sR + (long)r * D + col + 1];
                }
                long off = (long)v * sC + (long)r * D + col;
                if (Cf) {
                    float2 o2 = {v0, v1};
                    *(float2*)&Cf[off] = o2;
                } else if (CH) {
                    __nv_bfloat16 h0, h1, l0, l1;
                    bfsplit(v0, h0, l0);
                    bfsplit(v1, h1, l1);
                    *(__nv_bfloat162*)&CH[off] = __nv_bfloat162{h0, h1};
                    *(__nv_bfloat162*)&CL[off] = __nv_bfloat162{l0, l1};
                } else {
                    *(__half2*)&Ch[off] = __floats2half2_rn(v0, v1);
                }
            }
        }
    }
}

// ---------------- MMA flash attention (3-term bf16), mean over j ----------
#define ATTN_SMEM (32256 * 4)

__global__ void __launch_bounds__(256, 1)
attn_mma(const __nv_bfloat16* __restrict__ qkvH,
         const __nv_bfloat16* __restrict__ qkvL,
         __half* __restrict__ ctxF)
{
    const int h = blockIdx.x, b = blockIdx.y, iv = blockIdx.z;
    const int t = threadIdx.x, lane = t & 31, wid = t >> 5;
    const int fr = lane >> 2, fk = lane & 3;
    const int wm = wid * 32;
    const int D3 = 3 * C_;

    extern __shared__ uint32_t sa[];
    uint32_t* Qs[2] = { sa,          sa + 9216 };
    uint32_t* Ks[2] = { sa + 18432,  sa + 20736 };
    uint32_t* VT[2] = { sa + 23040,  sa + 25344 };
    uint32_t* VR[2] = { sa + 27648,  sa + 29952 };
    const uint32_t sb = smem_u32(sa);

    const long rowQ = (long)(iv * B_ + b) * N_;

    #pragma unroll
    for (int p = 0; p < 2; p++) {
        const __nv_bfloat16* src = (p ? qkvL : qkvH) + rowQ * D3 + h * HD_;
        uint32_t dstb = sb + (uint32_t)(p ? 9216 * 4 : 0);
        #pragma unroll
        for (int i = 0; i < 8; i++) {
            int lin = i * 256 + t;
            int row = lin >> 3, seg = lin & 7;
            CP_ASYNC16(dstb + row * 144 + seg * 16,
                       (const char*)(src + (long)row * D3) + seg * 16);
        }
    }
    CP_COMMIT();

    float outacc[2][8][4];
    #pragma unroll
    for (int a = 0; a < 2; a++)
        #pragma unroll
        for (int n = 0; n < 8; n++)
            #pragma unroll
            for (int q = 0; q < 4; q++) outacc[a][n][q] = 0.f;

    for (int j = 0; j < NVW; j++) {
        const long rowK = (long)(j * B_ + b) * N_;
        float m_[2][2] = {{-1e30f, -1e30f}, {-1e30f, -1e30f}};
        float l_[2][2] = {{0.f, 0.f}, {0.f, 0.f}};
        float cacc[2][8][4];
        #pragma unroll
        for (int a = 0; a < 2; a++)
            #pragma unroll
            for (int n = 0; n < 8; n++)
                #pragma unroll
                for (int q = 0; q < 4; q++) cacc[a][n][q] = 0.f;

        for (int kc = 0; kc < 4; kc++) {
            __syncthreads();
            #pragma unroll
            for (int p = 0; p < 2; p++) {
                const __nv_bfloat16* gk = (p ? qkvL : qkvH)
                    + (rowK + kc * 64) * D3 + C_ + h * HD_;
                const __nv_bfloat16* gv = (p ? qkvL : qkvH)
                    + (rowK + kc * 64) * D3 + 2 * C_ + h * HD_;
                uint32_t kb = sb + (uint32_t)((18432 + p * 2304) * 4);
                uint32_t vb = sb + (uint32_t)((27648 + p * 2304) * 4);
                #pragma unroll
                for (int i = 0; i < 2; i++) {
                    int lin = i * 256 + t;
                    int row = lin >> 3, seg = lin & 7;
                    CP_ASYNC16(kb + row * 144 + seg * 16,
                               (const char*)(gk + (long)row * D3) + seg * 16);
                    CP_ASYNC16(vb + row * 144 + seg * 16,
                               (const char*)(gv + (long)row * D3) + seg * 16);
                }
            }
            CP_COMMIT();
            CP_WAIT0();
            __syncthreads();

            #pragma unroll
            for (int p = 0; p < 2; p++) {
                const uint32_t* R = VR[p];
                uint32_t* T = VT[p];
                #pragma unroll
                for (int i = 0; i < 4; i++) {
                    int lin = i * 256 + t;
                    int kp = lin >> 5, cp = lin & 31;
                    uint32_t r0 = R[(2 * kp) * 36 + cp];
                    uint32_t r1 = R[(2 * kp + 1) * 36 + cp];
                    T[(2 * cp) * 36 + kp]     = (r0 & 0xffffu) | (r1 << 16);
                    T[(2 * cp + 1) * 36 + kp] = (r0 >> 16) | (r1 & 0xffff0000u);
                }
            }
            __syncthreads();

            float sacc[2][8][4];
            #pragma unroll
            for (int a = 0; a < 2; a++)
                #pragma unroll
                for (int n = 0; n < 8; n++)
                    #pragma unroll
                    for (int q = 0; q < 4; q++) sacc[a][n][q] = 0.f;

            #pragma unroll
            for (int kt = 0; kt < 4; kt++) {
                uint32_t qh_[2][4], ql_[2][4];
                #pragma unroll
                for (int mt = 0; mt < 2; mt++) {
                    int r0 = wm + mt * 16 + fr;
                    int i0 = r0 * 36 + kt * 8 + fk;
                    int i1 = (r0 + 8) * 36 + kt * 8 + fk;
                    qh_[mt][0] = Qs[0][i0];
                    qh_[mt][1] = Qs[0][i1];
                    qh_[mt][2] = Qs[0][i0 + 4];
                    qh_[mt][3] = Qs[0][i1 + 4];
                    ql_[mt][0] = Qs[1][i0];
                    ql_[mt][1] = Qs[1][i1];
                    ql_[mt][2] = Qs[1][i0 + 4];
                    ql_[mt][3] = Qs[1][i1 + 4];
                }
                #pragma unroll
                for (int nt = 0; nt < 8; nt++) {
                    int ib = (nt * 8 + fr) * 36 + kt * 8 + fk;
                    uint32_t kh_[2] = { Ks[0][ib], Ks[0][ib + 4] };
                    uint32_t kl_[2] = { Ks[1][ib], Ks[1][ib + 4] };
                    #pragma unroll
                    for (int mt = 0; mt < 2; mt++) {
                        MMA_BF16(sacc[mt][nt], qh_[mt], kh_);
                        MMA_BF16(sacc[mt][nt], qh_[mt], kl_);
                        MMA_BF16(sacc[mt][nt], ql_[mt], kh_);
                    }
                }
            }
            #pragma unroll
            for (int a = 0; a < 2; a++)
                #pragma unroll
                for (int n = 0; n < 8; n++)
                    #pragma unroll
                    for (int q = 0; q < 4; q++) sacc[a][n][q] *= 0.125f;

            #pragma unroll
            for (int mt = 0; mt < 2; mt++) {
                #pragma unroll
                for (int hf = 0; hf < 2; hf++) {
                    float cm = -1e30f;
                    #pragma unroll
                    for (int nt = 0; nt < 8; nt++)
                        cm = fmaxf(cm, fmaxf(sacc[mt][nt][hf*2], sacc[mt][nt][hf*2+1]));
                    cm = fmaxf(cm, __shfl_xor_sync(0xffffffffu, cm, 1));
                    cm = fmaxf(cm, __shfl_xor_sync(0xffffffffu, cm, 2));
                    float mo = m_[mt][hf];
                    float mn = fmaxf(mo, cm);
                    float corr = __expf(mo - mn);
                    m_[mt][hf] = mn;
                    float ps = 0.f;
                    #pragma unroll
                    for (int nt = 0; nt < 8; nt++) {
                        float p0 = __expf(sacc[mt][nt][hf*2]   - mn);
                        float p1 = __expf(sacc[mt][nt][hf*2+1] - mn);
                        sacc[mt][nt][hf*2]   = p0;
                        sacc[mt][nt][hf*2+1] = p1;
                        ps += p0 + p1;
                    }
                    ps += __shfl_xor_sync(0xffffffffu, ps, 1);
                    ps += __shfl_xor_sync(0xffffffffu, ps, 2);
                    l_[mt][hf] = l_[mt][hf] * corr + ps;
                    #pragma unroll
                    for (int nt = 0; nt < 8; nt++) {
                        cacc[mt][nt][hf*2]   *= corr;
                        cacc[mt][nt][hf*2+1] *= corr;
                    }
                }
            }

            #pragma unroll
            for (int ktk = 0; ktk < 4; ktk++) {
                uint32_t ph_[2][4], pl_[2][4];
                #pragma unroll
                for (int mt = 0; mt < 2; mt++) {
                    #pragma unroll
                    for (int q = 0; q < 4; q++) {
                        int nt = 2 * ktk + (q >> 1);
                        int base = (q & 1) * 2;
                        float p0 = sacc[mt][nt][base];
                        float p1 = sacc[mt][nt][base + 1];
                        __nv_bfloat16 h0 = __float2bfloat16(p0);
                        __nv_bfloat16 h1 = __float2bfloat16(p1);
                        float r0 = p0 - __bfloat162float(h0);
                        float r1 = p1 - __bfloat162float(h1);
                        uint16_t u0 = *(uint16_t*)&h0, u1 = *(uint16_t*)&h1;
                        ph_[mt][q] = ((uint32_t)u1 << 16) | u0;
                        pl_[mt][q] = bfpack(r0, r1);
                    }
                }
                #pragma unroll
                for (int nc = 0; nc < 8; nc++) {
                    int ib = (nc * 8 + fr) * 36 + ktk * 8 + fk;
                    uint32_t vh_[2] = { VT[0][ib], VT[0][ib + 4] };
                    uint32_t vl_[2] = { VT[1][ib], VT[1][ib + 4] };
                    #pragma unroll
                    for (int mt = 0; mt < 2; mt++) {
                        MMA_BF16(cacc[mt][nc], ph_[mt], vh_);
                        MMA_BF16(cacc[mt][nc], ph_[mt], vl_);
                        MMA_BF16(cacc[mt][nc], pl_[mt], vh_);
                    }
                }
            }
        } // kc

        #pragma unroll
        for (int mt = 0; mt < 2; mt++)
            #pragma unroll
            for (int hf = 0; hf < 2; hf++) {
                float inv = 0.25f / l_[mt][hf];
                #pragma unroll
                for (int nt = 0; nt < 8; nt++) {
                    outacc[mt][nt][hf*2]   += cacc[mt][nt][hf*2]   * inv;
                    outacc[mt][nt][hf*2+1] += cacc[mt][nt][hf*2+1] * inv;
                }
            }
    } // j

    // write ctx as single fp16 plane
    #pragma unroll
    for (int mt = 0; mt < 2; mt++) {
        #pragma unroll
        for (int hf = 0; hf < 2; hf++) {
            int row = wm + mt * 16 + fr + hf * 8;
            long obase = (rowQ + row) * C_ + h * HD_;
            #pragma unroll
            for (int nt = 0; nt < 8; nt++) {
                int col = nt * 8 + 2 * fk;
                *(__half2*)&ctxF[obase + col] =
                    __floats2half2_rn(outacc[mt][nt][hf*2], outacc[mt][nt][hf*2+1]);
            }
        }
    }
}

// ---------------- learnable-query projection ----------------
__global__ __launch_bounds__(256) void qh_kernel(
    const float* __restrict__ query, const float* __restrict__ w,
    const float* __restrict__ bq, float* __restrict__ qh)
{
    int v = blockIdx.x;
    int t = threadIdx.x;
    for (int d = t; d < C_; d += 256) {
        const float* wr = w + (long)v * (3 * C_) * C_ + (long)d * C_;
        float acc = 0.0f;
        #pragma unroll 4
        for (int c = 0; c < C_; c++) acc += query[c] * wr[c];
        qh[v * C_ + d] = acc + bq[(long)v * (3 * C_) + d];
    }
}

// ---------------- cross attention (single query) ----------------
__global__ __launch_bounds__(256) void cross_attn_kernel(
    const float* __restrict__ kv, const float* __restrict__ qh,
    float* __restrict__ c2)
{
    int h = blockIdx.x, b = blockIdx.y, v = blockIdx.z;
    int t = threadIdx.x;

    __shared__ float p[256];
    __shared__ float red[256];
    __shared__ float part[4][64];

    const float* kvb = kv + ((long)(v * B_ + b) * N_) * (2 * C_);
    const float* qhp = qh + v * C_ + h * HD_;
    const float* krow = kvb + (long)t * (2 * C_) + h * HD_;

    float s = 0.0f;
    #pragma unroll
    for (int e = 0; e < 64; e++) s += qhp[e] * krow[e];
    s *= 0.125f;

    red[t] = s; __syncthreads();
    for (int off = 128; off > 0; off >>= 1) {
        if (t < off) red[t] = fmaxf(red[t], red[t + off]);
        __syncthreads();
    }
    float mx = red[0];
    __syncthreads();

    float e_ = __expf(s - mx);
    p[t] = e_; red[t] = e_;
    __syncthreads();
    for (int off = 128; off > 0; off >>= 1) {
        if (t < off) red[t] += red[t + off];
        __syncthreads();
    }
    float inv = 1.0f / red[0];
    __syncthreads();

    int e = t & 63, pid = t >> 6;
    float acc = 0.0f;
    for (int n = pid * 64; n < pid * 64 + 64; n++)
        acc += p[n] * kvb[(long)n * (2 * C_) + C_ + h * HD_ + e];
    part[pid][e] = acc;
    __syncthreads();
    if (t < 64) {
        float r = (part[0][t] + part[1][t]) + (part[2][t] + part[3][t]);
        c2[(long)(v * B_ + b) * C_ + h * HD_ + t] = r * inv;
    }
}

// ---------------- output projection + broadcast over N ----------------
__global__ __launch_bounds__(256) void out_kernel(
    const float* __restrict__ c2, const float* __restrict__ w,
    const float* __restrict__ bias, float* __restrict__ out)
{
    int v = blockIdx.x, b = blockIdx.y;
    int t = threadIdx.x;

    __shared__ float sc[C_];
    for (int c = t; c < C_; c += 256) sc[c] = c2[(long)(v * B_ + b) * C_ + c];
    __syncthreads();

    float o[3];
    #pragma unroll
    for (int r = 0; r < 3; r++) {
        int co = t + r * 256;
        const float* wr = w + (long)v * C_ * C_ + (long)co * C_;
        float d0 = 0.f, d1 = 0.f, d2 = 0.f, d3 = 0.f;
        #pragma unroll 4
        for (int c = 0; c < C_; c += 4) {
            d0 += sc[c + 0] * wr[c + 0];
            d1 += sc[c + 1] * wr[c + 1];
            d2 += sc[c + 2] * wr[c + 2];
            d3 += sc[c + 3] * wr[c + 3];
        }
        o[r] = ((d0 + d1) + (d2 + d3)) + bias[v * C_ + co];
    }
    for (int n = 0; n < N_; n++) {
        long base = ((long)b * N_ + n) * (NVW * C_) + (long)v * C_;
        #pragma unroll
        for (int r = 0; r < 3; r++) out[base + t + r * 256] = o[r];
    }
}

// ---------------- launch ----------------
extern "C" void kernel_launch(void* const* d_in, const int* in_sizes, int n_in,
                              void* d_out, int out_size)
{
    const float* X        = (const float*)d_in[0];
    const float* norm1_g  = (const float*)d_in[1];
    const float* norm1_b  = (const float*)d_in[2];
    const float* qkv_w    = (const float*)d_in[3];
    const float* proj_w   = (const float*)d_in[4];
    const float* proj_b   = (const float*)d_in[5];
    const float* norm2_g  = (const float*)d_in[6];
    const float* norm2_b  = (const float*)d_in[7];
    const float* fc1_w    = (const float*)d_in[8];
    const float* fc1_b    = (const float*)d_in[9];
    const float* fc2_w    = (const float*)d_in[10];
    const float* fc2_b    = (const float*)d_in[11];
    const float* query    = (const float*)d_in[12];
    const float* mha_in_w = (const float*)d_in[13];
    const float* mha_in_b = (const float*)d_in[14];
    const float* mha_out_w= (const float*)d_in[15];
    const float* mha_out_b= (const float*)d_in[16];
    float* out = (float*)d_out;

    float *x, *kv, *qh, *c2;
    __nv_bfloat16 *qkvH, *qkvL;
    __half *XnF, *ctxF, *hnF, *h1F, *x2F;
    __half *WqkvH, *WqkvL, *WprjH, *WprjL, *Wf1H, *Wf1L, *Wf2H, *Wf2L, *WmhaH, *WmhaL;
    cudaGetSymbolAddress((void**)&x,    g_x);
    cudaGetSymbolAddress((void**)&kv,   g_kv);
    cudaGetSymbolAddress((void**)&qh,   g_qh);
    cudaGetSymbolAddress((void**)&c2,   g_c2);
    cudaGetSymbolAddress((void**)&qkvH, g_qkvH); cudaGetSymbolAddress((void**)&qkvL, g_qkvL);
    cudaGetSymbolAddress((void**)&XnF,  g_XnF);
    cudaGetSymbolAddress((void**)&ctxF, g_ctxF);
    cudaGetSymbolAddress((void**)&hnF,  g_hnF);
    cudaGetSymbolAddress((void**)&h1F,  g_h1F);
    cudaGetSymbolAddress((void**)&x2F,  g_x2F);
    cudaGetSymbolAddress((void**)&WqkvH, g_WqkvH); cudaGetSymbolAddress((void**)&WqkvL, g_WqkvL);
    cudaGetSymbolAddress((void**)&WprjH, g_WprjH); cudaGetSymbolAddress((void**)&WprjL, g_WprjL);
    cudaGetSymbolAddress((void**)&Wf1H,  g_Wf1H);  cudaGetSymbolAddress((void**)&Wf1L,  g_Wf1L);
    cudaGetSymbolAddress((void**)&Wf2H,  g_Wf2H);  cudaGetSymbolAddress((void**)&Wf2L,  g_Wf2L);
    cudaGetSymbolAddress((void**)&WmhaH, g_WmhaH); cudaGetSymbolAddress((void**)&WmhaL, g_WmhaL);

    cudaFuncSetAttribute(gemm_mma, cudaFuncAttributeMaxDynamicSharedMemorySize,
                         GEMM_SMEM);
    cudaFuncSetAttribute(attn_mma, cudaFuncAttributeMaxDynamicSharedMemorySize,
                         ATTN_SMEM);

    const long MC  = (long)MROWS * C_;
    const long MH  = (long)MROWS * HID_;

    auto wsplit = [&](const float* src, __half* hi, __half* lo, long n) {
        int n4 = (int)(n / 4);
        wsplit_kernel<<<(n4 + 255) / 256, 256>>>(src, hi, lo, n4);
    };

    // 0. split all weights into fp16 hi/lo planes
    wsplit(qkv_w,    WqkvH, WqkvL, (long)NVW * 3 * C_ * C_);
    wsplit(proj_w,   WprjH, WprjL, (long)NVW * C_ * C_);
    wsplit(fc1_w,    Wf1H,  Wf1L,  (long)NVW * HID_ * C_);
    wsplit(fc2_w,    Wf2H,  Wf2L,  (long)NVW * C_ * HID_);
    wsplit(mha_in_w, WmhaH, WmhaL, (long)NVW * 3 * C_ * C_);

    // 1. LN1 -> Xn fp16 (remap [b*NV+v] -> [v][b])
    ln_kernel<<<NVW * B_ * N_, 256>>>(X, norm1_g, norm1_b, XnF, 1, 0);

    // 2. QKV GEMM -> bf16 hi/lo qkv planes (for 3-term attention)
    gemm_mma<<<dim3(3 * C_ / 128, MROWS / 128, NVW), 256, GEMM_SMEM>>>(
        XnF, WqkvH, WqkvL, nullptr, nullptr, nullptr, qkvH, qkvL, nullptr,
        C_, 3 * C_, MC, (long)3 * C_ * C_, 0, 0, (long)MROWS * 3 * C_, 1.0f, 0);

    // 3. MMA flash attention, mean over j -> ctx fp16
    attn_mma<<<dim3(H_, B_, NVW), 256, ATTN_SMEM>>>(qkvH, qkvL, ctxF);

    // 4. proj GEMM (alpha=2 folds residual doubling) -> f32 x
    gemm_mma<<<dim3(C_ / 128, MROWS / 128, NVW), 256, GEMM_SMEM>>>(
        ctxF, WprjH, WprjL, proj_b, nullptr, x, nullptr, nullptr, nullptr,
        C_, C_, MC, (long)C_ * C_, C_, 0, MC, 2.0f, 0);

    // 5. LN2 -> hn fp16
    ln_kernel<<<NVW * B_ * N_, 256>>>(x, norm2_g, norm2_b, hnF, 0, 1);

    // 6. fc1 GEMM + bias + GELU -> h1 fp16
    gemm_mma<<<dim3(HID_ / 128, MROWS / 128, NVW), 256, GEMM_SMEM>>>(
        hnF, Wf1H, Wf1L, fc1_b, nullptr, nullptr, nullptr, nullptr, h1F,
        C_, HID_, MC, (long)HID_ * C_, HID_, 0, MH, 1.0f, 1);

    // 7. fc2 GEMM + bias + residual(x) -> x2 fp16
    gemm_mma<<<dim3(C_ / 128, MROWS / 128, NVW), 256, GEMM_SMEM>>>(
        h1F, Wf2H, Wf2L, fc2_b, x, nullptr, nullptr, nullptr, x2F,
        HID_, C_, MH, (long)C_ * HID_, C_, MC, MC, 1.0f, 0);

    // 8. learnable query projection (f32 weights)
    qh_kernel<<<NVW, 256>>>(query, mha_in_w, mha_in_b, qh);

    // 9. K/V projection of x2 -> f32 kv (W rows [C,3C) of mha_in_w)
    gemm_mma<<<dim3(2 * C_ / 128, MROWS / 128, NVW), 256, GEMM_SMEM>>>(
        x2F, WmhaH + (long)C_ * C_, WmhaL + (long)C_ * C_,
        mha_in_b + C_, nullptr, kv, nullptr, nullptr, nullptr,
        C_, 2 * C_, MC, (long)3 * C_ * C_, (long)3 * C_, 0,
        (long)MROWS * 2 * C_, 1.0f, 0);

    // 10. single-query cross attention -> c2[v][b][C]
    cross_attn_kernel<<<dim3(H_, B_, NVW), 256>>>(kv, qh, c2);

    // 11. output projection + broadcast over N
    out_kernel<<<dim3(NVW, B_), 256>>>(c2, mha_out_w, mha_out_b, out);
}

// round 14
// speedup vs baseline: 3.6736x; 1.0457x over previous
#include <cuda_runtime.h>
#include <cuda_bf16.h>
#include <cuda_fp16.h>
#include <math.h>
#include <stdint.h>

#define NVW 4
#define B_ 4
#define N_ 256
#define C_ 768
#define H_ 12
#define HD_ 64
#define HID_ 3072
#define MROWS (B_*N_)   // 1024 rows per view

// ---------------- scratch (device globals; no allocation) ----------------
__device__ float g_x  [NVW*MROWS*C_];
__device__ float g_kv [NVW*MROWS*2*C_];
__device__ float g_qh [NVW*C_];
__device__ float g_c2 [NVW*B_*C_];
// bf16 hi/lo qkv planes (consumed by 3-term attention)
__device__ __nv_bfloat16 g_qkvH[NVW*MROWS*3*C_], g_qkvL[NVW*MROWS*3*C_];
// fp16 single-plane activations
__device__ __half g_XnF [NVW*MROWS*C_];
__device__ __half g_ctxF[NVW*MROWS*C_];
__device__ __half g_hnF [NVW*MROWS*C_];
__device__ __half g_h1F [NVW*MROWS*HID_];
__device__ __half g_x2F [NVW*MROWS*C_];
// fp16 hi/lo weight planes
__device__ __half g_WqkvH[NVW*3*C_*C_], g_WqkvL[NVW*3*C_*C_];
__device__ __half g_WprjH[NVW*C_*C_],   g_WprjL[NVW*C_*C_];
__device__ __half g_Wf1H [NVW*HID_*C_], g_Wf1L [NVW*HID_*C_];
__device__ __half g_Wf2H [NVW*C_*HID_], g_Wf2L [NVW*C_*HID_];
__device__ __half g_WmhaH[NVW*3*C_*C_], g_WmhaL[NVW*3*C_*C_];

__device__ __forceinline__ float gelu_exact(float x) {
    return 0.5f * x * (1.0f + erff(x * 0.70710678118654752f));
}

__device__ __forceinline__ void bfsplit(float x, __nv_bfloat16& h, __nv_bfloat16& l) {
    h = __float2bfloat16(x);
    l = __float2bfloat16(x - __bfloat162float(h));
}

__device__ __forceinline__ void hsplit(float x, __half& h, __half& l) {
    h = __float2half(x);
    l = __float2half(x - __half2float(h));
}

__device__ __forceinline__ uint32_t bfpack(float a, float b) {
    __nv_bfloat16 ha = __float2bfloat16(a);
    __nv_bfloat16 hb = __float2bfloat16(b);
    uint16_t ua = *(uint16_t*)&ha, ub = *(uint16_t*)&hb;
    return ((uint32_t)ub << 16) | ua;
}

__device__ __forceinline__ uint32_t smem_u32(const void* p) {
    uint32_t a;
    asm("{ .reg .u64 t; cvta.to.shared.u64 t, %1; cvt.u32.u64 %0, t; }"
        : "=r"(a) : "l"(p));
    return a;
}

#define CP_ASYNC16(dst, src) \
    asm volatile("cp.async.ca.shared.global [%0], [%1], 16;" \
                 :: "r"(dst), "l"(src) : "memory")
#define CP_COMMIT() \
    asm volatile("cp.async.commit_group;" ::: "memory")
#define CP_WAIT1() \
    asm volatile("cp.async.wait_group 1;" ::: "memory")
#define CP_WAIT0() \
    asm volatile("cp.async.wait_group 0;" ::: "memory")

#define MMA_BF16(d, a, b) \
    asm volatile( \
        "mma.sync.aligned.m16n8k16.row.col.f32.bf16.bf16.f32 " \
        "{%0,%1,%2,%3}, {%4,%5,%6,%7}, {%8,%9}, {%0,%1,%2,%3};" \
        : "+f"((d)[0]), "+f"((d)[1]), "+f"((d)[2]), "+f"((d)[3]) \
        : "r"((a)[0]), "r"((a)[1]), "r"((a)[2]), "r"((a)[3]), \
          "r"((b)[0]), "r"((b)[1]))

#define MMA_F16(d, a, b) \
    asm volatile( \
        "mma.sync.aligned.m16n8k16.row.col.f32.f16.f16.f32 " \
        "{%0,%1,%2,%3}, {%4,%5,%6,%7}, {%8,%9}, {%0,%1,%2,%3};" \
        : "+f"((d)[0]), "+f"((d)[1]), "+f"((d)[2]), "+f"((d)[3]) \
        : "r"((a)[0]), "r"((a)[1]), "r"((a)[2]), "r"((a)[3]), \
          "r"((b)[0]), "r"((b)[1]))

// ---------------- weight split kernel (f32 -> fp16 hi/lo) ----------------
__global__ __launch_bounds__(256) void wsplit_kernel(
    const float* __restrict__ src, __half* __restrict__ hi,
    __half* __restrict__ lo, int n4)
{
    int i = blockIdx.x * 256 + threadIdx.x;
    if (i >= n4) return;
    float4 s = ((const float4*)src)[i];
    __half h0, h1, h2, h3, l0, l1, l2, l3;
    hsplit(s.x, h0, l0); hsplit(s.y, h1, l1);
    hsplit(s.z, h2, l2); hsplit(s.w, h3, l3);
    __half2* Hp = (__half2*)hi;
    __half2* Lp = (__half2*)lo;
    Hp[2*i]   = __half2{h0, h1};
    Hp[2*i+1] = __half2{h2, h3};
    Lp[2*i]   = __half2{l0, l1};
    Lp[2*i+1] = __half2{l2, l3};
}

// ---------------- LayerNorm -> fp16 single plane ----------------
__global__ __launch_bounds__(256) void ln_kernel(
    const float* __restrict__ X, const float* __restrict__ g,
    const float* __restrict__ be, __half* __restrict__ Y,
    int remap, int pervw)
{
    int r = blockIdx.x;
    int v = r / (B_ * N_);
    long inrow;
    if (remap) {
        int rem = r % (B_ * N_);
        int bb = rem / N_;
        int n  = rem % N_;
        inrow = ((long)(bb * NVW + v) * N_ + n);
    } else {
        inrow = r;
    }
    const float* x = X + inrow * C_;
    long obase = (long)r * C_;
    const float* gg = g  + (pervw ? v * C_ : 0);
    const float* bb2 = be + (pervw ? v * C_ : 0);

    int t = threadIdx.x;
    float v0 = x[t], v1 = x[t + 256], v2 = x[t + 512];
    float s  = v0 + v1 + v2;
    float sq = v0 * v0 + v1 * v1 + v2 * v2;

    __shared__ float rs[256], rq[256];
    rs[t] = s; rq[t] = sq;
    __syncthreads();
    for (int off = 128; off > 0; off >>= 1) {
        if (t < off) { rs[t] += rs[t + off]; rq[t] += rq[t + off]; }
        __syncthreads();
    }
    float mean = rs[0] * (1.0f / C_);
    float var  = rq[0] * (1.0f / C_) - mean * mean;
    float rstd = rsqrtf(var + 1e-6f);

    #pragma unroll
    for (int rr = 0; rr < 3; rr++) {
        int c = t + rr * 256;
        float val = (rr == 0 ? v0 : (rr == 1 ? v1 : v2));
        float y = (val - mean) * rstd * gg[c] + bb2[c];
        Y[obase + c] = __float2half(y);
    }
}

// ---------------- 2-term FP16 mma.sync batched NT GEMM ----------------
// D = A*Wh + A*Wl. A single fp16 plane, W dual fp16 planes.
// CTA 128x128, 256 threads, 8 warps (2x4), warp tile 64x32, K-chunk 32.
// 3-stage cp.async pipeline; 2 CTAs per SM for cross-CTA latency hiding.
#define KC 32
#define RSU 20
#define TILE_U (128 * RSU)                   // 2560 u32
#define NSTAGE 3
#define GEMM_SMEM (NSTAGE * 3 * TILE_U * 4)  // 92160 bytes

__global__ void __launch_bounds__(256, 2)
gemm_mma(const __half* __restrict__ A,
         const __half* __restrict__ Wh, const __half* __restrict__ Wl,
         const float* __restrict__ bias, const float* __restrict__ res,
         float* __restrict__ Cf,
         __nv_bfloat16* __restrict__ CH, __nv_bfloat16* __restrict__ CL,
         __half* __restrict__ Ch,
         int Kdim, int D,
         long sA, long sW, long sB, long sR, long sC, float alpha, int act)
{
    extern __shared__ uint32_t smu[];
    const int v = blockIdx.z;
    const int bm = blockIdx.y * 128, bn = blockIdx.x * 128;

    const int t = threadIdx.x, lane = t & 31, wid = t >> 5;
    const int wm = (wid >> 2) * 64;
    const int wn = (wid & 3) * 32;
    const int fr = lane >> 2;
    const int fk = lane & 3;

    // cp.async: 6 tasks/thread. lin = s*256+t; tile = lin>>9 (0=A,1=Wh,2=Wl);
    // row = (lin>>2)&127; seg = lin&3
    const char* gptr[6];
    uint32_t soff[6];
    #pragma unroll
    for (int s = 0; s < 6; s++) {
        int lin = s * 256 + t;
        int tile = lin >> 9;
        int row = (lin >> 2) & 127;
        int seg = lin & 3;
        const __half* base;
        if (tile == 0)      base = A  + (long)v * sA + (long)(bm + row) * Kdim;
        else if (tile == 1) base = Wh + (long)v * sW + (long)(bn + row) * Kdim;
        else                base = Wl + (long)v * sW + (long)(bn + row) * Kdim;
        gptr[s] = (const char*)base + seg * 16;
        soff[s] = (uint32_t)((tile * TILE_U + row * RSU) * 4 + seg * 16);
    }
    const uint32_t sbase = smem_u32(smu);

    float acc[4][4][4];
    #pragma unroll
    for (int a = 0; a < 4; a++)
        #pragma unroll
        for (int b = 0; b < 4; b++)
            #pragma unroll
            for (int c = 0; c < 4; c++) acc[a][b][c] = 0.0f;

    const int steps = Kdim / KC;

    // prologue: chunks 0,1
    #pragma unroll
    for (int p = 0; p < 2; p++) {
        if (p < steps) {
            uint32_t st = sbase + (uint32_t)((p % NSTAGE) * 3 * TILE_U * 4);
            #pragma unroll
            for (int s = 0; s < 6; s++)
                CP_ASYNC16(st + soff[s], gptr[s] + p * 64);
        }
        CP_COMMIT();
    }

    for (int c = 0; c < steps; c++) {
        CP_WAIT1();
        __syncthreads();

        int p = c + 2;
        if (p < steps) {
            uint32_t st = sbase + (uint32_t)((p % NSTAGE) * 3 * TILE_U * 4);
            #pragma unroll
            for (int s = 0; s < 6; s++)
                CP_ASYNC16(st + soff[s], gptr[s] + p * 64);
        }
        CP_COMMIT();

        const uint32_t* S   = smu + (c % NSTAGE) * 3 * TILE_U;
        const uint32_t* AS  = S;
        const uint32_t* WhS = S + TILE_U;
        const uint32_t* WlS = S + 2 * TILE_U;

        #pragma unroll
        for (int s = 0; s < 2; s++) {
            int ko = s * 8 + fk;
            uint32_t ah[4][4], bh[4][2], bl[4][2];
            #pragma unroll
            for (int mt = 0; mt < 4; mt++) {
                int r0 = wm + mt * 16 + fr;
                ah[mt][0] = AS[(r0    ) * RSU + ko];
                ah[mt][1] = AS[(r0 + 8) * RSU + ko];
                ah[mt][2] = AS[(r0    ) * RSU + ko + 4];
                ah[mt][3] = AS[(r0 + 8) * RSU + ko + 4];
            }
            #pragma unroll
            for (int nt = 0; nt < 4; nt++) {
                int n0 = wn + nt * 8 + fr;
                bh[nt][0] = WhS[n0 * RSU + ko];
                bh[nt][1] = WhS[n0 * RSU + ko + 4];
                bl[nt][0] = WlS[n0 * RSU + ko];
                bl[nt][1] = WlS[n0 * RSU + ko + 4];
            }
            #pragma unroll
            for (int mt = 0; mt < 4; mt++)
                #pragma unroll
                for (int nt = 0; nt < 4; nt++)
                    MMA_F16(acc[mt][nt], ah[mt], bh[nt]);
            #pragma unroll
            for (int mt = 0; mt < 4; mt++)
                #pragma unroll
                for (int nt = 0; nt < 4; nt++)
                    MMA_F16(acc[mt][nt], ah[mt], bl[nt]);
        }
    }

    __syncthreads();

    #pragma unroll
    for (int mt = 0; mt < 4; mt++) {
        #pragma unroll
        for (int nt = 0; nt < 4; nt++) {
            int row = bm + wm + mt * 16 + fr;
            int col = bn + wn + nt * 8 + 2 * fk;
            float b0 = 0.f, b1 = 0.f;
            if (bias) {
                b0 = bias[(long)v * sB + col];
                b1 = bias[(long)v * sB + col + 1];
            }
            #pragma unroll
            for (int half = 0; half < 2; half++) {
                int r = row + half * 8;
                float v0 = alpha * (acc[mt][nt][half * 2 + 0] + b0);
                float v1 = alpha * (acc[mt][nt][half * 2 + 1] + b1);
                if (act == 1) { v0 = gelu_exact(v0); v1 = gelu_exact(v1); }
                if (res) {
                    v0 += res[(long)v * sR + (long)r * D + col];
                    v1 += res[(long)v * sR + (long)r * D + col + 1];
                }
                long off = (long)v * sC + (long)r * D + col;
                if (Cf) {
                    float2 o2 = {v0, v1};
                    *(float2*)&Cf[off] = o2;
                } else if (CH) {
                    __nv_bfloat16 h0, h1, l0, l1;
                    bfsplit(v0, h0, l0);
                    bfsplit(v1, h1, l1);
                    *(__nv_bfloat162*)&CH[off] = __nv_bfloat162{h0, h1};
                    *(__nv_bfloat162*)&CL[off] = __nv_bfloat162{l0, l1};
                } else {
                    *(__half2*)&Ch[off] = __floats2half2_rn(v0, v1);
                }
            }
        }
    }
}

// ---------------- MMA flash attention (3-term bf16), mean over j ----------
#define ATTN_SMEM (32256 * 4)

__global__ void __launch_bounds__(256, 1)
attn_mma(const __nv_bfloat16* __restrict__ qkvH,
         const __nv_bfloat16* __restrict__ qkvL,
         __half* __restrict__ ctxF)
{
    const int h = blockIdx.x, b = blockIdx.y, iv = blockIdx.z;
    const int t = threadIdx.x, lane = t & 31, wid = t >> 5;
    const int fr = lane >> 2, fk = lane & 3;
    const int wm = wid * 32;
    const int D3 = 3 * C_;

    extern __shared__ uint32_t sa[];
    uint32_t* Qs[2] = { sa,          sa + 9216 };
    uint32_t* Ks[2] = { sa + 18432,  sa + 20736 };
    uint32_t* VT[2] = { sa + 23040,  sa + 25344 };
    uint32_t* VR[2] = { sa + 27648,  sa + 29952 };
    const uint32_t sb = smem_u32(sa);

    const long rowQ = (long)(iv * B_ + b) * N_;

    #pragma unroll
    for (int p = 0; p < 2; p++) {
        const __nv_bfloat16* src = (p ? qkvL : qkvH) + rowQ * D3 + h * HD_;
        uint32_t dstb = sb + (uint32_t)(p ? 9216 * 4 : 0);
        #pragma unroll
        for (int i = 0; i < 8; i++) {
            int lin = i * 256 + t;
            int row = lin >> 3, seg = lin & 7;
            CP_ASYNC16(dstb + row * 144 + seg * 16,
                       (const char*)(src + (long)row * D3) + seg * 16);
        }
    }
    CP_COMMIT();

    float outacc[2][8][4];
    #pragma unroll
    for (int a = 0; a < 2; a++)
        #pragma unroll
        for (int n = 0; n < 8; n++)
            #pragma unroll
            for (int q = 0; q < 4; q++) outacc[a][n][q] = 0.f;

    for (int j = 0; j < NVW; j++) {
        const long rowK = (long)(j * B_ + b) * N_;
        float m_[2][2] = {{-1e30f, -1e30f}, {-1e30f, -1e30f}};
        float l_[2][2] = {{0.f, 0.f}, {0.f, 0.f}};
        float cacc[2][8][4];
        #pragma unroll
        for (int a = 0; a < 2; a++)
            #pragma unroll
            for (int n = 0; n < 8; n++)
                #pragma unroll
                for (int q = 0; q < 4; q++) cacc[a][n][q] = 0.f;

        for (int kc = 0; kc < 4; kc++) {
            __syncthreads();
            #pragma unroll
            for (int p = 0; p < 2; p++) {
                const __nv_bfloat16* gk = (p ? qkvL : qkvH)
                    + (rowK + kc * 64) * D3 + C_ + h * HD_;
                const __nv_bfloat16* gv = (p ? qkvL : qkvH)
                    + (rowK + kc * 64) * D3 + 2 * C_ + h * HD_;
                uint32_t kb = sb + (uint32_t)((18432 + p * 2304) * 4);
                uint32_t vb = sb + (uint32_t)((27648 + p * 2304) * 4);
                #pragma unroll
                for (int i = 0; i < 2; i++) {
                    int lin = i * 256 + t;
                    int row = lin >> 3, seg = lin & 7;
                    CP_ASYNC16(kb + row * 144 + seg * 16,
                               (const char*)(gk + (long)row * D3) + seg * 16);
                    CP_ASYNC16(vb + row * 144 + seg * 16,
                               (const char*)(gv + (long)row * D3) + seg * 16);
                }
            }
            CP_COMMIT();
            CP_WAIT0();
            __syncthreads();

            #pragma unroll
            for (int p = 0; p < 2; p++) {
                const uint32_t* R = VR[p];
                uint32_t* T = VT[p];
                #pragma unroll
                for (int i = 0; i < 4; i++) {
                    int lin = i * 256 + t;
                    int kp = lin >> 5, cp = lin & 31;
                    uint32_t r0 = R[(2 * kp) * 36 + cp];
                    uint32_t r1 = R[(2 * kp + 1) * 36 + cp];
                    T[(2 * cp) * 36 + kp]     = (r0 & 0xffffu) | (r1 << 16);
                    T[(2 * cp + 1) * 36 + kp] = (r0 >> 16) | (r1 & 0xffff0000u);
                }
            }
            __syncthreads();

            float sacc[2][8][4];
            #pragma unroll
            for (int a = 0; a < 2; a++)
                #pragma unroll
                for (int n = 0; n < 8; n++)
                    #pragma unroll
                    for (int q = 0; q < 4; q++) sacc[a][n][q] = 0.f;

            #pragma unroll
            for (int kt = 0; kt < 4; kt++) {
                uint32_t qh_[2][4], ql_[2][4];
                #pragma unroll
                for (int mt = 0; mt < 2; mt++) {
                    int r0 = wm + mt * 16 + fr;
                    int i0 = r0 * 36 + kt * 8 + fk;
                    int i1 = (r0 + 8) * 36 + kt * 8 + fk;
                    qh_[mt][0] = Qs[0][i0];
                    qh_[mt][1] = Qs[0][i1];
                    qh_[mt][2] = Qs[0][i0 + 4];
                    qh_[mt][3] = Qs[0][i1 + 4];
                    ql_[mt][0] = Qs[1][i0];
                    ql_[mt][1] = Qs[1][i1];
                    ql_[mt][2] = Qs[1][i0 + 4];
                    ql_[mt][3] = Qs[1][i1 + 4];
                }
                #pragma unroll
                for (int nt = 0; nt < 8; nt++) {
                    int ib = (nt * 8 + fr) * 36 + kt * 8 + fk;
                    uint32_t kh_[2] = { Ks[0][ib], Ks[0][ib + 4] };
                    uint32_t kl_[2] = { Ks[1][ib], Ks[1][ib + 4] };
                    #pragma unroll
                    for (int mt = 0; mt < 2; mt++) {
                        MMA_BF16(sacc[mt][nt], qh_[mt], kh_);
                        MMA_BF16(sacc[mt][nt], qh_[mt], kl_);
                        MMA_BF16(sacc[mt][nt], ql_[mt], kh_);
                    }
                }
            }
            #pragma unroll
            for (int a = 0; a < 2; a++)
                #pragma unroll
                for (int n = 0; n < 8; n++)
                    #pragma unroll
                    for (int q = 0; q < 4; q++) sacc[a][n][q] *= 0.125f;

            #pragma unroll
            for (int mt = 0; mt < 2; mt++) {
                #pragma unroll
                for (int hf = 0; hf < 2; hf++) {
                    float cm = -1e30f;
                    #pragma unroll
                    for (int nt = 0; nt < 8; nt++)
                        cm = fmaxf(cm, fmaxf(sacc[mt][nt][hf*2], sacc[mt][nt][hf*2+1]));
                    cm = fmaxf(cm, __shfl_xor_sync(0xffffffffu, cm, 1));
                    cm = fmaxf(cm, __shfl_xor_sync(0xffffffffu, cm, 2));
                    float mo = m_[mt][hf];
                    float mn = fmaxf(mo, cm);
                    float corr = __expf(mo - mn);
                    m_[mt][hf] = mn;
                    float ps = 0.f;
                    #pragma unroll
                    for (int nt = 0; nt < 8; nt++) {
                        float p0 = __expf(sacc[mt][nt][hf*2]   - mn);
                        float p1 = __expf(sacc[mt][nt][hf*2+1] - mn);
                        sacc[mt][nt][hf*2]   = p0;
                        sacc[mt][nt][hf*2+1] = p1;
                        ps += p0 + p1;
                    }
                    ps += __shfl_xor_sync(0xffffffffu, ps, 1);
                    ps += __shfl_xor_sync(0xffffffffu, ps, 2);
                    l_[mt][hf] = l_[mt][hf] * corr + ps;
                    #pragma unroll
                    for (int nt = 0; nt < 8; nt++) {
                        cacc[mt][nt][hf*2]   *= corr;
                        cacc[mt][nt][hf*2+1] *= corr;
                    }
                }
            }

            #pragma unroll
            for (int ktk = 0; ktk < 4; ktk++) {
                uint32_t ph_[2][4], pl_[2][4];
                #pragma unroll
                for (int mt = 0; mt < 2; mt++) {
                    #pragma unroll
                    for (int q = 0; q < 4; q++) {
                        int nt = 2 * ktk + (q >> 1);
                        int base = (q & 1) * 2;
                        float p0 = sacc[mt][nt][base];
                        float p1 = sacc[mt][nt][base + 1];
                        __nv_bfloat16 h0 = __float2bfloat16(p0);
                        __nv_bfloat16 h1 = __float2bfloat16(p1);
                        float r0 = p0 - __bfloat162float(h0);
                        float r1 = p1 - __bfloat162float(h1);
                        uint16_t u0 = *(uint16_t*)&h0, u1 = *(uint16_t*)&h1;
                        ph_[mt][q] = ((uint32_t)u1 << 16) | u0;
                        pl_[mt][q] = bfpack(r0, r1);
                    }
                }
                #pragma unroll
                for (int nc = 0; nc < 8; nc++) {
                    int ib = (nc * 8 + fr) * 36 + ktk * 8 + fk;
                    uint32_t vh_[2] = { VT[0][ib], VT[0][ib + 4] };
                    uint32_t vl_[2] = { VT[1][ib], VT[1][ib + 4] };
                    #pragma unroll
                    for (int mt = 0; mt < 2; mt++) {
                        MMA_BF16(cacc[mt][nc], ph_[mt], vh_);
                        MMA_BF16(cacc[mt][nc], ph_[mt], vl_);
                        MMA_BF16(cacc[mt][nc], pl_[mt], vh_);
                    }
                }
            }
        } // kc

        #pragma unroll
        for (int mt = 0; mt < 2; mt++)
            #pragma unroll
            for (int hf = 0; hf < 2; hf++) {
                float inv = 0.25f / l_[mt][hf];
                #pragma unroll
                for (int nt = 0; nt < 8; nt++) {
                    outacc[mt][nt][hf*2]   += cacc[mt][nt][hf*2]   * inv;
                    outacc[mt][nt][hf*2+1] += cacc[mt][nt][hf*2+1] * inv;
                }
            }
    } // j

    #pragma unroll
    for (int mt = 0; mt < 2; mt++) {
        #pragma unroll
        for (int hf = 0; hf < 2; hf++) {
            int row = wm + mt * 16 + fr + hf * 8;
            long obase = (rowQ + row) * C_ + h * HD_;
            #pragma unroll
            for (int nt = 0; nt < 8; nt++) {
                int col = nt * 8 + 2 * fk;
                *(__half2*)&ctxF[obase + col] =
                    __floats2half2_rn(outacc[mt][nt][hf*2], outacc[mt][nt][hf*2+1]);
            }
        }
    }
}

// ---------------- learnable-query projection ----------------
__global__ __launch_bounds__(256) void qh_kernel(
    const float* __restrict__ query, const float* __restrict__ w,
    const float* __restrict__ bq, float* __restrict__ qh)
{
    int v = blockIdx.x;
    int t = threadIdx.x;
    for (int d = t; d < C_; d += 256) {
        const float* wr = w + (long)v * (3 * C_) * C_ + (long)d * C_;
        float acc = 0.0f;
        #pragma unroll 4
        for (int c = 0; c < C_; c++) acc += query[c] * wr[c];
        qh[v * C_ + d] = acc + bq[(long)v * (3 * C_) + d];
    }
}

// ---------------- cross attention (single query) ----------------
__global__ __launch_bounds__(256) void cross_attn_kernel(
    const float* __restrict__ kv, const float* __restrict__ qh,
    float* __restrict__ c2)
{
    int h = blockIdx.x, b = blockIdx.y, v = blockIdx.z;
    int t = threadIdx.x;

    __shared__ float p[256];
    __shared__ float red[256];
    __shared__ float part[4][64];

    const float* kvb = kv + ((long)(v * B_ + b) * N_) * (2 * C_);
    const float* qhp = qh + v * C_ + h * HD_;
    const float* krow = kvb + (long)t * (2 * C_) + h * HD_;

    float s = 0.0f;
    #pragma unroll
    for (int e = 0; e < 64; e++) s += qhp[e] * krow[e];
    s *= 0.125f;

    red[t] = s; __syncthreads();
    for (int off = 128; off > 0; off >>= 1) {
        if (t < off) red[t] = fmaxf(red[t], red[t + off]);
        __syncthreads();
    }
    float mx = red[0];
    __syncthreads();

    float e_ = __expf(s - mx);
    p[t] = e_; red[t] = e_;
    __syncthreads();
    for (int off = 128; off > 0; off >>= 1) {
        if (t < off) red[t] += red[t + off];
        __syncthreads();
    }
    float inv = 1.0f / red[0];
    __syncthreads();

    int e = t & 63, pid = t >> 6;
    float acc = 0.0f;
    for (int n = pid * 64; n < pid * 64 + 64; n++)
        acc += p[n] * kvb[(long)n * (2 * C_) + C_ + h * HD_ + e];
    part[pid][e] = acc;
    __syncthreads();
    if (t < 64) {
        float r = (part[0][t] + part[1][t]) + (part[2][t] + part[3][t]);
        c2[(long)(v * B_ + b) * C_ + h * HD_ + t] = r * inv;
    }
}

// ---------------- output projection + broadcast over N ----------------
__global__ __launch_bounds__(256) void out_kernel(
    const float* __restrict__ c2, const float* __restrict__ w,
    const float* __restrict__ bias, float* __restrict__ out)
{
    int v = blockIdx.x, b = blockIdx.y;
    int t = threadIdx.x;

    __shared__ float sc[C_];
    for (int c = t; c < C_; c += 256) sc[c] = c2[(long)(v * B_ + b) * C_ + c];
    __syncthreads();

    float o[3];
    #pragma unroll
    for (int r = 0; r < 3; r++) {
        int co = t + r * 256;
        const float* wr = w + (long)v * C_ * C_ + (long)co * C_;
        float d0 = 0.f, d1 = 0.f, d2 = 0.f, d3 = 0.f;
        #pragma unroll 4
        for (int c = 0; c < C_; c += 4) {
            d0 += sc[c + 0] * wr[c + 0];
            d1 += sc[c + 1] * wr[c + 1];
            d2 += sc[c + 2] * wr[c + 2];
            d3 += sc[c + 3] * wr[c + 3];
        }
        o[r] = ((d0 + d1) + (d2 + d3)) + bias[v * C_ + co];
    }
    for (int n = 0; n < N_; n++) {
        long base = ((long)b * N_ + n) * (NVW * C_) + (long)v * C_;
        #pragma unroll
        for (int r = 0; r < 3; r++) out[base + t + r * 256] = o[r];
    }
}

// ---------------- launch ----------------
extern "C" void kernel_launch(void* const* d_in, const int* in_sizes, int n_in,
                              void* d_out, int out_size)
{
    const float* X        = (const float*)d_in[0];
    const float* norm1_g  = (const float*)d_in[1];
    const float* norm1_b  = (const float*)d_in[2];
    const float* qkv_w    = (const float*)d_in[3];
    const float* proj_w   = (const float*)d_in[4];
    const float* proj_b   = (const float*)d_in[5];
    const float* norm2_g  = (const float*)d_in[6];
    const float* norm2_b  = (const float*)d_in[7];
    const float* fc1_w    = (const float*)d_in[8];
    const float* fc1_b    = (const float*)d_in[9];
    const float* fc2_w    = (const float*)d_in[10];
    const float* fc2_b    = (const float*)d_in[11];
    const float* query    = (const float*)d_in[12];
    const float* mha_in_w = (const float*)d_in[13];
    const float* mha_in_b = (const float*)d_in[14];
    const float* mha_out_w= (const float*)d_in[15];
    const float* mha_out_b= (const float*)d_in[16];
    float* out = (float*)d_out;

    float *x, *kv, *qh, *c2;
    __nv_bfloat16 *qkvH, *qkvL;
    __half *XnF, *ctxF, *hnF, *h1F, *x2F;
    __half *WqkvH, *WqkvL, *WprjH, *WprjL, *Wf1H, *Wf1L, *Wf2H, *Wf2L, *WmhaH, *WmhaL;
    cudaGetSymbolAddress((void**)&x,    g_x);
    cudaGetSymbolAddress((void**)&kv,   g_kv);
    cudaGetSymbolAddress((void**)&qh,   g_qh);
    cudaGetSymbolAddress((void**)&c2,   g_c2);
    cudaGetSymbolAddress((void**)&qkvH, g_qkvH); cudaGetSymbolAddress((void**)&qkvL, g_qkvL);
    cudaGetSymbolAddress((void**)&XnF,  g_XnF);
    cudaGetSymbolAddress((void**)&ctxF, g_ctxF);
    cudaGetSymbolAddress((void**)&hnF,  g_hnF);
    cudaGetSymbolAddress((void**)&h1F,  g_h1F);
    cudaGetSymbolAddress((void**)&x2F,  g_x2F);
    cudaGetSymbolAddress((void**)&WqkvH, g_WqkvH); cudaGetSymbolAddress((void**)&WqkvL, g_WqkvL);
    cudaGetSymbolAddress((void**)&WprjH, g_WprjH); cudaGetSymbolAddress((void**)&WprjL, g_WprjL);
    cudaGetSymbolAddress((void**)&Wf1H,  g_Wf1H);  cudaGetSymbolAddress((void**)&Wf1L,  g_Wf1L);
    cudaGetSymbolAddress((void**)&Wf2H,  g_Wf2H);  cudaGetSymbolAddress((void**)&Wf2L,  g_Wf2L);
    cudaGetSymbolAddress((void**)&WmhaH, g_WmhaH); cudaGetSymbolAddress((void**)&WmhaL, g_WmhaL);

    cudaFuncSetAttribute(gemm_mma, cudaFuncAttributeMaxDynamicSharedMemorySize,
                         GEMM_SMEM);
    cudaFuncSetAttribute(attn_mma, cudaFuncAttributeMaxDynamicSharedMemorySize,
                         ATTN_SMEM);

    const long MC  = (long)MROWS * C_;
    const long MH  = (long)MROWS * HID_;

    auto wsplit = [&](const float* src, __half* hi, __half* lo, long n) {
        int n4 = (int)(n / 4);
        wsplit_kernel<<<(n4 + 255) / 256, 256>>>(src, hi, lo, n4);
    };

    // 0. split all weights into fp16 hi/lo planes
    wsplit(qkv_w,    WqkvH, WqkvL, (long)NVW * 3 * C_ * C_);
    wsplit(proj_w,   WprjH, WprjL, (long)NVW * C_ * C_);
    wsplit(fc1_w,    Wf1H,  Wf1L,  (long)NVW * HID_ * C_);
    wsplit(fc2_w,    Wf2H,  Wf2L,  (long)NVW * C_ * HID_);
    wsplit(mha_in_w, WmhaH, WmhaL, (long)NVW * 3 * C_ * C_);

    // 1. LN1 -> Xn fp16 (remap [b*NV+v] -> [v][b])
    ln_kernel<<<NVW * B_ * N_, 256>>>(X, norm1_g, norm1_b, XnF, 1, 0);

    // 2. QKV GEMM -> bf16 hi/lo qkv planes (for 3-term attention)
    gemm_mma<<<dim3(3 * C_ / 128, MROWS / 128, NVW), 256, GEMM_SMEM>>>(
        XnF, WqkvH, WqkvL, nullptr, nullptr, nullptr, qkvH, qkvL, nullptr,
        C_, 3 * C_, MC, (long)3 * C_ * C_, 0, 0, (long)MROWS * 3 * C_, 1.0f, 0);

    // 3. MMA flash attention, mean over j -> ctx fp16
    attn_mma<<<dim3(H_, B_, NVW), 256, ATTN_SMEM>>>(qkvH, qkvL, ctxF);

    // 4. proj GEMM (alpha=2 folds residual doubling) -> f32 x
    gemm_mma<<<dim3(C_ / 128, MROWS / 128, NVW), 256, GEMM_SMEM>>>(
        ctxF, WprjH, WprjL, proj_b, nullptr, x, nullptr, nullptr, nullptr,
        C_, C_, MC, (long)C_ * C_, C_, 0, MC, 2.0f, 0);

    // 5. LN2 -> hn fp16
    ln_kernel<<<NVW * B_ * N_, 256>>>(x, norm2_g, norm2_b, hnF, 0, 1);

    // 6. fc1 GEMM + bias + GELU -> h1 fp16
    gemm_mma<<<dim3(HID_ / 128, MROWS / 128, NVW), 256, GEMM_SMEM>>>(
        hnF, Wf1H, Wf1L, fc1_b, nullptr, nullptr, nullptr, nullptr, h1F,
        C_, HID_, MC, (long)HID_ * C_, HID_, 0, MH, 1.0f, 1);

    // 7. fc2 GEMM + bias + residual(x) -> x2 fp16
    gemm_mma<<<dim3(C_ / 128, MROWS / 128, NVW), 256, GEMM_SMEM>>>(
        h1F, Wf2H, Wf2L, fc2_b, x, nullptr, nullptr, nullptr, x2F,
        HID_, C_, MH, (long)C_ * HID_, C_, MC, MC, 1.0f, 0);

    // 8. learnable query projection (f32 weights)
    qh_kernel<<<NVW, 256>>>(query, mha_in_w, mha_in_b, qh);

    // 9. K/V projection of x2 -> f32 kv (W rows [C,3C) of mha_in_w)
    gemm_mma<<<dim3(2 * C_ / 128, MROWS / 128, NVW), 256, GEMM_SMEM>>>(
        x2F, WmhaH + (long)C_ * C_, WmhaL + (long)C_ * C_,
        mha_in_b + C_, nullptr, kv, nullptr, nullptr, nullptr,
        C_, 2 * C_, MC, (long)3 * C_ * C_, (long)3 * C_, 0,
        (long)MROWS * 2 * C_, 1.0f, 0);

    // 10. single-query cross attention -> c2[v][b][C]
    cross_attn_kernel<<<dim3(H_, B_, NVW), 256>>>(kv, qh, c2);

    // 11. output projection + broadcast over N
    out_kernel<<<dim3(NVW, B_), 256>>>(c2, mha_out_w, mha_out_b, out);
}

// round 15
// speedup vs baseline: 3.8435x; 1.0462x over previous
#include <cuda_runtime.h>
#include <cuda_bf16.h>
#include <cuda_fp16.h>
#include <math.h>
#include <stdint.h>

#define NVW 4
#define B_ 4
#define N_ 256
#define C_ 768
#define H_ 12
#define HD_ 64
#define HID_ 3072
#define MROWS (B_*N_)   // 1024 rows per view

// ---------------- scratch (device globals; no allocation) ----------------
__device__ float g_x  [NVW*MROWS*C_];
__device__ float g_kv [NVW*MROWS*2*C_];
__device__ float g_qh [NVW*C_];
__device__ float g_c2 [NVW*B_*C_];
// bf16 hi/lo qkv planes (consumed by 3-term attention)
__device__ __nv_bfloat16 g_qkvH[NVW*MROWS*3*C_], g_qkvL[NVW*MROWS*3*C_];
// fp16 single-plane activations
__device__ __half g_XnF [NVW*MROWS*C_];
__device__ __half g_ctxF[NVW*MROWS*C_];
__device__ __half g_hnF [NVW*MROWS*C_];
__device__ __half g_h1F [NVW*MROWS*HID_];
__device__ __half g_x2F [NVW*MROWS*C_];
// fp16 hi/lo weight planes
__device__ __half g_WqkvH[NVW*3*C_*C_], g_WqkvL[NVW*3*C_*C_];
__device__ __half g_WprjH[NVW*C_*C_],   g_WprjL[NVW*C_*C_];
__device__ __half g_Wf1H [NVW*HID_*C_], g_Wf1L [NVW*HID_*C_];
__device__ __half g_Wf2H [NVW*C_*HID_], g_Wf2L [NVW*C_*HID_];
__device__ __half g_WmhaH[NVW*3*C_*C_], g_WmhaL[NVW*3*C_*C_];

__device__ __forceinline__ float gelu_exact(float x) {
    return 0.5f * x * (1.0f + erff(x * 0.70710678118654752f));
}

__device__ __forceinline__ void bfsplit(float x, __nv_bfloat16& h, __nv_bfloat16& l) {
    h = __float2bfloat16(x);
    l = __float2bfloat16(x - __bfloat162float(h));
}

__device__ __forceinline__ void hsplit(float x, __half& h, __half& l) {
    h = __float2half(x);
    l = __float2half(x - __half2float(h));
}

__device__ __forceinline__ uint32_t bfpack(float a, float b) {
    __nv_bfloat16 ha = __float2bfloat16(a);
    __nv_bfloat16 hb = __float2bfloat16(b);
    uint16_t ua = *(uint16_t*)&ha, ub = *(uint16_t*)&hb;
    return ((uint32_t)ub << 16) | ua;
}

__device__ __forceinline__ uint32_t smem_u32(const void* p) {
    uint32_t a;
    asm("{ .reg .u64 t; cvta.to.shared.u64 t, %1; cvt.u32.u64 %0, t; }"
        : "=r"(a) : "l"(p));
    return a;
}

#define CP_ASYNC16(dst, src) \
    asm volatile("cp.async.ca.shared.global [%0], [%1], 16;" \
                 :: "r"(dst), "l"(src) : "memory")
#define CP_COMMIT() \
    asm volatile("cp.async.commit_group;" ::: "memory")
#define CP_WAIT1() \
    asm volatile("cp.async.wait_group 1;" ::: "memory")
#define CP_WAIT0() \
    asm volatile("cp.async.wait_group 0;" ::: "memory")

#define MMA_BF16(d, a, b) \
    asm volatile( \
        "mma.sync.aligned.m16n8k16.row.col.f32.bf16.bf16.f32 " \
        "{%0,%1,%2,%3}, {%4,%5,%6,%7}, {%8,%9}, {%0,%1,%2,%3};" \
        : "+f"((d)[0]), "+f"((d)[1]), "+f"((d)[2]), "+f"((d)[3]) \
        : "r"((a)[0]), "r"((a)[1]), "r"((a)[2]), "r"((a)[3]), \
          "r"((b)[0]), "r"((b)[1]))

#define MMA_F16(d, a, b) \
    asm volatile( \
        "mma.sync.aligned.m16n8k16.row.col.f32.f16.f16.f32 " \
        "{%0,%1,%2,%3}, {%4,%5,%6,%7}, {%8,%9}, {%0,%1,%2,%3};" \
        : "+f"((d)[0]), "+f"((d)[1]), "+f"((d)[2]), "+f"((d)[3]) \
        : "r"((a)[0]), "r"((a)[1]), "r"((a)[2]), "r"((a)[3]), \
          "r"((b)[0]), "r"((b)[1]))

#define LDSM_X4(r0, r1, r2, r3, addr) \
    asm volatile("ldmatrix.sync.aligned.m8n8.x4.shared.b16 {%0,%1,%2,%3}, [%4];" \
        : "=r"(r0), "=r"(r1), "=r"(r2), "=r"(r3) : "r"(addr))

// ---------------- weight split kernel (f32 -> fp16 hi/lo) ----------------
__global__ __launch_bounds__(256) void wsplit_kernel(
    const float* __restrict__ src, __half* __restrict__ hi,
    __half* __restrict__ lo, int n4)
{
    int i = blockIdx.x * 256 + threadIdx.x;
    if (i >= n4) return;
    float4 s = ((const float4*)src)[i];
    __half h0, h1, h2, h3, l0, l1, l2, l3;
    hsplit(s.x, h0, l0); hsplit(s.y, h1, l1);
    hsplit(s.z, h2, l2); hsplit(s.w, h3, l3);
    __half2* Hp = (__half2*)hi;
    __half2* Lp = (__half2*)lo;
    Hp[2*i]   = __half2{h0, h1};
    Hp[2*i+1] = __half2{h2, h3};
    Lp[2*i]   = __half2{l0, l1};
    Lp[2*i+1] = __half2{l2, l3};
}

// ---------------- LayerNorm -> fp16 single plane ----------------
__global__ __launch_bounds__(256) void ln_kernel(
    const float* __restrict__ X, const float* __restrict__ g,
    const float* __restrict__ be, __half* __restrict__ Y,
    int remap, int pervw)
{
    int r = blockIdx.x;
    int v = r / (B_ * N_);
    long inrow;
    if (remap) {
        int rem = r % (B_ * N_);
        int bb = rem / N_;
        int n  = rem % N_;
        inrow = ((long)(bb * NVW + v) * N_ + n);
    } else {
        inrow = r;
    }
    const float* x = X + inrow * C_;
    long obase = (long)r * C_;
    const float* gg = g  + (pervw ? v * C_ : 0);
    const float* bb2 = be + (pervw ? v * C_ : 0);

    int t = threadIdx.x;
    float v0 = x[t], v1 = x[t + 256], v2 = x[t + 512];
    float s  = v0 + v1 + v2;
    float sq = v0 * v0 + v1 * v1 + v2 * v2;

    __shared__ float rs[256], rq[256];
    rs[t] = s; rq[t] = sq;
    __syncthreads();
    for (int off = 128; off > 0; off >>= 1) {
        if (t < off) { rs[t] += rs[t + off]; rq[t] += rq[t + off]; }
        __syncthreads();
    }
    float mean = rs[0] * (1.0f / C_);
    float var  = rq[0] * (1.0f / C_) - mean * mean;
    float rstd = rsqrtf(var + 1e-6f);

    #pragma unroll
    for (int rr = 0; rr < 3; rr++) {
        int c = t + rr * 256;
        float val = (rr == 0 ? v0 : (rr == 1 ? v1 : v2));
        float y = (val - mean) * rstd * gg[c] + bb2[c];
        Y[obase + c] = __float2half(y);
    }
}

// ---------------- 2-term FP16 mma.sync batched NT GEMM (ldmatrix) --------
// D = A*Wh + A*Wl. A single fp16 plane, W dual fp16 planes.
// CTA 128x128, 256 threads, 8 warps (2x4), warp tile 64x32, K-chunk 32.
// 3-stage cp.async pipeline; 2 CTAs/SM. Fragments via ldmatrix.x4:
// per k16-step: 4 (A) + 2 (Wh) + 2 (Wl) ldmatrix vs 32 scalar LDS.
#define KC 32
#define RSU 20
#define TILE_U (128 * RSU)                   // 2560 u32
#define NSTAGE 3
#define GEMM_SMEM (NSTAGE * 3 * TILE_U * 4)  // 92160 bytes

__global__ void __launch_bounds__(256, 2)
gemm_mma(const __half* __restrict__ A,
         const __half* __restrict__ Wh, const __half* __restrict__ Wl,
         const float* __restrict__ bias, const float* __restrict__ res,
         float* __restrict__ Cf,
         __nv_bfloat16* __restrict__ CH, __nv_bfloat16* __restrict__ CL,
         __half* __restrict__ Ch,
         int Kdim, int D,
         long sA, long sW, long sB, long sR, long sC, float alpha, int act)
{
    extern __shared__ uint32_t smu[];
    const int v = blockIdx.z;
    const int bm = blockIdx.y * 128, bn = blockIdx.x * 128;

    const int t = threadIdx.x, lane = t & 31, wid = t >> 5;
    const int wm = (wid >> 2) * 64;
    const int wn = (wid & 3) * 32;
    const int fr = lane >> 2;
    const int fk = lane & 3;

    // cp.async: 6 tasks/thread
    const char* gptr[6];
    uint32_t soff[6];
    #pragma unroll
    for (int s = 0; s < 6; s++) {
        int lin = s * 256 + t;
        int tile = lin >> 9;
        int row = (lin >> 2) & 127;
        int seg = lin & 3;
        const __half* base;
        if (tile == 0)      base = A  + (long)v * sA + (long)(bm + row) * Kdim;
        else if (tile == 1) base = Wh + (long)v * sW + (long)(bn + row) * Kdim;
        else                base = Wl + (long)v * sW + (long)(bn + row) * Kdim;
        gptr[s] = (const char*)base + seg * 16;
        soff[s] = (uint32_t)((tile * TILE_U + row * RSU) * 4 + seg * 16);
    }
    const uint32_t sbase = smem_u32(smu);

    // ldmatrix per-lane base addresses (u32 units, within a stage)
    // A fragment (mt): lanes 0-15 -> rows wm+mt*16+(lane&15), khalf (lane>>4)
    uint32_t aBase[4];
    {
        int rowA = wm + (lane & 15);
        int kh = (lane >> 4) & 1;
        #pragma unroll
        for (int mt = 0; mt < 4; mt++)
            aBase[mt] = (uint32_t)(((rowA + mt * 16) * RSU + kh * 4) * 4);
    }
    // W fragment quad q (nt = 2q, 2q+1), plane offset added at use:
    // g = lane>>3: row = wn + (2q + (g>>1))*8 + (lane&7), khalf = g&1
    uint32_t wBase[2];
    {
        int g = lane >> 3;
        int rowW = wn + ((g >> 1) * 8) + (lane & 7);
        int kh = g & 1;
        #pragma unroll
        for (int q = 0; q < 2; q++)
            wBase[q] = (uint32_t)(((rowW + q * 16) * RSU + kh * 4) * 4);
    }

    float acc[4][4][4];
    #pragma unroll
    for (int a = 0; a < 4; a++)
        #pragma unroll
        for (int b = 0; b < 4; b++)
            #pragma unroll
            for (int c = 0; c < 4; c++) acc[a][b][c] = 0.0f;

    const int steps = Kdim / KC;

    #pragma unroll
    for (int p = 0; p < 2; p++) {
        if (p < steps) {
            uint32_t st = sbase + (uint32_t)((p % NSTAGE) * 3 * TILE_U * 4);
            #pragma unroll
            for (int s = 0; s < 6; s++)
                CP_ASYNC16(st + soff[s], gptr[s] + p * 64);
        }
        CP_COMMIT();
    }

    for (int c = 0; c < steps; c++) {
        CP_WAIT1();
        __syncthreads();

        int p = c + 2;
        if (p < steps) {
            uint32_t st = sbase + (uint32_t)((p % NSTAGE) * 3 * TILE_U * 4);
            #pragma unroll
            for (int s = 0; s < 6; s++)
                CP_ASYNC16(st + soff[s], gptr[s] + p * 64);
        }
        CP_COMMIT();

        uint32_t stg = sbase + (uint32_t)((c % NSTAGE) * 3 * TILE_U * 4);
        uint32_t whOff = stg + (uint32_t)(TILE_U * 4);
        uint32_t wlOff = stg + (uint32_t)(2 * TILE_U * 4);

        #pragma unroll
        for (int s = 0; s < 2; s++) {
            uint32_t ks = (uint32_t)(s * 32);   // 8 u32 = 32 bytes per k16 step
            uint32_t ah[4][4], bh[4][2], bl[4][2];
            #pragma unroll
            for (int mt = 0; mt < 4; mt++)
                LDSM_X4(ah[mt][0], ah[mt][1], ah[mt][2], ah[mt][3],
                        stg + aBase[mt] + ks);
            #pragma unroll
            for (int q = 0; q < 2; q++) {
                LDSM_X4(bh[2*q][0], bh[2*q][1], bh[2*q+1][0], bh[2*q+1][1],
                        whOff + wBase[q] + ks);
                LDSM_X4(bl[2*q][0], bl[2*q][1], bl[2*q+1][0], bl[2*q+1][1],
                        wlOff + wBase[q] + ks);
            }
            #pragma unroll
            for (int mt = 0; mt < 4; mt++)
                #pragma unroll
                for (int nt = 0; nt < 4; nt++)
                    MMA_F16(acc[mt][nt], ah[mt], bh[nt]);
            #pragma unroll
            for (int mt = 0; mt < 4; mt++)
                #pragma unroll
                for (int nt = 0; nt < 4; nt++)
                    MMA_F16(acc[mt][nt], ah[mt], bl[nt]);
        }
    }

    __syncthreads();

    #pragma unroll
    for (int mt = 0; mt < 4; mt++) {
        #pragma unroll
        for (int nt = 0; nt < 4; nt++) {
            int row = bm + wm + mt * 16 + fr;
            int col = bn + wn + nt * 8 + 2 * fk;
            float b0 = 0.f, b1 = 0.f;
            if (bias) {
                b0 = bias[(long)v * sB + col];
                b1 = bias[(long)v * sB + col + 1];
            }
            #pragma unroll
            for (int half = 0; half < 2; half++) {
                int r = row + half * 8;
                float v0 = alpha * (acc[mt][nt][half * 2 + 0] + b0);
                float v1 = alpha * (acc[mt][nt][half * 2 + 1] + b1);
                if (act == 1) { v0 = gelu_exact(v0); v1 = gelu_exact(v1); }
                if (res) {
                    v0 += res[(long)v * sR + (long)r * D + col];
                    v1 += res[(long)v * sR + (long)r * D + col + 1];
                }
                long off = (long)v * sC + (long)r * D + col;
                if (Cf) {
                    float2 o2 = {v0, v1};
                    *(float2*)&Cf[off] = o2;
                } else if (CH) {
                    __nv_bfloat16 h0, h1, l0, l1;
                    bfsplit(v0, h0, l0);
                    bfsplit(v1, h1, l1);
                    *(__nv_bfloat162*)&CH[off] = __nv_bfloat162{h0, h1};
                    *(__nv_bfloat162*)&CL[off] = __nv_bfloat162{l0, l1};
                } else {
                    *(__half2*)&Ch[off] = __floats2half2_rn(v0, v1);
                }
            }
        }
    }
}

// ---------------- MMA flash attention (3-term bf16), mean over j ----------
#define ATTN_SMEM (32256 * 4)

__global__ void __launch_bounds__(256, 1)
attn_mma(const __nv_bfloat16* __restrict__ qkvH,
         const __nv_bfloat16* __restrict__ qkvL,
         __half* __restrict__ ctxF)
{
    const int h = blockIdx.x, b = blockIdx.y, iv = blockIdx.z;
    const int t = threadIdx.x, lane = t & 31, wid = t >> 5;
    const int fr = lane >> 2, fk = lane & 3;
    const int wm = wid * 32;
    const int D3 = 3 * C_;

    extern __shared__ uint32_t sa[];
    uint32_t* Qs[2] = { sa,          sa + 9216 };
    uint32_t* Ks[2] = { sa + 18432,  sa + 20736 };
    uint32_t* VT[2] = { sa + 23040,  sa + 25344 };
    uint32_t* VR[2] = { sa + 27648,  sa + 29952 };
    const uint32_t sb = smem_u32(sa);

    const long rowQ = (long)(iv * B_ + b) * N_;

    #pragma unroll
    for (int p = 0; p < 2; p++) {
        const __nv_bfloat16* src = (p ? qkvL : qkvH) + rowQ * D3 + h * HD_;
        uint32_t dstb = sb + (uint32_t)(p ? 9216 * 4 : 0);
        #pragma unroll
        for (int i = 0; i < 8; i++) {
            int lin = i * 256 + t;
            int row = lin >> 3, seg = lin & 7;
            CP_ASYNC16(dstb + row * 144 + seg * 16,
                       (const char*)(src + (long)row * D3) + seg * 16);
        }
    }
    CP_COMMIT();

    float outacc[2][8][4];
    #pragma unroll
    for (int a = 0; a < 2; a++)
        #pragma unroll
        for (int n = 0; n < 8; n++)
            #pragma unroll
            for (int q = 0; q < 4; q++) outacc[a][n][q] = 0.f;

    for (int j = 0; j < NVW; j++) {
        const long rowK = (long)(j * B_ + b) * N_;
        float m_[2][2] = {{-1e30f, -1e30f}, {-1e30f, -1e30f}};
        float l_[2][2] = {{0.f, 0.f}, {0.f, 0.f}};
        float cacc[2][8][4];
        #pragma unroll
        for (int a = 0; a < 2; a++)
            #pragma unroll
            for (int n = 0; n < 8; n++)
                #pragma unroll
                for (int q = 0; q < 4; q++) cacc[a][n][q] = 0.f;

        for (int kc = 0; kc < 4; kc++) {
            __syncthreads();
            #pragma unroll
            for (int p = 0; p < 2; p++) {
                const __nv_bfloat16* gk = (p ? qkvL : qkvH)
                    + (rowK + kc * 64) * D3 + C_ + h * HD_;
                const __nv_bfloat16* gv = (p ? qkvL : qkvH)
                    + (rowK + kc * 64) * D3 + 2 * C_ + h * HD_;
                uint32_t kb = sb + (uint32_t)((18432 + p * 2304) * 4);
                uint32_t vb = sb + (uint32_t)((27648 + p * 2304) * 4);
                #pragma unroll
                for (int i = 0; i < 2; i++) {
                    int lin = i * 256 + t;
                    int row = lin >> 3, seg = lin & 7;
                    CP_ASYNC16(kb + row * 144 + seg * 16,
                               (const char*)(gk + (long)row * D3) + seg * 16);
                    CP_ASYNC16(vb + row * 144 + seg * 16,
                               (const char*)(gv + (long)row * D3) + seg * 16);
                }
            }
            CP_COMMIT();
            CP_WAIT0();
            __syncthreads();

            #pragma unroll
            for (int p = 0; p < 2; p++) {
                const uint32_t* R = VR[p];
                uint32_t* T = VT[p];
                #pragma unroll
                for (int i = 0; i < 4; i++) {
                    int lin = i * 256 + t;
                    int kp = lin >> 5, cp = lin & 31;
                    uint32_t r0 = R[(2 * kp) * 36 + cp];
                    uint32_t r1 = R[(2 * kp + 1) * 36 + cp];
                    T[(2 * cp) * 36 + kp]     = (r0 & 0xffffu) | (r1 << 16);
                    T[(2 * cp + 1) * 36 + kp] = (r0 >> 16) | (r1 & 0xffff0000u);
                }
            }
            __syncthreads();

            float sacc[2][8][4];
            #pragma unroll
            for (int a = 0; a < 2; a++)
                #pragma unroll
                for (int n = 0; n < 8; n++)
                    #pragma unroll
                    for (int q = 0; q < 4; q++) sacc[a][n][q] = 0.f;

            #pragma unroll
            for (int kt = 0; kt < 4; kt++) {
                uint32_t qh_[2][4], ql_[2][4];
                #pragma unroll
                for (int mt = 0; mt < 2; mt++) {
                    int r0 = wm + mt * 16 + fr;
                    int i0 = r0 * 36 + kt * 8 + fk;
                    int i1 = (r0 + 8) * 36 + kt * 8 + fk;
                    qh_[mt][0] = Qs[0][i0];
                    qh_[mt][1] = Qs[0][i1];
                    qh_[mt][2] = Qs[0][i0 + 4];
                    qh_[mt][3] = Qs[0][i1 + 4];
                    ql_[mt][0] = Qs[1][i0];
                    ql_[mt][1] = Qs[1][i1];
                    ql_[mt][2] = Qs[1][i0 + 4];
                    ql_[mt][3] = Qs[1][i1 + 4];
                }
                #pragma unroll
                for (int nt = 0; nt < 8; nt++) {
                    int ib = (nt * 8 + fr) * 36 + kt * 8 + fk;
                    uint32_t kh_[2] = { Ks[0][ib], Ks[0][ib + 4] };
                    uint32_t kl_[2] = { Ks[1][ib], Ks[1][ib + 4] };
                    #pragma unroll
                    for (int mt = 0; mt < 2; mt++) {
                        MMA_BF16(sacc[mt][nt], qh_[mt], kh_);
                        MMA_BF16(sacc[mt][nt], qh_[mt], kl_);
                        MMA_BF16(sacc[mt][nt], ql_[mt], kh_);
                    }
                }
            }
            #pragma unroll
            for (int a = 0; a < 2; a++)
                #pragma unroll
                for (int n = 0; n < 8; n++)
                    #pragma unroll
                    for (int q = 0; q < 4; q++) sacc[a][n][q] *= 0.125f;

            #pragma unroll
            for (int mt = 0; mt < 2; mt++) {
                #pragma unroll
                for (int hf = 0; hf < 2; hf++) {
                    float cm = -1e30f;
                    #pragma unroll
                    for (int nt = 0; nt < 8; nt++)
                        cm = fmaxf(cm, fmaxf(sacc[mt][nt][hf*2], sacc[mt][nt][hf*2+1]));
                    cm = fmaxf(cm, __shfl_xor_sync(0xffffffffu, cm, 1));
                    cm = fmaxf(cm, __shfl_xor_sync(0xffffffffu, cm, 2));
                    float mo = m_[mt][hf];
                    float mn = fmaxf(mo, cm);
                    float corr = __expf(mo - mn);
                    m_[mt][hf] = mn;
                    float ps = 0.f;
                    #pragma unroll
                    for (int nt = 0; nt < 8; nt++) {
                        float p0 = __expf(sacc[mt][nt][hf*2]   - mn);
                        float p1 = __expf(sacc[mt][nt][hf*2+1] - mn);
                        sacc[mt][nt][hf*2]   = p0;
                        sacc[mt][nt][hf*2+1] = p1;
                        ps += p0 + p1;
                    }
                    ps += __shfl_xor_sync(0xffffffffu, ps, 1);
                    ps += __shfl_xor_sync(0xffffffffu, ps, 2);
                    l_[mt][hf] = l_[mt][hf] * corr + ps;
                    #pragma unroll
                    for (int nt = 0; nt < 8; nt++) {
                        cacc[mt][nt][hf*2]   *= corr;
                        cacc[mt][nt][hf*2+1] *= corr;
                    }
                }
            }

            #pragma unroll
            for (int ktk = 0; ktk < 4; ktk++) {
                uint32_t ph_[2][4], pl_[2][4];
                #pragma unroll
                for (int mt = 0; mt < 2; mt++) {
                    #pragma unroll
                    for (int q = 0; q < 4; q++) {
                        int nt = 2 * ktk + (q >> 1);
                        int base = (q & 1) * 2;
                        float p0 = sacc[mt][nt][base];
                        float p1 = sacc[mt][nt][base + 1];
                        __nv_bfloat16 h0 = __float2bfloat16(p0);
                        __nv_bfloat16 h1 = __float2bfloat16(p1);
                        float r0 = p0 - __bfloat162float(h0);
                        float r1 = p1 - __bfloat162float(h1);
                        uint16_t u0 = *(uint16_t*)&h0, u1 = *(uint16_t*)&h1;
                        ph_[mt][q] = ((uint32_t)u1 << 16) | u0;
                        pl_[mt][q] = bfpack(r0, r1);
                    }
                }
                #pragma unroll
                for (int nc = 0; nc < 8; nc++) {
                    int ib = (nc * 8 + fr) * 36 + ktk * 8 + fk;
                    uint32_t vh_[2] = { VT[0][ib], VT[0][ib + 4] };
                    uint32_t vl_[2] = { VT[1][ib], VT[1][ib + 4] };
                    #pragma unroll
                    for (int mt = 0; mt < 2; mt++) {
                        MMA_BF16(cacc[mt][nc], ph_[mt], vh_);
                        MMA_BF16(cacc[mt][nc], ph_[mt], vl_);
                        MMA_BF16(cacc[mt][nc], pl_[mt], vh_);
                    }
                }
            }
        } // kc

        #pragma unroll
        for (int mt = 0; mt < 2; mt++)
            #pragma unroll
            for (int hf = 0; hf < 2; hf++) {
                float inv = 0.25f / l_[mt][hf];
                #pragma unroll
                for (int nt = 0; nt < 8; nt++) {
                    outacc[mt][nt][hf*2]   += cacc[mt][nt][hf*2]   * inv;
                    outacc[mt][nt][hf*2+1] += cacc[mt][nt][hf*2+1] * inv;
                }
            }
    } // j

    #pragma unroll
    for (int mt = 0; mt < 2; mt++) {
        #pragma unroll
        for (int hf = 0; hf < 2; hf++) {
            int row = wm + mt * 16 + fr + hf * 8;
            long obase = (rowQ + row) * C_ + h * HD_;
            #pragma unroll
            for (int nt = 0; nt < 8; nt++) {
                int col = nt * 8 + 2 * fk;
                *(__half2*)&ctxF[obase + col] =
                    __floats2half2_rn(outacc[mt][nt][hf*2], outacc[mt][nt][hf*2+1]);
            }
        }
    }
}

// ---------------- learnable-query projection ----------------
__global__ __launch_bounds__(256) void qh_kernel(
    const float* __restrict__ query, const float* __restrict__ w,
    const float* __restrict__ bq, float* __restrict__ qh)
{
    int v = blockIdx.x;
    int t = threadIdx.x;
    for (int d = t; d < C_; d += 256) {
        const float* wr = w + (long)v * (3 * C_) * C_ + (long)d * C_;
        float acc = 0.0f;
        #pragma unroll 4
        for (int c = 0; c < C_; c++) acc += query[c] * wr[c];
        qh[v * C_ + d] = acc + bq[(long)v * (3 * C_) + d];
    }
}

// ---------------- cross attention (single query) ----------------
__global__ __launch_bounds__(256) void cross_attn_kernel(
    const float* __restrict__ kv, const float* __restrict__ qh,
    float* __restrict__ c2)
{
    int h = blockIdx.x, b = blockIdx.y, v = blockIdx.z;
    int t = threadIdx.x;

    __shared__ float p[256];
    __shared__ float red[256];
    __shared__ float part[4][64];

    const float* kvb = kv + ((long)(v * B_ + b) * N_) * (2 * C_);
    const float* qhp = qh + v * C_ + h * HD_;
    const float* krow = kvb + (long)t * (2 * C_) + h * HD_;

    float s = 0.0f;
    #pragma unroll
    for (int e = 0; e < 64; e++) s += qhp[e] * krow[e];
    s *= 0.125f;

    red[t] = s; __syncthreads();
    for (int off = 128; off > 0; off >>= 1) {
        if (t < off) red[t] = fmaxf(red[t], red[t + off]);
        __syncthreads();
    }
    float mx = red[0];
    __syncthreads();

    float e_ = __expf(s - mx);
    p[t] = e_; red[t] = e_;
    __syncthreads();
    for (int off = 128; off > 0; off >>= 1) {
        if (t < off) red[t] += red[t + off];
        __syncthreads();
    }
    float inv = 1.0f / red[0];
    __syncthreads();

    int e = t & 63, pid = t >> 6;
    float acc = 0.0f;
    for (int n = pid * 64; n < pid * 64 + 64; n++)
        acc += p[n] * kvb[(long)n * (2 * C_) + C_ + h * HD_ + e];
    part[pid][e] = acc;
    __syncthreads();
    if (t < 64) {
        float r = (part[0][t] + part[1][t]) + (part[2][t] + part[3][t]);
        c2[(long)(v * B_ + b) * C_ + h * HD_ + t] = r * inv;
    }
}

// ---------------- output projection + broadcast over N ----------------
__global__ __launch_bounds__(256) void out_kernel(
    const float* __restrict__ c2, const float* __restrict__ w,
    const float* __restrict__ bias, float* __restrict__ out)
{
    int v = blockIdx.x, b = blockIdx.y;
    int t = threadIdx.x;

    __shared__ float sc[C_];
    for (int c = t; c < C_; c += 256) sc[c] = c2[(long)(v * B_ + b) * C_ + c];
    __syncthreads();

    float o[3];
    #pragma unroll
    for (int r = 0; r < 3; r++) {
        int co = t + r * 256;
        const float* wr = w + (long)v * C_ * C_ + (long)co * C_;
        float d0 = 0.f, d1 = 0.f, d2 = 0.f, d3 = 0.f;
        #pragma unroll 4
        for (int c = 0; c < C_; c += 4) {
            d0 += sc[c + 0] * wr[c + 0];
            d1 += sc[c + 1] * wr[c + 1];
            d2 += sc[c + 2] * wr[c + 2];
            d3 += sc[c + 3] * wr[c + 3];
        }
        o[r] = ((d0 + d1) + (d2 + d3)) + bias[v * C_ + co];
    }
    for (int n = 0; n < N_; n++) {
        long base = ((long)b * N_ + n) * (NVW * C_) + (long)v * C_;
        #pragma unroll
        for (int r = 0; r < 3; r++) out[base + t + r * 256] = o[r];
    }
}

// ---------------- launch ----------------
extern "C" void kernel_launch(void* const* d_in, const int* in_sizes, int n_in,
                              void* d_out, int out_size)
{
    const float* X        = (const float*)d_in[0];
    const float* norm1_g  = (const float*)d_in[1];
    const float* norm1_b  = (const float*)d_in[2];
    const float* qkv_w    = (const float*)d_in[3];
    const float* proj_w   = (const float*)d_in[4];
    const float* proj_b   = (const float*)d_in[5];
    const float* norm2_g  = (const float*)d_in[6];
    const float* norm2_b  = (const float*)d_in[7];
    const float* fc1_w    = (const float*)d_in[8];
    const float* fc1_b    = (const float*)d_in[9];
    const float* fc2_w    = (const float*)d_in[10];
    const float* fc2_b    = (const float*)d_in[11];
    const float* query    = (const float*)d_in[12];
    const float* mha_in_w = (const float*)d_in[13];
    const float* mha_in_b = (const float*)d_in[14];
    const float* mha_out_w= (const float*)d_in[15];
    const float* mha_out_b= (const float*)d_in[16];
    float* out = (float*)d_out;

    float *x, *kv, *qh, *c2;
    __nv_bfloat16 *qkvH, *qkvL;
    __half *XnF, *ctxF, *hnF, *h1F, *x2F;
    __half *WqkvH, *WqkvL, *WprjH, *WprjL, *Wf1H, *Wf1L, *Wf2H, *Wf2L, *WmhaH, *WmhaL;
    cudaGetSymbolAddress((void**)&x,    g_x);
    cudaGetSymbolAddress((void**)&kv,   g_kv);
    cudaGetSymbolAddress((void**)&qh,   g_qh);
    cudaGetSymbolAddress((void**)&c2,   g_c2);
    cudaGetSymbolAddress((void**)&qkvH, g_qkvH); cudaGetSymbolAddress((void**)&qkvL, g_qkvL);
    cudaGetSymbolAddress((void**)&XnF,  g_XnF);
    cudaGetSymbolAddress((void**)&ctxF, g_ctxF);
    cudaGetSymbolAddress((void**)&hnF,  g_hnF);
    cudaGetSymbolAddress((void**)&h1F,  g_h1F);
    cudaGetSymbolAddress((void**)&x2F,  g_x2F);
    cudaGetSymbolAddress((void**)&WqkvH, g_WqkvH); cudaGetSymbolAddress((void**)&WqkvL, g_WqkvL);
    cudaGetSymbolAddress((void**)&WprjH, g_WprjH); cudaGetSymbolAddress((void**)&WprjL, g_WprjL);
    cudaGetSymbolAddress((void**)&Wf1H,  g_Wf1H);  cudaGetSymbolAddress((void**)&Wf1L,  g_Wf1L);
    cudaGetSymbolAddress((void**)&Wf2H,  g_Wf2H);  cudaGetSymbolAddress((void**)&Wf2L,  g_Wf2L);
    cudaGetSymbolAddress((void**)&WmhaH, g_WmhaH); cudaGetSymbolAddress((void**)&WmhaL, g_WmhaL);

    cudaFuncSetAttribute(gemm_mma, cudaFuncAttributeMaxDynamicSharedMemorySize,
                         GEMM_SMEM);
    cudaFuncSetAttribute(attn_mma, cudaFuncAttributeMaxDynamicSharedMemorySize,
                         ATTN_SMEM);

    const long MC  = (long)MROWS * C_;
    const long MH  = (long)MROWS * HID_;

    auto wsplit = [&](const float* src, __half* hi, __half* lo, long n) {
        int n4 = (int)(n / 4);
        wsplit_kernel<<<(n4 + 255) / 256, 256>>>(src, hi, lo, n4);
    };

    // 0. split all weights into fp16 hi/lo planes
    wsplit(qkv_w,    WqkvH, WqkvL, (long)NVW * 3 * C_ * C_);
    wsplit(proj_w,   WprjH, WprjL, (long)NVW * C_ * C_);
    wsplit(fc1_w,    Wf1H,  Wf1L,  (long)NVW * HID_ * C_);
    wsplit(fc2_w,    Wf2H,  Wf2L,  (long)NVW * C_ * HID_);
    wsplit(mha_in_w, WmhaH, WmhaL, (long)NVW * 3 * C_ * C_);

    // 1. LN1 -> Xn fp16 (remap [b*NV+v] -> [v][b])
    ln_kernel<<<NVW * B_ * N_, 256>>>(X, norm1_g, norm1_b, XnF, 1, 0);

    // 2. QKV GEMM -> bf16 hi/lo qkv planes (for 3-term attention)
    gemm_mma<<<dim3(3 * C_ / 128, MROWS / 128, NVW), 256, GEMM_SMEM>>>(
        XnF, WqkvH, WqkvL, nullptr, nullptr, nullptr, qkvH, qkvL, nullptr,
        C_, 3 * C_, MC, (long)3 * C_ * C_, 0, 0, (long)MROWS * 3 * C_, 1.0f, 0);

    // 3. MMA flash attention, mean over j -> ctx fp16
    attn_mma<<<dim3(H_, B_, NVW), 256, ATTN_SMEM>>>(qkvH, qkvL, ctxF);

    // 4. proj GEMM (alpha=2 folds residual doubling) -> f32 x
    gemm_mma<<<dim3(C_ / 128, MROWS / 128, NVW), 256, GEMM_SMEM>>>(
        ctxF, WprjH, WprjL, proj_b, nullptr, x, nullptr, nullptr, nullptr,
        C_, C_, MC, (long)C_ * C_, C_, 0, MC, 2.0f, 0);

    // 5. LN2 -> hn fp16
    ln_kernel<<<NVW * B_ * N_, 256>>>(x, norm2_g, norm2_b, hnF, 0, 1);

    // 6. fc1 GEMM + bias + GELU -> h1 fp16
    gemm_mma<<<dim3(HID_ / 128, MROWS / 128, NVW), 256, GEMM_SMEM>>>(
        hnF, Wf1H, Wf1L, fc1_b, nullptr, nullptr, nullptr, nullptr, h1F,
        C_, HID_, MC, (long)HID_ * C_, HID_, 0, MH, 1.0f, 1);

    // 7. fc2 GEMM + bias + residual(x) -> x2 fp16
    gemm_mma<<<dim3(C_ / 128, MROWS / 128, NVW), 256, GEMM_SMEM>>>(
        h1F, Wf2H, Wf2L, fc2_b, x, nullptr, nullptr, nullptr, x2F,
        HID_, C_, MH, (long)C_ * HID_, C_, MC, MC, 1.0f, 0);

    // 8. learnable query projection (f32 weights)
    qh_kernel<<<NVW, 256>>>(query, mha_in_w, mha_in_b, qh);

    // 9. K/V projection of x2 -> f32 kv (W rows [C,3C) of mha_in_w)
    gemm_mma<<<dim3(2 * C_ / 128, MROWS / 128, NVW), 256, GEMM_SMEM>>>(
        x2F, WmhaH + (long)C_ * C_, WmhaL + (long)C_ * C_,
        mha_in_b + C_, nullptr, kv, nullptr, nullptr, nullptr,
        C_, 2 * C_, MC, (long)3 * C_ * C_, (long)3 * C_, 0,
        (long)MROWS * 2 * C_, 1.0f, 0);

    // 10. single-query cross attention -> c2[v][b][C]
    cross_attn_kernel<<<dim3(H_, B_, NVW), 256>>>(kv, qh, c2);

    // 11. output projection + broadcast over N
    out_kernel<<<dim3(NVW, B_), 256>>>(c2, mha_out_w, mha_out_b, out);
}

// round 16
// speedup vs baseline: 4.4082x; 1.1469x over previous
#include <cuda_runtime.h>
#include <cuda_bf16.h>
#include <cuda_fp16.h>
#include <math.h>
#include <stdint.h>

#define NVW 4
#define B_ 4
#define N_ 256
#define C_ 768
#define H_ 12
#define HD_ 64
#define HID_ 3072
#define MROWS (B_*N_)   // 1024 rows per view

// ---------------- scratch (device globals; no allocation) ----------------
__device__ float g_x  [NVW*MROWS*C_];
__device__ float g_kv [NVW*MROWS*2*C_];
__device__ float g_qh [NVW*C_];
__device__ float g_c2 [NVW*B_*C_];
// bf16 hi/lo qkv planes (consumed by 3-term attention)
__device__ __nv_bfloat16 g_qkvH[NVW*MROWS*3*C_], g_qkvL[NVW*MROWS*3*C_];
// fp16 single-plane activations
__device__ __half g_XnF [NVW*MROWS*C_];
__device__ __half g_ctxF[NVW*MROWS*C_];
__device__ __half g_hnF [NVW*MROWS*C_];
__device__ __half g_h1F [NVW*MROWS*HID_];
__device__ __half g_x2F [NVW*MROWS*C_];
// fp16 single-plane weights
__device__ __half g_Wqkv[NVW*3*C_*C_];
__device__ __half g_Wprj[NVW*C_*C_];
__device__ __half g_Wf1 [NVW*HID_*C_];
__device__ __half g_Wf2 [NVW*C_*HID_];
__device__ __half g_Wmha[NVW*3*C_*C_];

__device__ __forceinline__ float gelu_exact(float x) {
    return 0.5f * x * (1.0f + erff(x * 0.70710678118654752f));
}

__device__ __forceinline__ void bfsplit(float x, __nv_bfloat16& h, __nv_bfloat16& l) {
    h = __float2bfloat16(x);
    l = __float2bfloat16(x - __bfloat162float(h));
}

__device__ __forceinline__ uint32_t bfpack(float a, float b) {
    __nv_bfloat16 ha = __float2bfloat16(a);
    __nv_bfloat16 hb = __float2bfloat16(b);
    uint16_t ua = *(uint16_t*)&ha, ub = *(uint16_t*)&hb;
    return ((uint32_t)ub << 16) | ua;
}

__device__ __forceinline__ uint32_t smem_u32(const void* p) {
    uint32_t a;
    asm("{ .reg .u64 t; cvta.to.shared.u64 t, %1; cvt.u32.u64 %0, t; }"
        : "=r"(a) : "l"(p));
    return a;
}

#define CP_ASYNC16(dst, src) \
    asm volatile("cp.async.ca.shared.global [%0], [%1], 16;" \
                 :: "r"(dst), "l"(src) : "memory")
#define CP_COMMIT() \
    asm volatile("cp.async.commit_group;" ::: "memory")
#define CP_WAIT1() \
    asm volatile("cp.async.wait_group 1;" ::: "memory")
#define CP_WAIT0() \
    asm volatile("cp.async.wait_group 0;" ::: "memory")

#define MMA_BF16(d, a, b) \
    asm volatile( \
        "mma.sync.aligned.m16n8k16.row.col.f32.bf16.bf16.f32 " \
        "{%0,%1,%2,%3}, {%4,%5,%6,%7}, {%8,%9}, {%0,%1,%2,%3};" \
        : "+f"((d)[0]), "+f"((d)[1]), "+f"((d)[2]), "+f"((d)[3]) \
        : "r"((a)[0]), "r"((a)[1]), "r"((a)[2]), "r"((a)[3]), \
          "r"((b)[0]), "r"((b)[1]))

#define MMA_F16(d, a, b) \
    asm volatile( \
        "mma.sync.aligned.m16n8k16.row.col.f32.f16.f16.f32 " \
        "{%0,%1,%2,%3}, {%4,%5,%6,%7}, {%8,%9}, {%0,%1,%2,%3};" \
        : "+f"((d)[0]), "+f"((d)[1]), "+f"((d)[2]), "+f"((d)[3]) \
        : "r"((a)[0]), "r"((a)[1]), "r"((a)[2]), "r"((a)[3]), \
          "r"((b)[0]), "r"((b)[1]))

#define LDSM_X4(r0, r1, r2, r3, addr) \
    asm volatile("ldmatrix.sync.aligned.m8n8.x4.shared.b16 {%0,%1,%2,%3}, [%4];" \
        : "=r"(r0), "=r"(r1), "=r"(r2), "=r"(r3) : "r"(addr))

// ---------------- weight convert kernel (f32 -> fp16) ----------------
__global__ __launch_bounds__(256) void wconv_kernel(
    const float* __restrict__ src, __half* __restrict__ dst, int n4)
{
    int i = blockIdx.x * 256 + threadIdx.x;
    if (i >= n4) return;
    float4 s = ((const float4*)src)[i];
    __half2* Dp = (__half2*)dst;
    Dp[2*i]   = __floats2half2_rn(s.x, s.y);
    Dp[2*i+1] = __floats2half2_rn(s.z, s.w);
}

// ---------------- LayerNorm -> fp16 single plane ----------------
__global__ __launch_bounds__(256) void ln_kernel(
    const float* __restrict__ X, const float* __restrict__ g,
    const float* __restrict__ be, __half* __restrict__ Y,
    int remap, int pervw)
{
    int r = blockIdx.x;
    int v = r / (B_ * N_);
    long inrow;
    if (remap) {
        int rem = r % (B_ * N_);
        int bb = rem / N_;
        int n  = rem % N_;
        inrow = ((long)(bb * NVW + v) * N_ + n);
    } else {
        inrow = r;
    }
    const float* x = X + inrow * C_;
    long obase = (long)r * C_;
    const float* gg = g  + (pervw ? v * C_ : 0);
    const float* bb2 = be + (pervw ? v * C_ : 0);

    int t = threadIdx.x;
    float v0 = x[t], v1 = x[t + 256], v2 = x[t + 512];
    float s  = v0 + v1 + v2;
    float sq = v0 * v0 + v1 * v1 + v2 * v2;

    __shared__ float rs[256], rq[256];
    rs[t] = s; rq[t] = sq;
    __syncthreads();
    for (int off = 128; off > 0; off >>= 1) {
        if (t < off) { rs[t] += rs[t + off]; rq[t] += rq[t + off]; }
        __syncthreads();
    }
    float mean = rs[0] * (1.0f / C_);
    float var  = rq[0] * (1.0f / C_) - mean * mean;
    float rstd = rsqrtf(var + 1e-6f);

    #pragma unroll
    for (int rr = 0; rr < 3; rr++) {
        int c = t + rr * 256;
        float val = (rr == 0 ? v0 : (rr == 1 ? v1 : v2));
        float y = (val - mean) * rstd * gg[c] + bb2[c];
        Y[obase + c] = __float2half(y);
    }
}

// ---------------- 1-term FP16 mma.sync batched NT GEMM (ldmatrix) --------
// D = A*W, both single fp16 planes. CTA 128x128, 256 threads, 8 warps,
// warp tile 64x32, K-chunk 32, 3-stage cp.async, 2 CTAs/SM, ldmatrix frags.
#define KC 32
#define RSU 20
#define TILE_U (128 * RSU)                   // 2560 u32
#define NSTAGE 3
#define GEMM_SMEM (NSTAGE * 2 * TILE_U * 4)  // 61440 bytes

__global__ void __launch_bounds__(256, 2)
gemm_mma(const __half* __restrict__ A, const __half* __restrict__ W,
         const float* __restrict__ bias, const float* __restrict__ res,
         float* __restrict__ Cf,
         __nv_bfloat16* __restrict__ CH, __nv_bfloat16* __restrict__ CL,
         __half* __restrict__ Ch,
         int Kdim, int D,
         long sA, long sW, long sB, long sR, long sC, float alpha, int act)
{
    extern __shared__ uint32_t smu[];
    const int v = blockIdx.z;
    const int bm = blockIdx.y * 128, bn = blockIdx.x * 128;

    const int t = threadIdx.x, lane = t & 31, wid = t >> 5;
    const int wm = (wid >> 2) * 64;
    const int wn = (wid & 3) * 32;
    const int fr = lane >> 2;
    const int fk = lane & 3;

    // cp.async: 4 tasks/thread. lin = s*256+t; tile = lin>>9 (0=A,1=W);
    // row = (lin>>2)&127; seg = lin&3
    const char* gptr[4];
    uint32_t soff[4];
    #pragma unroll
    for (int s = 0; s < 4; s++) {
        int lin = s * 256 + t;
        int tile = lin >> 9;
        int row = (lin >> 2) & 127;
        int seg = lin & 3;
        const __half* base = tile
            ? (W + (long)v * sW + (long)(bn + row) * Kdim)
            : (A + (long)v * sA + (long)(bm + row) * Kdim);
        gptr[s] = (const char*)base + seg * 16;
        soff[s] = (uint32_t)((tile * TILE_U + row * RSU) * 4 + seg * 16);
    }
    const uint32_t sbase = smem_u32(smu);

    // ldmatrix per-lane base addresses (bytes, within a stage)
    uint32_t aBase[4];
    {
        int rowA = wm + (lane & 15);
        int kh = (lane >> 4) & 1;
        #pragma unroll
        for (int mt = 0; mt < 4; mt++)
            aBase[mt] = (uint32_t)(((rowA + mt * 16) * RSU + kh * 4) * 4);
    }
    uint32_t wBase[2];
    {
        int g = lane >> 3;
        int rowW = wn + ((g >> 1) * 8) + (lane & 7);
        int kh = g & 1;
        #pragma unroll
        for (int q = 0; q < 2; q++)
            wBase[q] = (uint32_t)(((rowW + q * 16) * RSU + kh * 4) * 4);
    }

    float acc[4][4][4];
    #pragma unroll
    for (int a = 0; a < 4; a++)
        #pragma unroll
        for (int b = 0; b < 4; b++)
            #pragma unroll
            for (int c = 0; c < 4; c++) acc[a][b][c] = 0.0f;

    const int steps = Kdim / KC;

    #pragma unroll
    for (int p = 0; p < 2; p++) {
        if (p < steps) {
            uint32_t st = sbase + (uint32_t)((p % NSTAGE) * 2 * TILE_U * 4);
            #pragma unroll
            for (int s = 0; s < 4; s++)
                CP_ASYNC16(st + soff[s], gptr[s] + p * 64);
        }
        CP_COMMIT();
    }

    for (int c = 0; c < steps; c++) {
        CP_WAIT1();
        __syncthreads();

        int p = c + 2;
        if (p < steps) {
            uint32_t st = sbase + (uint32_t)((p % NSTAGE) * 2 * TILE_U * 4);
            #pragma unroll
            for (int s = 0; s < 4; s++)
                CP_ASYNC16(st + soff[s], gptr[s] + p * 64);
        }
        CP_COMMIT();

        uint32_t stg = sbase + (uint32_t)((c % NSTAGE) * 2 * TILE_U * 4);
        uint32_t wOff = stg + (uint32_t)(TILE_U * 4);

        #pragma unroll
        for (int s = 0; s < 2; s++) {
            uint32_t ks = (uint32_t)(s * 32);
            uint32_t ah[4][4], bh[4][2];
            #pragma unroll
            for (int mt = 0; mt < 4; mt++)
                LDSM_X4(ah[mt][0], ah[mt][1], ah[mt][2], ah[mt][3],
                        stg + aBase[mt] + ks);
            #pragma unroll
            for (int q = 0; q < 2; q++)
                LDSM_X4(bh[2*q][0], bh[2*q][1], bh[2*q+1][0], bh[2*q+1][1],
                        wOff + wBase[q] + ks);
            #pragma unroll
            for (int mt = 0; mt < 4; mt++)
                #pragma unroll
                for (int nt = 0; nt < 4; nt++)
                    MMA_F16(acc[mt][nt], ah[mt], bh[nt]);
        }
    }

    __syncthreads();

    #pragma unroll
    for (int mt = 0; mt < 4; mt++) {
        #pragma unroll
        for (int nt = 0; nt < 4; nt++) {
            int row = bm + wm + mt * 16 + fr;
            int col = bn + wn + nt * 8 + 2 * fk;
            float b0 = 0.f, b1 = 0.f;
            if (bias) {
                b0 = bias[(long)v * sB + col];
                b1 = bias[(long)v * sB + col + 1];
            }
            #pragma unroll
            for (int half = 0; half < 2; half++) {
                int r = row + half * 8;
                float v0 = alpha * (acc[mt][nt][half * 2 + 0] + b0);
                float v1 = alpha * (acc[mt][nt][half * 2 + 1] + b1);
                if (act == 1) { v0 = gelu_exact(v0); v1 = gelu_exact(v1); }
                if (res) {
                    v0 += res[(long)v * sR + (long)r * D + col];
                    v1 += res[(long)v * sR + (long)r * D + col + 1];
                }
                long off = (long)v * sC + (long)r * D + col;
                if (Cf) {
                    float2 o2 = {v0, v1};
                    *(float2*)&Cf[off] = o2;
                } else if (CH) {
                    __nv_bfloat16 h0, h1, l0, l1;
                    bfsplit(v0, h0, l0);
                    bfsplit(v1, h1, l1);
                    *(__nv_bfloat162*)&CH[off] = __nv_bfloat162{h0, h1};
                    *(__nv_bfloat162*)&CL[off] = __nv_bfloat162{l0, l1};
                } else {
                    *(__half2*)&Ch[off] = __floats2half2_rn(v0, v1);
                }
            }
        }
    }
}

// ---------------- MMA flash attention (3-term bf16), mean over j ----------
#define ATTN_SMEM (32256 * 4)

__global__ void __launch_bounds__(256, 1)
attn_mma(const __nv_bfloat16* __restrict__ qkvH,
         const __nv_bfloat16* __restrict__ qkvL,
         __half* __restrict__ ctxF)
{
    const int h = blockIdx.x, b = blockIdx.y, iv = blockIdx.z;
    const int t = threadIdx.x, lane = t & 31, wid = t >> 5;
    const int fr = lane >> 2, fk = lane & 3;
    const int wm = wid * 32;
    const int D3 = 3 * C_;

    extern __shared__ uint32_t sa[];
    uint32_t* Qs[2] = { sa,          sa + 9216 };
    uint32_t* Ks[2] = { sa + 18432,  sa + 20736 };
    uint32_t* VT[2] = { sa + 23040,  sa + 25344 };
    uint32_t* VR[2] = { sa + 27648,  sa + 29952 };
    const uint32_t sb = smem_u32(sa);

    const long rowQ = (long)(iv * B_ + b) * N_;

    #pragma unroll
    for (int p = 0; p < 2; p++) {
        const __nv_bfloat16* src = (p ? qkvL : qkvH) + rowQ * D3 + h * HD_;
        uint32_t dstb = sb + (uint32_t)(p ? 9216 * 4 : 0);
        #pragma unroll
        for (int i = 0; i < 8; i++) {
            int lin = i * 256 + t;
            int row = lin >> 3, seg = lin & 7;
            CP_ASYNC16(dstb + row * 144 + seg * 16,
                       (const char*)(src + (long)row * D3) + seg * 16);
        }
    }
    CP_COMMIT();

    float outacc[2][8][4];
    #pragma unroll
    for (int a = 0; a < 2; a++)
        #pragma unroll
        for (int n = 0; n < 8; n++)
            #pragma unroll
            for (int q = 0; q < 4; q++) outacc[a][n][q] = 0.f;

    for (int j = 0; j < NVW; j++) {
        const long rowK = (long)(j * B_ + b) * N_;
        float m_[2][2] = {{-1e30f, -1e30f}, {-1e30f, -1e30f}};
        float l_[2][2] = {{0.f, 0.f}, {0.f, 0.f}};
        float cacc[2][8][4];
        #pragma unroll
        for (int a = 0; a < 2; a++)
            #pragma unroll
            for (int n = 0; n < 8; n++)
                #pragma unroll
                for (int q = 0; q < 4; q++) cacc[a][n][q] = 0.f;

        for (int kc = 0; kc < 4; kc++) {
            __syncthreads();
            #pragma unroll
            for (int p = 0; p < 2; p++) {
                const __nv_bfloat16* gk = (p ? qkvL : qkvH)
                    + (rowK + kc * 64) * D3 + C_ + h * HD_;
                const __nv_bfloat16* gv = (p ? qkvL : qkvH)
                    + (rowK + kc * 64) * D3 + 2 * C_ + h * HD_;
                uint32_t kb = sb + (uint32_t)((18432 + p * 2304) * 4);
                uint32_t vb = sb + (uint32_t)((27648 + p * 2304) * 4);
                #pragma unroll
                for (int i = 0; i < 2; i++) {
                    int lin = i * 256 + t;
                    int row = lin >> 3, seg = lin & 7;
                    CP_ASYNC16(kb + row * 144 + seg * 16,
                               (const char*)(gk + (long)row * D3) + seg * 16);
                    CP_ASYNC16(vb + row * 144 + seg * 16,
                               (const char*)(gv + (long)row * D3) + seg * 16);
                }
            }
            CP_COMMIT();
            CP_WAIT0();
            __syncthreads();

            #pragma unroll
            for (int p = 0; p < 2; p++) {
                const uint32_t* R = VR[p];
                uint32_t* T = VT[p];
                #pragma unroll
                for (int i = 0; i < 4; i++) {
                    int lin = i * 256 + t;
                    int kp = lin >> 5, cp = lin & 31;
                    uint32_t r0 = R[(2 * kp) * 36 + cp];
                    uint32_t r1 = R[(2 * kp + 1) * 36 + cp];
                    T[(2 * cp) * 36 + kp]     = (r0 & 0xffffu) | (r1 << 16);
                    T[(2 * cp + 1) * 36 + kp] = (r0 >> 16) | (r1 & 0xffff0000u);
                }
            }
            __syncthreads();

            float sacc[2][8][4];
            #pragma unroll
            for (int a = 0; a < 2; a++)
                #pragma unroll
                for (int n = 0; n < 8; n++)
                    #pragma unroll
                    for (int q = 0; q < 4; q++) sacc[a][n][q] = 0.f;

            #pragma unroll
            for (int kt = 0; kt < 4; kt++) {
                uint32_t qh_[2][4], ql_[2][4];
                #pragma unroll
                for (int mt = 0; mt < 2; mt++) {
                    int r0 = wm + mt * 16 + fr;
                    int i0 = r0 * 36 + kt * 8 + fk;
                    int i1 = (r0 + 8) * 36 + kt * 8 + fk;
                    qh_[mt][0] = Qs[0][i0];
                    qh_[mt][1] = Qs[0][i1];
                    qh_[mt][2] = Qs[0][i0 + 4];
                    qh_[mt][3] = Qs[0][i1 + 4];
                    ql_[mt][0] = Qs[1][i0];
                    ql_[mt][1] = Qs[1][i1];
                    ql_[mt][2] = Qs[1][i0 + 4];
                    ql_[mt][3] = Qs[1][i1 + 4];
                }
                #pragma unroll
                for (int nt = 0; nt < 8; nt++) {
                    int ib = (nt * 8 + fr) * 36 + kt * 8 + fk;
                    uint32_t kh_[2] = { Ks[0][ib], Ks[0][ib + 4] };
                    uint32_t kl_[2] = { Ks[1][ib], Ks[1][ib + 4] };
                    #pragma unroll
                    for (int mt = 0; mt < 2; mt++) {
                        MMA_BF16(sacc[mt][nt], qh_[mt], kh_);
                        MMA_BF16(sacc[mt][nt], qh_[mt], kl_);
                        MMA_BF16(sacc[mt][nt], ql_[mt], kh_);
                    }
                }
            }
            #pragma unroll
            for (int a = 0; a < 2; a++)
                #pragma unroll
                for (int n = 0; n < 8; n++)
                    #pragma unroll
                    for (int q = 0; q < 4; q++) sacc[a][n][q] *= 0.125f;

            #pragma unroll
            for (int mt = 0; mt < 2; mt++) {
                #pragma unroll
                for (int hf = 0; hf < 2; hf++) {
                    float cm = -1e30f;
                    #pragma unroll
                    for (int nt = 0; nt < 8; nt++)
                        cm = fmaxf(cm, fmaxf(sacc[mt][nt][hf*2], sacc[mt][nt][hf*2+1]));
                    cm = fmaxf(cm, __shfl_xor_sync(0xffffffffu, cm, 1));
                    cm = fmaxf(cm, __shfl_xor_sync(0xffffffffu, cm, 2));
                    float mo = m_[mt][hf];
                    float mn = fmaxf(mo, cm);
                    float corr = __expf(mo - mn);
                    m_[mt][hf] = mn;
                    float ps = 0.f;
                    #pragma unroll
                    for (int nt = 0; nt < 8; nt++) {
                        float p0 = __expf(sacc[mt][nt][hf*2]   - mn);
                        float p1 = __expf(sacc[mt][nt][hf*2+1] - mn);
                        sacc[mt][nt][hf*2]   = p0;
                        sacc[mt][nt][hf*2+1] = p1;
                        ps += p0 + p1;
                    }
                    ps += __shfl_xor_sync(0xffffffffu, ps, 1);
                    ps += __shfl_xor_sync(0xffffffffu, ps, 2);
                    l_[mt][hf] = l_[mt][hf] * corr + ps;
                    #pragma unroll
                    for (int nt = 0; nt < 8; nt++) {
                        cacc[mt][nt][hf*2]   *= corr;
                        cacc[mt][nt][hf*2+1] *= corr;
                    }
                }
            }

            #pragma unroll
            for (int ktk = 0; ktk < 4; ktk++) {
                uint32_t ph_[2][4], pl_[2][4];
                #pragma unroll
                for (int mt = 0; mt < 2; mt++) {
                    #pragma unroll
                    for (int q = 0; q < 4; q++) {
                        int nt = 2 * ktk + (q >> 1);
                        int base = (q & 1) * 2;
                        float p0 = sacc[mt][nt][base];
                        float p1 = sacc[mt][nt][base + 1];
                        __nv_bfloat16 h0 = __float2bfloat16(p0);
                        __nv_bfloat16 h1 = __float2bfloat16(p1);
                        float r0 = p0 - __bfloat162float(h0);
                        float r1 = p1 - __bfloat162float(h1);
                        uint16_t u0 = *(uint16_t*)&h0, u1 = *(uint16_t*)&h1;
                        ph_[mt][q] = ((uint32_t)u1 << 16) | u0;
                        pl_[mt][q] = bfpack(r0, r1);
                    }
                }
                #pragma unroll
                for (int nc = 0; nc < 8; nc++) {
                    int ib = (nc * 8 + fr) * 36 + ktk * 8 + fk;
                    uint32_t vh_[2] = { VT[0][ib], VT[0][ib + 4] };
                    uint32_t vl_[2] = { VT[1][ib], VT[1][ib + 4] };
                    #pragma unroll
                    for (int mt = 0; mt < 2; mt++) {
                        MMA_BF16(cacc[mt][nc], ph_[mt], vh_);
                        MMA_BF16(cacc[mt][nc], ph_[mt], vl_);
                        MMA_BF16(cacc[mt][nc], pl_[mt], vh_);
                    }
                }
            }
        } // kc

        #pragma unroll
        for (int mt = 0; mt < 2; mt++)
            #pragma unroll
            for (int hf = 0; hf < 2; hf++) {
                float inv = 0.25f / l_[mt][hf];
                #pragma unroll
                for (int nt = 0; nt < 8; nt++) {
                    outacc[mt][nt][hf*2]   += cacc[mt][nt][hf*2]   * inv;
                    outacc[mt][nt][hf*2+1] += cacc[mt][nt][hf*2+1] * inv;
                }
            }
    } // j

    #pragma unroll
    for (int mt = 0; mt < 2; mt++) {
        #pragma unroll
        for (int hf = 0; hf < 2; hf++) {
            int row = wm + mt * 16 + fr + hf * 8;
            long obase = (rowQ + row) * C_ + h * HD_;
            #pragma unroll
            for (int nt = 0; nt < 8; nt++) {
                int col = nt * 8 + 2 * fk;
                *(__half2*)&ctxF[obase + col] =
                    __floats2half2_rn(outacc[mt][nt][hf*2], outacc[mt][nt][hf*2+1]);
            }
        }
    }
}

// ---------------- learnable-query projection ----------------
__global__ __launch_bounds__(256) void qh_kernel(
    const float* __restrict__ query, const float* __restrict__ w,
    const float* __restrict__ bq, float* __restrict__ qh)
{
    int v = blockIdx.x;
    int t = threadIdx.x;
    for (int d = t; d < C_; d += 256) {
        const float* wr = w + (long)v * (3 * C_) * C_ + (long)d * C_;
        float acc = 0.0f;
        #pragma unroll 4
        for (int c = 0; c < C_; c++) acc += query[c] * wr[c];
        qh[v * C_ + d] = acc + bq[(long)v * (3 * C_) + d];
    }
}

// ---------------- cross attention (single query) ----------------
__global__ __launch_bounds__(256) void cross_attn_kernel(
    const float* __restrict__ kv, const float* __restrict__ qh,
    float* __restrict__ c2)
{
    int h = blockIdx.x, b = blockIdx.y, v = blockIdx.z;
    int t = threadIdx.x;

    __shared__ float p[256];
    __shared__ float red[256];
    __shared__ float part[4][64];

    const float* kvb = kv + ((long)(v * B_ + b) * N_) * (2 * C_);
    const float* qhp = qh + v * C_ + h * HD_;
    const float* krow = kvb + (long)t * (2 * C_) + h * HD_;

    float s = 0.0f;
    #pragma unroll
    for (int e = 0; e < 64; e++) s += qhp[e] * krow[e];
    s *= 0.125f;

    red[t] = s; __syncthreads();
    for (int off = 128; off > 0; off >>= 1) {
        if (t < off) red[t] = fmaxf(red[t], red[t + off]);
        __syncthreads();
    }
    float mx = red[0];
    __syncthreads();

    float e_ = __expf(s - mx);
    p[t] = e_; red[t] = e_;
    __syncthreads();
    for (int off = 128; off > 0; off >>= 1) {
        if (t < off) red[t] += red[t + off];
        __syncthreads();
    }
    float inv = 1.0f / red[0];
    __syncthreads();

    int e = t & 63, pid = t >> 6;
    float acc = 0.0f;
    for (int n = pid * 64; n < pid * 64 + 64; n++)
        acc += p[n] * kvb[(long)n * (2 * C_) + C_ + h * HD_ + e];
    part[pid][e] = acc;
    __syncthreads();
    if (t < 64) {
        float r = (part[0][t] + part[1][t]) + (part[2][t] + part[3][t]);
        c2[(long)(v * B_ + b) * C_ + h * HD_ + t] = r * inv;
    }
}

// ---------------- output projection + broadcast over N ----------------
__global__ __launch_bounds__(256) void out_kernel(
    const float* __restrict__ c2, const float* __restrict__ w,
    const float* __restrict__ bias, float* __restrict__ out)
{
    int v = blockIdx.x, b = blockIdx.y;
    int t = threadIdx.x;

    __shared__ float sc[C_];
    for (int c = t; c < C_; c += 256) sc[c] = c2[(long)(v * B_ + b) * C_ + c];
    __syncthreads();

    float o[3];
    #pragma unroll
    for (int r = 0; r < 3; r++) {
        int co = t + r * 256;
        const float* wr = w + (long)v * C_ * C_ + (long)co * C_;
        float d0 = 0.f, d1 = 0.f, d2 = 0.f, d3 = 0.f;
        #pragma unroll 4
        for (int c = 0; c < C_; c += 4) {
            d0 += sc[c + 0] * wr[c + 0];
            d1 += sc[c + 1] * wr[c + 1];
            d2 += sc[c + 2] * wr[c + 2];
            d3 += sc[c + 3] * wr[c + 3];
        }
        o[r] = ((d0 + d1) + (d2 + d3)) + bias[v * C_ + co];
    }
    for (int n = 0; n < N_; n++) {
        long base = ((long)b * N_ + n) * (NVW * C_) + (long)v * C_;
        #pragma unroll
        for (int r = 0; r < 3; r++) out[base + t + r * 256] = o[r];
    }
}

// ---------------- launch ----------------
extern "C" void kernel_launch(void* const* d_in, const int* in_sizes, int n_in,
                              void* d_out, int out_size)
{
    const float* X        = (const float*)d_in[0];
    const float* norm1_g  = (const float*)d_in[1];
    const float* norm1_b  = (const float*)d_in[2];
    const float* qkv_w    = (const float*)d_in[3];
    const float* proj_w   = (const float*)d_in[4];
    const float* proj_b   = (const float*)d_in[5];
    const float* norm2_g  = (const float*)d_in[6];
    const float* norm2_b  = (const float*)d_in[7];
    const float* fc1_w    = (const float*)d_in[8];
    const float* fc1_b    = (const float*)d_in[9];
    const float* fc2_w    = (const float*)d_in[10];
    const float* fc2_b    = (const float*)d_in[11];
    const float* query    = (const float*)d_in[12];
    const float* mha_in_w = (const float*)d_in[13];
    const float* mha_in_b = (const float*)d_in[14];
    const float* mha_out_w= (const float*)d_in[15];
    const float* mha_out_b= (const float*)d_in[16];
    float* out = (float*)d_out;

    float *x, *kv, *qh, *c2;
    __nv_bfloat16 *qkvH, *qkvL;
    __half *XnF, *ctxF, *hnF, *h1F, *x2F;
    __half *Wqkv, *Wprj, *Wf1, *Wf2, *Wmha;
    cudaGetSymbolAddress((void**)&x,    g_x);
    cudaGetSymbolAddress((void**)&kv,   g_kv);
    cudaGetSymbolAddress((void**)&qh,   g_qh);
    cudaGetSymbolAddress((void**)&c2,   g_c2);
    cudaGetSymbolAddress((void**)&qkvH, g_qkvH); cudaGetSymbolAddress((void**)&qkvL, g_qkvL);
    cudaGetSymbolAddress((void**)&XnF,  g_XnF);
    cudaGetSymbolAddress((void**)&ctxF, g_ctxF);
    cudaGetSymbolAddress((void**)&hnF,  g_hnF);
    cudaGetSymbolAddress((void**)&h1F,  g_h1F);
    cudaGetSymbolAddress((void**)&x2F,  g_x2F);
    cudaGetSymbolAddress((void**)&Wqkv, g_Wqkv);
    cudaGetSymbolAddress((void**)&Wprj, g_Wprj);
    cudaGetSymbolAddress((void**)&Wf1,  g_Wf1);
    cudaGetSymbolAddress((void**)&Wf2,  g_Wf2);
    cudaGetSymbolAddress((void**)&Wmha, g_Wmha);

    cudaFuncSetAttribute(gemm_mma, cudaFuncAttributeMaxDynamicSharedMemorySize,
                         GEMM_SMEM);
    cudaFuncSetAttribute(attn_mma, cudaFuncAttributeMaxDynamicSharedMemorySize,
                         ATTN_SMEM);

    const long MC  = (long)MROWS * C_;
    const long MH  = (long)MROWS * HID_;

    auto wconv = [&](const float* src, __half* dst, long n) {
        int n4 = (int)(n / 4);
        wconv_kernel<<<(n4 + 255) / 256, 256>>>(src, dst, n4);
    };

    // 0. convert all weights to fp16
    wconv(qkv_w,    Wqkv, (long)NVW * 3 * C_ * C_);
    wconv(proj_w,   Wprj, (long)NVW * C_ * C_);
    wconv(fc1_w,    Wf1,  (long)NVW * HID_ * C_);
    wconv(fc2_w,    Wf2,  (long)NVW * C_ * HID_);
    wconv(mha_in_w, Wmha, (long)NVW * 3 * C_ * C_);

    // 1. LN1 -> Xn fp16 (remap [b*NV+v] -> [v][b])
    ln_kernel<<<NVW * B_ * N_, 256>>>(X, norm1_g, norm1_b, XnF, 1, 0);

    // 2. QKV GEMM -> bf16 hi/lo qkv planes (for 3-term attention)
    gemm_mma<<<dim3(3 * C_ / 128, MROWS / 128, NVW), 256, GEMM_SMEM>>>(
        XnF, Wqkv, nullptr, nullptr, nullptr, qkvH, qkvL, nullptr,
        C_, 3 * C_, MC, (long)3 * C_ * C_, 0, 0, (long)MROWS * 3 * C_, 1.0f, 0);

    // 3. MMA flash attention, mean over j -> ctx fp16
    attn_mma<<<dim3(H_, B_, NVW), 256, ATTN_SMEM>>>(qkvH, qkvL, ctxF);

    // 4. proj GEMM (alpha=2 folds residual doubling) -> f32 x
    gemm_mma<<<dim3(C_ / 128, MROWS / 128, NVW), 256, GEMM_SMEM>>>(
        ctxF, Wprj, proj_b, nullptr, x, nullptr, nullptr, nullptr,
        C_, C_, MC, (long)C_ * C_, C_, 0, MC, 2.0f, 0);

    // 5. LN2 -> hn fp16
    ln_kernel<<<NVW * B_ * N_, 256>>>(x, norm2_g, norm2_b, hnF, 0, 1);

    // 6. fc1 GEMM + bias + GELU -> h1 fp16
    gemm_mma<<<dim3(HID_ / 128, MROWS / 128, NVW), 256, GEMM_SMEM>>>(
        hnF, Wf1, fc1_b, nullptr, nullptr, nullptr, nullptr, h1F,
        C_, HID_, MC, (long)HID_ * C_, HID_, 0, MH, 1.0f, 1);

    // 7. fc2 GEMM + bias + residual(x) -> x2 fp16
    gemm_mma<<<dim3(C_ / 128, MROWS / 128, NVW), 256, GEMM_SMEM>>>(
        h1F, Wf2, fc2_b, x, nullptr, nullptr, nullptr, x2F,
        HID_, C_, MH, (long)C_ * HID_, C_, MC, MC, 1.0f, 0);

    // 8. learnable query projection (f32 weights)
    qh_kernel<<<NVW, 256>>>(query, mha_in_w, mha_in_b, qh);

    // 9. K/V projection of x2 -> f32 kv (W rows [C,3C) of mha_in_w)
    gemm_mma<<<dim3(2 * C_ / 128, MROWS / 128, NVW), 256, GEMM_SMEM>>>(
        x2F, Wmha + (long)C_ * C_,
        mha_in_b + C_, nullptr, kv, nullptr, nullptr, nullptr,
        C_, 2 * C_, MC, (long)3 * C_ * C_, (long)3 * C_, 0,
        (long)MROWS * 2 * C_, 1.0f, 0);

    // 10. single-query cross attention -> c2[v][b][C]
    cross_attn_kernel<<<dim3(H_, B_, NVW), 256>>>(kv, qh, c2);

    // 11. output projection + broadcast over N
    out_kernel<<<dim3(NVW, B_), 256>>>(c2, mha_out_w, mha_out_b, out);
}

// round 17
// speedup vs baseline: 6.8999x; 1.5652x over previous
#include <cuda_runtime.h>
#include <cuda_bf16.h>
#include <cuda_fp16.h>
#include <math.h>
#include <stdint.h>

#define NVW 4
#define B_ 4
#define N_ 256
#define C_ 768
#define H_ 12
#define HD_ 64
#define HID_ 3072
#define MROWS (B_*N_)   // 1024 rows per view

// ---------------- scratch (device globals; no allocation) ----------------
__device__ float g_x  [NVW*MROWS*C_];
__device__ float g_kv [NVW*MROWS*2*C_];
__device__ float g_qh [NVW*C_];
__device__ float g_c2 [NVW*B_*C_];
// fp16 single-plane activations
__device__ __half g_qkvF[NVW*MROWS*3*C_];
__device__ __half g_XnF [NVW*MROWS*C_];
__device__ __half g_ctxF[NVW*MROWS*C_];
__device__ __half g_hnF [NVW*MROWS*C_];
__device__ __half g_h1F [NVW*MROWS*HID_];
__device__ __half g_x2F [NVW*MROWS*C_];
// fp16 single-plane weights
__device__ __half g_Wqkv[NVW*3*C_*C_];
__device__ __half g_Wprj[NVW*C_*C_];
__device__ __half g_Wf1 [NVW*HID_*C_];
__device__ __half g_Wf2 [NVW*C_*HID_];
__device__ __half g_Wmha[NVW*3*C_*C_];

__device__ __forceinline__ float gelu_exact(float x) {
    return 0.5f * x * (1.0f + erff(x * 0.70710678118654752f));
}

__device__ __forceinline__ uint32_t smem_u32(const void* p) {
    uint32_t a;
    asm("{ .reg .u64 t; cvta.to.shared.u64 t, %1; cvt.u32.u64 %0, t; }"
        : "=r"(a) : "l"(p));
    return a;
}

__device__ __forceinline__ uint32_t hpack(float a, float b) {
    __half2 h = __floats2half2_rn(a, b);
    return *(uint32_t*)&h;
}

#define CP_ASYNC16(dst, src) \
    asm volatile("cp.async.ca.shared.global [%0], [%1], 16;" \
                 :: "r"(dst), "l"(src) : "memory")
#define CP_COMMIT() \
    asm volatile("cp.async.commit_group;" ::: "memory")
#define CP_WAIT1() \
    asm volatile("cp.async.wait_group 1;" ::: "memory")
#define CP_WAIT0() \
    asm volatile("cp.async.wait_group 0;" ::: "memory")

#define MMA_F16(d, a, b) \
    asm volatile( \
        "mma.sync.aligned.m16n8k16.row.col.f32.f16.f16.f32 " \
        "{%0,%1,%2,%3}, {%4,%5,%6,%7}, {%8,%9}, {%0,%1,%2,%3};" \
        : "+f"((d)[0]), "+f"((d)[1]), "+f"((d)[2]), "+f"((d)[3]) \
        : "r"((a)[0]), "r"((a)[1]), "r"((a)[2]), "r"((a)[3]), \
          "r"((b)[0]), "r"((b)[1]))

#define LDSM_X4(r0, r1, r2, r3, addr) \
    asm volatile("ldmatrix.sync.aligned.m8n8.x4.shared.b16 {%0,%1,%2,%3}, [%4];" \
        : "=r"(r0), "=r"(r1), "=r"(r2), "=r"(r3) : "r"(addr))

// ---------------- weight convert kernel (f32 -> fp16) ----------------
__global__ __launch_bounds__(256) void wconv_kernel(
    const float* __restrict__ src, __half* __restrict__ dst, int n4)
{
    int i = blockIdx.x * 256 + threadIdx.x;
    if (i >= n4) return;
    float4 s = ((const float4*)src)[i];
    __half2* Dp = (__half2*)dst;
    Dp[2*i]   = __floats2half2_rn(s.x, s.y);
    Dp[2*i+1] = __floats2half2_rn(s.z, s.w);
}

// ---------------- LayerNorm -> fp16 single plane ----------------
__global__ __launch_bounds__(256) void ln_kernel(
    const float* __restrict__ X, const float* __restrict__ g,
    const float* __restrict__ be, __half* __restrict__ Y,
    int remap, int pervw)
{
    int r = blockIdx.x;
    int v = r / (B_ * N_);
    long inrow;
    if (remap) {
        int rem = r % (B_ * N_);
        int bb = rem / N_;
        int n  = rem % N_;
        inrow = ((long)(bb * NVW + v) * N_ + n);
    } else {
        inrow = r;
    }
    const float* x = X + inrow * C_;
    long obase = (long)r * C_;
    const float* gg = g  + (pervw ? v * C_ : 0);
    const float* bb2 = be + (pervw ? v * C_ : 0);

    int t = threadIdx.x;
    float v0 = x[t], v1 = x[t + 256], v2 = x[t + 512];
    float s  = v0 + v1 + v2;
    float sq = v0 * v0 + v1 * v1 + v2 * v2;

    __shared__ float rs[256], rq[256];
    rs[t] = s; rq[t] = sq;
    __syncthreads();
    for (int off = 128; off > 0; off >>= 1) {
        if (t < off) { rs[t] += rs[t + off]; rq[t] += rq[t + off]; }
        __syncthreads();
    }
    float mean = rs[0] * (1.0f / C_);
    float var  = rq[0] * (1.0f / C_) - mean * mean;
    float rstd = rsqrtf(var + 1e-6f);

    #pragma unroll
    for (int rr = 0; rr < 3; rr++) {
        int c = t + rr * 256;
        float val = (rr == 0 ? v0 : (rr == 1 ? v1 : v2));
        float y = (val - mean) * rstd * gg[c] + bb2[c];
        Y[obase + c] = __float2half(y);
    }
}

// ---------------- 1-term FP16 mma.sync batched NT GEMM (ldmatrix) --------
#define KC 32
#define RSU 20
#define TILE_U (128 * RSU)                   // 2560 u32
#define NSTAGE 3
#define GEMM_SMEM (NSTAGE * 2 * TILE_U * 4)  // 61440 bytes

__global__ void __launch_bounds__(256, 2)
gemm_mma(const __half* __restrict__ A, const __half* __restrict__ W,
         const float* __restrict__ bias, const float* __restrict__ res,
         float* __restrict__ Cf, __half* __restrict__ Ch,
         int Kdim, int D,
         long sA, long sW, long sB, long sR, long sC, float alpha, int act)
{
    extern __shared__ uint32_t smu[];
    const int v = blockIdx.z;
    const int bm = blockIdx.y * 128, bn = blockIdx.x * 128;

    const int t = threadIdx.x, lane = t & 31, wid = t >> 5;
    const int wm = (wid >> 2) * 64;
    const int wn = (wid & 3) * 32;
    const int fr = lane >> 2;
    const int fk = lane & 3;

    const char* gptr[4];
    uint32_t soff[4];
    #pragma unroll
    for (int s = 0; s < 4; s++) {
        int lin = s * 256 + t;
        int tile = lin >> 9;
        int row = (lin >> 2) & 127;
        int seg = lin & 3;
        const __half* base = tile
            ? (W + (long)v * sW + (long)(bn + row) * Kdim)
            : (A + (long)v * sA + (long)(bm + row) * Kdim);
        gptr[s] = (const char*)base + seg * 16;
        soff[s] = (uint32_t)((tile * TILE_U + row * RSU) * 4 + seg * 16);
    }
    const uint32_t sbase = smem_u32(smu);

    uint32_t aBase[4];
    {
        int rowA = wm + (lane & 15);
        int kh = (lane >> 4) & 1;
        #pragma unroll
        for (int mt = 0; mt < 4; mt++)
            aBase[mt] = (uint32_t)(((rowA + mt * 16) * RSU + kh * 4) * 4);
    }
    uint32_t wBase[2];
    {
        int g = lane >> 3;
        int rowW = wn + ((g >> 1) * 8) + (lane & 7);
        int kh = g & 1;
        #pragma unroll
        for (int q = 0; q < 2; q++)
            wBase[q] = (uint32_t)(((rowW + q * 16) * RSU + kh * 4) * 4);
    }

    float acc[4][4][4];
    #pragma unroll
    for (int a = 0; a < 4; a++)
        #pragma unroll
        for (int b = 0; b < 4; b++)
            #pragma unroll
            for (int c = 0; c < 4; c++) acc[a][b][c] = 0.0f;

    const int steps = Kdim / KC;

    #pragma unroll
    for (int p = 0; p < 2; p++) {
        if (p < steps) {
            uint32_t st = sbase + (uint32_t)((p % NSTAGE) * 2 * TILE_U * 4);
            #pragma unroll
            for (int s = 0; s < 4; s++)
                CP_ASYNC16(st + soff[s], gptr[s] + p * 64);
        }
        CP_COMMIT();
    }

    for (int c = 0; c < steps; c++) {
        CP_WAIT1();
        __syncthreads();

        int p = c + 2;
        if (p < steps) {
            uint32_t st = sbase + (uint32_t)((p % NSTAGE) * 2 * TILE_U * 4);
            #pragma unroll
            for (int s = 0; s < 4; s++)
                CP_ASYNC16(st + soff[s], gptr[s] + p * 64);
        }
        CP_COMMIT();

        uint32_t stg = sbase + (uint32_t)((c % NSTAGE) * 2 * TILE_U * 4);
        uint32_t wOff = stg + (uint32_t)(TILE_U * 4);

        #pragma unroll
        for (int s = 0; s < 2; s++) {
            uint32_t ks = (uint32_t)(s * 32);
            uint32_t ah[4][4], bh[4][2];
            #pragma unroll
            for (int mt = 0; mt < 4; mt++)
                LDSM_X4(ah[mt][0], ah[mt][1], ah[mt][2], ah[mt][3],
                        stg + aBase[mt] + ks);
            #pragma unroll
            for (int q = 0; q < 2; q++)
                LDSM_X4(bh[2*q][0], bh[2*q][1], bh[2*q+1][0], bh[2*q+1][1],
                        wOff + wBase[q] + ks);
            #pragma unroll
            for (int mt = 0; mt < 4; mt++)
                #pragma unroll
                for (int nt = 0; nt < 4; nt++)
                    MMA_F16(acc[mt][nt], ah[mt], bh[nt]);
        }
    }

    __syncthreads();

    #pragma unroll
    for (int mt = 0; mt < 4; mt++) {
        #pragma unroll
        for (int nt = 0; nt < 4; nt++) {
            int row = bm + wm + mt * 16 + fr;
            int col = bn + wn + nt * 8 + 2 * fk;
            float b0 = 0.f, b1 = 0.f;
            if (bias) {
                b0 = bias[(long)v * sB + col];
                b1 = bias[(long)v * sB + col + 1];
            }
            #pragma unroll
            for (int half = 0; half < 2; half++) {
                int r = row + half * 8;
                float v0 = alpha * (acc[mt][nt][half * 2 + 0] + b0);
                float v1 = alpha * (acc[mt][nt][half * 2 + 1] + b1);
                if (act == 1) { v0 = gelu_exact(v0); v1 = gelu_exact(v1); }
                if (res) {
                    v0 += res[(long)v * sR + (long)r * D + col];
                    v1 += res[(long)v * sR + (long)r * D + col + 1];
                }
                long off = (long)v * sC + (long)r * D + col;
                if (Cf) {
                    float2 o2 = {v0, v1};
                    *(float2*)&Cf[off] = o2;
                } else {
                    *(__half2*)&Ch[off] = __floats2half2_rn(v0, v1);
                }
            }
        }
    }
}

// ---------------- MMA flash attention (1-term fp16), mean over j ----------
// smem (u32): Q 9216 | K 2304 | VT 2304 | VR 2304 = 16128 u32 = 64512 B
#define ATTN_SMEM (16128 * 4)

__global__ void __launch_bounds__(256, 1)
attn_mma(const __half* __restrict__ qkvF, __half* __restrict__ ctxF)
{
    const int h = blockIdx.x, b = blockIdx.y, iv = blockIdx.z;
    const int t = threadIdx.x, lane = t & 31, wid = t >> 5;
    const int fr = lane >> 2, fk = lane & 3;
    const int wm = wid * 32;
    const int D3 = 3 * C_;

    extern __shared__ uint32_t sa[];
    uint32_t* Qs = sa;
    uint32_t* Ks = sa + 9216;
    uint32_t* VT = sa + 11520;
    uint32_t* VR = sa + 13824;
    const uint32_t sb = smem_u32(sa);

    const long rowQ = (long)(iv * B_ + b) * N_;

    // stage Q (256 rows x 64 fp16 = 128B/row)
    {
        const __half* src = qkvF + rowQ * D3 + h * HD_;
        #pragma unroll
        for (int i = 0; i < 8; i++) {
            int lin = i * 256 + t;
            int row = lin >> 3, seg = lin & 7;
            CP_ASYNC16(sb + row * 144 + seg * 16,
                       (const char*)(src + (long)row * D3) + seg * 16);
        }
    }
    CP_COMMIT();

    float outacc[2][8][4];
    #pragma unroll
    for (int a = 0; a < 2; a++)
        #pragma unroll
        for (int n = 0; n < 8; n++)
            #pragma unroll
            for (int q = 0; q < 4; q++) outacc[a][n][q] = 0.f;

    for (int j = 0; j < NVW; j++) {
        const long rowK = (long)(j * B_ + b) * N_;
        float m_[2][2] = {{-1e30f, -1e30f}, {-1e30f, -1e30f}};
        float l_[2][2] = {{0.f, 0.f}, {0.f, 0.f}};
        float cacc[2][8][4];
        #pragma unroll
        for (int a = 0; a < 2; a++)
            #pragma unroll
            for (int n = 0; n < 8; n++)
                #pragma unroll
                for (int q = 0; q < 4; q++) cacc[a][n][q] = 0.f;

        for (int kc = 0; kc < 4; kc++) {
            __syncthreads();
            {
                const __half* gk = qkvF + (rowK + kc * 64) * D3 + C_ + h * HD_;
                const __half* gv = qkvF + (rowK + kc * 64) * D3 + 2 * C_ + h * HD_;
                uint32_t kb = sb + (uint32_t)(9216 * 4);
                uint32_t vb = sb + (uint32_t)(13824 * 4);
                #pragma unroll
                for (int i = 0; i < 2; i++) {
                    int lin = i * 256 + t;
                    int row = lin >> 3, seg = lin & 7;
                    CP_ASYNC16(kb + row * 144 + seg * 16,
                               (const char*)(gk + (long)row * D3) + seg * 16);
                    CP_ASYNC16(vb + row * 144 + seg * 16,
                               (const char*)(gv + (long)row * D3) + seg * 16);
                }
            }
            CP_COMMIT();
            CP_WAIT0();
            __syncthreads();

            // transpose VR [key][colpair] -> VT [col][keypair]
            #pragma unroll
            for (int i = 0; i < 4; i++) {
                int lin = i * 256 + t;
                int kp = lin >> 5, cp = lin & 31;
                uint32_t r0 = VR[(2 * kp) * 36 + cp];
                uint32_t r1 = VR[(2 * kp + 1) * 36 + cp];
                VT[(2 * cp) * 36 + kp]     = (r0 & 0xffffu) | (r1 << 16);
                VT[(2 * cp + 1) * 36 + kp] = (r0 >> 16) | (r1 & 0xffff0000u);
            }
            __syncthreads();

            // S = Q K^T (1-term fp16)
            float sacc[2][8][4];
            #pragma unroll
            for (int a = 0; a < 2; a++)
                #pragma unroll
                for (int n = 0; n < 8; n++)
                    #pragma unroll
                    for (int q = 0; q < 4; q++) sacc[a][n][q] = 0.f;

            #pragma unroll
            for (int kt = 0; kt < 4; kt++) {
                uint32_t qf[2][4];
                #pragma unroll
                for (int mt = 0; mt < 2; mt++) {
                    int r0 = wm + mt * 16 + fr;
                    int i0 = r0 * 36 + kt * 8 + fk;
                    int i1 = (r0 + 8) * 36 + kt * 8 + fk;
                    qf[mt][0] = Qs[i0];
                    qf[mt][1] = Qs[i1];
                    qf[mt][2] = Qs[i0 + 4];
                    qf[mt][3] = Qs[i1 + 4];
                }
                #pragma unroll
                for (int nt = 0; nt < 8; nt++) {
                    int ib = (nt * 8 + fr) * 36 + kt * 8 + fk;
                    uint32_t kf[2] = { Ks[ib], Ks[ib + 4] };
                    #pragma unroll
                    for (int mt = 0; mt < 2; mt++)
                        MMA_F16(sacc[mt][nt], qf[mt], kf);
                }
            }
            #pragma unroll
            for (int a = 0; a < 2; a++)
                #pragma unroll
                for (int n = 0; n < 8; n++)
                    #pragma unroll
                    for (int q = 0; q < 4; q++) sacc[a][n][q] *= 0.125f;

            // online softmax (rows spread across fk quad)
            #pragma unroll
            for (int mt = 0; mt < 2; mt++) {
                #pragma unroll
                for (int hf = 0; hf < 2; hf++) {
                    float cm = -1e30f;
                    #pragma unroll
                    for (int nt = 0; nt < 8; nt++)
                        cm = fmaxf(cm, fmaxf(sacc[mt][nt][hf*2], sacc[mt][nt][hf*2+1]));
                    cm = fmaxf(cm, __shfl_xor_sync(0xffffffffu, cm, 1));
                    cm = fmaxf(cm, __shfl_xor_sync(0xffffffffu, cm, 2));
                    float mo = m_[mt][hf];
                    float mn = fmaxf(mo, cm);
                    float corr = __expf(mo - mn);
                    m_[mt][hf] = mn;
                    float ps = 0.f;
                    #pragma unroll
                    for (int nt = 0; nt < 8; nt++) {
                        float p0 = __expf(sacc[mt][nt][hf*2]   - mn);
                        float p1 = __expf(sacc[mt][nt][hf*2+1] - mn);
                        sacc[mt][nt][hf*2]   = p0;
                        sacc[mt][nt][hf*2+1] = p1;
                        ps += p0 + p1;
                    }
                    ps += __shfl_xor_sync(0xffffffffu, ps, 1);
                    ps += __shfl_xor_sync(0xffffffffu, ps, 2);
                    l_[mt][hf] = l_[mt][hf] * corr + ps;
                    #pragma unroll
                    for (int nt = 0; nt < 8; nt++) {
                        cacc[mt][nt][hf*2]   *= corr;
                        cacc[mt][nt][hf*2+1] *= corr;
                    }
                }
            }

            // ctx += P V (1-term fp16; P frags from sacc registers)
            #pragma unroll
            for (int ktk = 0; ktk < 4; ktk++) {
                uint32_t ph_[2][4];
                #pragma unroll
                for (int mt = 0; mt < 2; mt++) {
                    #pragma unroll
                    for (int q = 0; q < 4; q++) {
                        int nt = 2 * ktk + (q >> 1);
                        int base = (q & 1) * 2;
                        ph_[mt][q] = hpack(sacc[mt][nt][base], sacc[mt][nt][base + 1]);
                    }
                }
                #pragma unroll
                for (int nc = 0; nc < 8; nc++) {
                    int ib = (nc * 8 + fr) * 36 + ktk * 8 + fk;
                    uint32_t vf[2] = { VT[ib], VT[ib + 4] };
                    #pragma unroll
                    for (int mt = 0; mt < 2; mt++)
                        MMA_F16(cacc[mt][nc], ph_[mt], vf);
                }
            }
        } // kc

        #pragma unroll
        for (int mt = 0; mt < 2; mt++)
            #pragma unroll
            for (int hf = 0; hf < 2; hf++) {
                float inv = 0.25f / l_[mt][hf];
                #pragma unroll
                for (int nt = 0; nt < 8; nt++) {
                    outacc[mt][nt][hf*2]   += cacc[mt][nt][hf*2]   * inv;
                    outacc[mt][nt][hf*2+1] += cacc[mt][nt][hf*2+1] * inv;
                }
            }
    } // j

    #pragma unroll
    for (int mt = 0; mt < 2; mt++) {
        #pragma unroll
        for (int hf = 0; hf < 2; hf++) {
            int row = wm + mt * 16 + fr + hf * 8;
            long obase = (rowQ + row) * C_ + h * HD_;
            #pragma unroll
            for (int nt = 0; nt < 8; nt++) {
                int col = nt * 8 + 2 * fk;
                *(__half2*)&ctxF[obase + col] =
                    __floats2half2_rn(outacc[mt][nt][hf*2], outacc[mt][nt][hf*2+1]);
            }
        }
    }
}

// ---------------- learnable-query projection (warp per output) -----------
__global__ __launch_bounds__(256) void qh_kernel(
    const float* __restrict__ query, const float* __restrict__ w,
    const float* __restrict__ bq, float* __restrict__ qh)
{
    int v = blockIdx.y;
    int d = blockIdx.x * 8 + (threadIdx.x >> 5);
    int lane = threadIdx.x & 31;
    const float* wr = w + (long)v * (3 * C_) * C_ + (long)d * C_;
    float acc = 0.0f;
    #pragma unroll
    for (int c = lane; c < C_; c += 32) acc += query[c] * wr[c];
    #pragma unroll
    for (int off = 16; off > 0; off >>= 1)
        acc += __shfl_xor_sync(0xffffffffu, acc, off);
    if (lane == 0)
        qh[v * C_ + d] = acc + bq[(long)v * (3 * C_) + d];
}

// ---------------- cross attention (single query) ----------------
__global__ __launch_bounds__(256) void cross_attn_kernel(
    const float* __restrict__ kv, const float* __restrict__ qh,
    float* __restrict__ c2)
{
    int h = blockIdx.x, b = blockIdx.y, v = blockIdx.z;
    int t = threadIdx.x;

    __shared__ float p[256];
    __shared__ float red[256];
    __shared__ float part[4][64];

    const float* kvb = kv + ((long)(v * B_ + b) * N_) * (2 * C_);
    const float* qhp = qh + v * C_ + h * HD_;
    const float* krow = kvb + (long)t * (2 * C_) + h * HD_;

    float s = 0.0f;
    #pragma unroll
    for (int e = 0; e < 64; e++) s += qhp[e] * krow[e];
    s *= 0.125f;

    red[t] = s; __syncthreads();
    for (int off = 128; off > 0; off >>= 1) {
        if (t < off) red[t] = fmaxf(red[t], red[t + off]);
        __syncthreads();
    }
    float mx = red[0];
    __syncthreads();

    float e_ = __expf(s - mx);
    p[t] = e_; red[t] = e_;
    __syncthreads();
    for (int off = 128; off > 0; off >>= 1) {
        if (t < off) red[t] += red[t + off];
        __syncthreads();
    }
    float inv = 1.0f / red[0];
    __syncthreads();

    int e = t & 63, pid = t >> 6;
    float acc = 0.0f;
    for (int n = pid * 64; n < pid * 64 + 64; n++)
        acc += p[n] * kvb[(long)n * (2 * C_) + C_ + h * HD_ + e];
    part[pid][e] = acc;
    __syncthreads();
    if (t < 64) {
        float r = (part[0][t] + part[1][t]) + (part[2][t] + part[3][t]);
        c2[(long)(v * B_ + b) * C_ + h * HD_ + t] = r * inv;
    }
}

// ---------------- output projection + broadcast over N (split writes) ----
__global__ __launch_bounds__(256) void out_kernel(
    const float* __restrict__ c2, const float* __restrict__ w,
    const float* __restrict__ bias, float* __restrict__ out)
{
    int v = blockIdx.x, b = blockIdx.y, nz = blockIdx.z;
    int t = threadIdx.x;

    __shared__ float sc[C_];
    for (int c = t; c < C_; c += 256) sc[c] = c2[(long)(v * B_ + b) * C_ + c];
    __syncthreads();

    float o[3];
    #pragma unroll
    for (int r = 0; r < 3; r++) {
        int co = t + r * 256;
        const float* wr = w + (long)v * C_ * C_ + (long)co * C_;
        float d0 = 0.f, d1 = 0.f, d2 = 0.f, d3 = 0.f;
        #pragma unroll 4
        for (int c = 0; c < C_; c += 4) {
            d0 += sc[c + 0] * wr[c + 0];
            d1 += sc[c + 1] * wr[c + 1];
            d2 += sc[c + 2] * wr[c + 2];
            d3 += sc[c + 3] * wr[c + 3];
        }
        o[r] = ((d0 + d1) + (d2 + d3)) + bias[v * C_ + co];
    }
    for (int n = nz * 32; n < nz * 32 + 32; n++) {
        long base = ((long)b * N_ + n) * (NVW * C_) + (long)v * C_;
        #pragma unroll
        for (int r = 0; r < 3; r++) out[base + t + r * 256] = o[r];
    }
}

// ---------------- launch ----------------
extern "C" void kernel_launch(void* const* d_in, const int* in_sizes, int n_in,
                              void* d_out, int out_size)
{
    const float* X        = (const float*)d_in[0];
    const float* norm1_g  = (const float*)d_in[1];
    const float* norm1_b  = (const float*)d_in[2];
    const float* qkv_w    = (const float*)d_in[3];
    const float* proj_w   = (const float*)d_in[4];
    const float* proj_b   = (const float*)d_in[5];
    const float* norm2_g  = (const float*)d_in[6];
    const float* norm2_b  = (const float*)d_in[7];
    const float* fc1_w    = (const float*)d_in[8];
    const float* fc1_b    = (const float*)d_in[9];
    const float* fc2_w    = (const float*)d_in[10];
    const float* fc2_b    = (const float*)d_in[11];
    const float* query    = (const float*)d_in[12];
    const float* mha_in_w = (const float*)d_in[13];
    const float* mha_in_b = (const float*)d_in[14];
    const float* mha_out_w= (const float*)d_in[15];
    const float* mha_out_b= (const float*)d_in[16];
    float* out = (float*)d_out;

    float *x, *kv, *qh, *c2;
    __half *qkvF, *XnF, *ctxF, *hnF, *h1F, *x2F;
    __half *Wqkv, *Wprj, *Wf1, *Wf2, *Wmha;
    cudaGetSymbolAddress((void**)&x,    g_x);
    cudaGetSymbolAddress((void**)&kv,   g_kv);
    cudaGetSymbolAddress((void**)&qh,   g_qh);
    cudaGetSymbolAddress((void**)&c2,   g_c2);
    cudaGetSymbolAddress((void**)&qkvF, g_qkvF);
    cudaGetSymbolAddress((void**)&XnF,  g_XnF);
    cudaGetSymbolAddress((void**)&ctxF, g_ctxF);
    cudaGetSymbolAddress((void**)&hnF,  g_hnF);
    cudaGetSymbolAddress((void**)&h1F,  g_h1F);
    cudaGetSymbolAddress((void**)&x2F,  g_x2F);
    cudaGetSymbolAddress((void**)&Wqkv, g_Wqkv);
    cudaGetSymbolAddress((void**)&Wprj, g_Wprj);
    cudaGetSymbolAddress((void**)&Wf1,  g_Wf1);
    cudaGetSymbolAddress((void**)&Wf2,  g_Wf2);
    cudaGetSymbolAddress((void**)&Wmha, g_Wmha);

    cudaFuncSetAttribute(gemm_mma, cudaFuncAttributeMaxDynamicSharedMemorySize,
                         GEMM_SMEM);
    cudaFuncSetAttribute(attn_mma, cudaFuncAttributeMaxDynamicSharedMemorySize,
                         ATTN_SMEM);

    const long MC  = (long)MROWS * C_;
    const long MH  = (long)MROWS * HID_;

    auto wconv = [&](const float* src, __half* dst, long n) {
        int n4 = (int)(n / 4);
        wconv_kernel<<<(n4 + 255) / 256, 256>>>(src, dst, n4);
    };

    // 0. convert all weights to fp16
    wconv(qkv_w,    Wqkv, (long)NVW * 3 * C_ * C_);
    wconv(proj_w,   Wprj, (long)NVW * C_ * C_);
    wconv(fc1_w,    Wf1,  (long)NVW * HID_ * C_);
    wconv(fc2_w,    Wf2,  (long)NVW * C_ * HID_);
    wconv(mha_in_w, Wmha, (long)NVW * 3 * C_ * C_);

    // 1. LN1 -> Xn fp16 (remap [b*NV+v] -> [v][b])
    ln_kernel<<<NVW * B_ * N_, 256>>>(X, norm1_g, norm1_b, XnF, 1, 0);

    // 2. QKV GEMM -> fp16 qkv plane
    gemm_mma<<<dim3(3 * C_ / 128, MROWS / 128, NVW), 256, GEMM_SMEM>>>(
        XnF, Wqkv, nullptr, nullptr, nullptr, qkvF,
        C_, 3 * C_, MC, (long)3 * C_ * C_, 0, 0, (long)MROWS * 3 * C_, 1.0f, 0);

    // 3. MMA flash attention, mean over j -> ctx fp16
    attn_mma<<<dim3(H_, B_, NVW), 256, ATTN_SMEM>>>(qkvF, ctxF);

    // 4. proj GEMM (alpha=2 folds residual doubling) -> f32 x
    gemm_mma<<<dim3(C_ / 128, MROWS / 128, NVW), 256, GEMM_SMEM>>>(
        ctxF, Wprj, proj_b, nullptr, x, nullptr,
        C_, C_, MC, (long)C_ * C_, C_, 0, MC, 2.0f, 0);

    // 5. LN2 -> hn fp16
    ln_kernel<<<NVW * B_ * N_, 256>>>(x, norm2_g, norm2_b, hnF, 0, 1);

    // 6. fc1 GEMM + bias + GELU -> h1 fp16
    gemm_mma<<<dim3(HID_ / 128, MROWS / 128, NVW), 256, GEMM_SMEM>>>(
        hnF, Wf1, fc1_b, nullptr, nullptr, h1F,
        C_, HID_, MC, (long)HID_ * C_, HID_, 0, MH, 1.0f, 1);

    // 7. fc2 GEMM + bias + residual(x) -> x2 fp16
    gemm_mma<<<dim3(C_ / 128, MROWS / 128, NVW), 256, GEMM_SMEM>>>(
        h1F, Wf2, fc2_b, x, nullptr, x2F,
        HID_, C_, MH, (long)C_ * HID_, C_, MC, MC, 1.0f, 0);

    // 8. learnable query projection (f32 weights, warp-per-output)
    qh_kernel<<<dim3(96, NVW), 256>>>(query, mha_in_w, mha_in_b, qh);

    // 9. K/V projection of x2 -> f32 kv (W rows [C,3C) of mha_in_w)
    gemm_mma<<<dim3(2 * C_ / 128, MROWS / 128, NVW), 256, GEMM_SMEM>>>(
        x2F, Wmha + (long)C_ * C_,
        mha_in_b + C_, nullptr, kv, nullptr,
        C_, 2 * C_, MC, (long)3 * C_ * C_, (long)3 * C_, 0,
        (long)MROWS * 2 * C_, 1.0f, 0);

    // 10. single-query cross attention -> c2[v][b][C]
    cross_attn_kernel<<<dim3(H_, B_, NVW), 256>>>(kv, qh, c2);

    // 11. output projection + broadcast over N (8-way write split)
    out_kernel<<<dim3(NVW, B_, 8), 256>>>(c2, mha_out_w, mha_out_b, out);
}